// round 2
// baseline (speedup 1.0000x reference)
#include <cuda_runtime.h>
#include <math.h>
#include <stdint.h>

// Problem constants
#define Bz   8
#define Cc   256
#define Hh   64
#define Ww   64
#define HW   (Hh*Ww)
#define Ee   4
#define Dd   4
#define CRr  16
#define GIN  (2*Cc+16)   // 528

// ---------------- scratch (static device globals; no allocation) -------------
__device__ float g_bufA[Bz*Cc*HW];
__device__ float g_bufB[Bz*Cc*HW];
__device__ float g_bufC[Bz*Cc*HW];
__device__ float g_xavg[Bz*Cc];
__device__ float g_xmax[Bz*Cc];
__device__ float g_stat1[Bz*Cc];   // dstat / h-avg
__device__ float g_stat2[Bz*Cc];   // h-max
__device__ float g_wfull[Bz*Ee];
__device__ float g_g1[Bz];
__device__ float g_ca[Bz*Cc];
__device__ float g_sain[Bz*2*HW];
__device__ float g_sa[Bz*HW];

// ---------------- helpers ----------------------------------------------------
__device__ __forceinline__ float sigmoidf_(float x) { return 1.f / (1.f + __expf(-x)); }
__device__ __forceinline__ float gelu_tanh(float v) {
    // jax.nn.gelu default (approximate=True)
    float x3 = v * v * v;
    return 0.5f * v * (1.f + tanhf(0.7978845608028654f * (v + 0.044715f * x3)));
}

// ---------------- zero init --------------------------------------------------
__global__ void zero_kernel(float* out, int n) {
    int i = blockIdx.x * blockDim.x + threadIdx.x;
    if (i < n) out[i] = 0.f;
}

// ---------------- spatial avg/max stats per (b,c) ----------------------------
// grid = Bz*Cc blocks, 256 threads. expert<0 => no skip check.
__global__ void stats_kernel(const float* __restrict__ in,
                             float* __restrict__ avg, float* __restrict__ mx,
                             int expert) {
    int bc = blockIdx.x;
    int b  = bc / Cc;
    if (expert >= 0 && g_wfull[b*Ee + expert] == 0.f) return;
    const float* p = in + (size_t)bc * HW;
    float s = 0.f, m = -INFINITY;
    for (int i = threadIdx.x; i < HW; i += 256) {
        float v = p[i];
        s += v; m = fmaxf(m, v);
    }
    __shared__ float ss[256], sm[256];
    int t = threadIdx.x;
    ss[t] = s; sm[t] = m; __syncthreads();
    for (int k = 128; k; k >>= 1) {
        if (t < k) { ss[t] += ss[t+k]; sm[t] = fmaxf(sm[t], sm[t+k]); }
        __syncthreads();
    }
    if (t == 0) {
        avg[bc] = ss[0] * (1.f / HW);
        if (mx) mx[bc] = sm[0];
    }
}

// ---------------- gate network: Linear->LN->ReLU->Linear->softmax->top2 ------
// one block, 256 threads; loops over batch
__global__ void gate_kernel(const int* __restrict__ dom,
                            const float* __restrict__ w1, const float* __restrict__ b1,
                            const float* __restrict__ lns, const float* __restrict__ lnb,
                            const float* __restrict__ w2, const float* __restrict__ b2,
                            const float* __restrict__ dom_emb) {
    __shared__ float gi[GIN];
    __shared__ float red[256];
    __shared__ float logit[Ee];
    int t = threadIdx.x;
    for (int b = 0; b < Bz; b++) {
        // build gate input [GAP(x) | GMP(x) | dom_emb]
        for (int k = t; k < GIN; k += 256) {
            float v;
            if (k < Cc)            v = g_xavg[b*Cc + k];
            else if (k < 2*Cc)     v = g_xmax[b*Cc + k - Cc];
            else                   v = dom_emb[dom[b]*16 + (k - 2*Cc)];
            gi[k] = v;
        }
        __syncthreads();
        // hg[t] = gi @ w1[:,t] + b1[t]
        float acc = b1[t];
        for (int k = 0; k < GIN; k++) acc += gi[k] * w1[k*Cc + t];
        // LayerNorm over 256
        red[t] = acc; __syncthreads();
        for (int k = 128; k; k >>= 1) { if (t < k) red[t] += red[t+k]; __syncthreads(); }
        float mu = red[0] * (1.f / Cc);
        __syncthreads();
        red[t] = acc * acc; __syncthreads();
        for (int k = 128; k; k >>= 1) { if (t < k) red[t] += red[t+k]; __syncthreads(); }
        float var = red[0] * (1.f / Cc) - mu * mu;
        __syncthreads();
        float h = (acc - mu) * rsqrtf(var + 1e-5f) * lns[t] + lnb[t];
        h = fmaxf(h, 0.f);
        // logits: h @ w2 + b2 (4 block-reductions)
        for (int e = 0; e < Ee; e++) {
            red[t] = h * w2[t*Ee + e]; __syncthreads();
            for (int k = 128; k; k >>= 1) { if (t < k) red[t] += red[t+k]; __syncthreads(); }
            if (t == 0) logit[e] = red[0] + b2[e];
            __syncthreads();
        }
        if (t == 0) {
            float mx = logit[0];
            for (int e = 1; e < Ee; e++) mx = fmaxf(mx, logit[e]);
            float pr[Ee], s = 0.f;
            for (int e = 0; e < Ee; e++) { pr[e] = __expf(logit[e] - mx); s += pr[e]; }
            for (int e = 0; e < Ee; e++) pr[e] /= s;
            int i1 = 0;
            for (int e = 1; e < Ee; e++) if (pr[e] > pr[i1]) i1 = e;
            int i2 = -1;
            for (int e = 0; e < Ee; e++) if (e != i1 && (i2 < 0 || pr[e] > pr[i2])) i2 = e;
            float s2 = pr[i1] + pr[i2];
            for (int e = 0; e < Ee; e++) g_wfull[b*Ee + e] = 0.f;
            g_wfull[b*Ee + i1] = pr[i1] / s2;
            g_wfull[b*Ee + i2] = pr[i2] / s2;
        }
        __syncthreads();
    }
}

// ---------------- conv 3x3, pad 1, direct, tiled -----------------------------
#define CO_TILE 64
#define TH 8
#define TW 32
#define CICH 8
#define MODE_GELU 0
#define MODE_NONE 1
#define MODE_RELU 2

__global__ __launch_bounds__(256) void conv3x3_kernel(
    const float* __restrict__ in, const float* __restrict__ wgt,
    const float* __restrict__ bias,
    const float* __restrict__ bns, const float* __restrict__ bnb,
    float* __restrict__ out, int e, int mode)
{
    int b = blockIdx.z / (Cc / CO_TILE);
    if (g_wfull[b*Ee + e] == 0.f) return;
    int cob  = (blockIdx.z % (Cc / CO_TILE)) * CO_TILE;
    int row0 = blockIdx.y * TH;
    int col0 = blockIdx.x * TW;
    const float* wbase = wgt + (size_t)e * Cc * Cc * 9;

    __shared__ float s_in[CICH][TH+2][TW+2];
    __shared__ float s_w[CICH][CO_TILE][9];

    int tid = threadIdx.x;
    int tx = tid & 31;     // pixel column within tile
    int ty = tid >> 5;     // 8-wide out-channel group

    float acc[8][8];
    #pragma unroll
    for (int i = 0; i < 8; i++)
        #pragma unroll
        for (int r = 0; r < 8; r++) acc[i][r] = 0.f;

    for (int cib = 0; cib < Cc; cib += CICH) {
        __syncthreads();
        // load input tile + halo
        for (int idx = tid; idx < CICH*(TH+2)*(TW+2); idx += 256) {
            int ci  = idx / ((TH+2)*(TW+2));
            int rem = idx % ((TH+2)*(TW+2));
            int r   = rem / (TW+2);
            int cc  = rem % (TW+2);
            int gy = row0 - 1 + r, gx = col0 - 1 + cc;
            float v = 0.f;
            if (gy >= 0 && gy < Hh && gx >= 0 && gx < Ww)
                v = in[(((size_t)b*Cc + cib + ci)*Hh + gy)*Ww + gx];
            s_in[ci][r][cc] = v;
        }
        // load weights (reorder: [ci][co][k] for broadcast)
        for (int idx = tid; idx < CICH*CO_TILE*9; idx += 256) {
            int k  = idx % 9;
            int t2 = idx / 9;
            int ci = t2 % CICH;
            int co = t2 / CICH;
            s_w[ci][co][k] = wbase[(((size_t)(cob+co))*Cc + cib + ci)*9 + k];
        }
        __syncthreads();
        #pragma unroll
        for (int ci = 0; ci < CICH; ci++) {
            #pragma unroll
            for (int ky = 0; ky < 3; ky++) {
                #pragma unroll
                for (int kx = 0; kx < 3; kx++) {
                    float wv[8];
                    #pragma unroll
                    for (int i = 0; i < 8; i++) wv[i] = s_w[ci][ty*8+i][ky*3+kx];
                    #pragma unroll
                    for (int r = 0; r < 8; r++) {
                        float iv = s_in[ci][r+ky][tx+kx];
                        #pragma unroll
                        for (int i = 0; i < 8; i++) acc[i][r] += wv[i] * iv;
                    }
                }
            }
        }
    }
    // epilogue: (+bias) -> BN affine -> activation
    #pragma unroll
    for (int i = 0; i < 8; i++) {
        int co = cob + ty*8 + i;
        float s  = bns[e*Cc + co];
        float bb = bnb[e*Cc + co];
        float bi = bias ? bias[e*Cc + co] : 0.f;
        #pragma unroll
        for (int r = 0; r < 8; r++) {
            float v = (acc[i][r] + bi) * s + bb;
            if (mode == MODE_GELU)      v = gelu_tanh(v);
            else if (mode == MODE_RELU) v = fmaxf(v, 0.f);
            out[(((size_t)b*Cc + co)*Hh + (row0 + r))*Ww + (col0 + tx)] = v;
        }
    }
}

// ---------------- domain gate: g1[b] = sigmoid(dot(GAP(d), gate_w) + gate_b) -
__global__ void dgate_kernel(const float* __restrict__ gw, const float* __restrict__ gb, int e) {
    int b = blockIdx.x;
    if (g_wfull[b*Ee + e] == 0.f) return;
    int t = threadIdx.x;
    __shared__ float red[256];
    red[t] = g_stat1[b*Cc + t] * gw[e*Cc + t];
    __syncthreads();
    for (int k = 128; k; k >>= 1) { if (t < k) red[t] += red[t+k]; __syncthreads(); }
    if (t == 0) g_g1[b] = sigmoidf_(red[0] + gb[e]);
}

// ---------------- out = x + g1[b]*d ------------------------------------------
__global__ void axpy_kernel(const float* __restrict__ x, int e) {
    int b = blockIdx.y;
    if (g_wfull[b*Ee + e] == 0.f) return;
    int i = blockIdx.x * 256 + threadIdx.x;
    size_t off = (size_t)b * Cc * HW + i;
    g_bufC[off] = x[off] + g_g1[b] * g_bufB[off];
}

// ---------------- channel attention MLP --------------------------------------
__global__ void camlp_kernel(const float* __restrict__ w1, const float* __restrict__ w2, int e) {
    int b = blockIdx.x;
    if (g_wfull[b*Ee + e] == 0.f) return;
    int t = threadIdx.x;
    __shared__ float hs[CRr];
    if (t < CRr) {
        float sa_ = 0.f, sm_ = 0.f;
        const float* w1r = w1 + ((size_t)e*CRr + t) * Cc;
        for (int c = 0; c < Cc; c++) {
            sa_ += g_stat1[b*Cc + c] * w1r[c];
            sm_ += g_stat2[b*Cc + c] * w1r[c];
        }
        hs[t] = fmaxf(sa_, 0.f) + fmaxf(sm_, 0.f);
    }
    __syncthreads();
    float o = 0.f;
    const float* w2r = w2 + ((size_t)e*Cc + t) * CRr;
    #pragma unroll
    for (int j = 0; j < CRr; j++) o += hs[j] * w2r[j];
    g_ca[b*Cc + t] = sigmoidf_(o);
}

// ---------------- spatial-attention input: mean/max over channels ------------
__global__ void sastats_kernel(int e) {
    int b = blockIdx.y;
    if (g_wfull[b*Ee + e] == 0.f) return;
    __shared__ float sca[Cc];
    int t = threadIdx.x;
    sca[t] = g_ca[b*Cc + t];
    __syncthreads();
    int p = blockIdx.x * 256 + t;
    float s = 0.f, m = -INFINITY;
    for (int c = 0; c < Cc; c++) {
        float v = g_bufB[((size_t)b*Cc + c)*HW + p] * sca[c];
        s += v; m = fmaxf(m, v);
    }
    g_sain[((size_t)b*2    )*HW + p] = s * (1.f / Cc);
    g_sain[((size_t)b*2 + 1)*HW + p] = m;
}

// ---------------- spatial attention: 7x7 conv (2->1) + sigmoid ---------------
__global__ void saconv_kernel(const float* __restrict__ saw, int e) {
    int b = blockIdx.y;
    if (g_wfull[b*Ee + e] == 0.f) return;
    __shared__ float sw[2*49];
    int t = threadIdx.x;
    if (t < 98) sw[t] = saw[e*98 + t];
    __syncthreads();
    int p = blockIdx.x * 256 + t;
    int y = p >> 6, x = p & 63;
    float a = 0.f;
    #pragma unroll
    for (int ch = 0; ch < 2; ch++)
        for (int ky = 0; ky < 7; ky++) {
            int gy = y + ky - 3;
            if (gy < 0 || gy >= Hh) continue;
            for (int kx = 0; kx < 7; kx++) {
                int gx = x + kx - 3;
                if (gx < 0 || gx >= Ww) continue;
                a += g_sain[((size_t)b*2 + ch)*HW + gy*Ww + gx] * sw[ch*49 + ky*7 + kx];
            }
        }
    g_sa[(size_t)b*HW + p] = sigmoidf_(a);
}

// ---------------- final: relu(h*ca*sa + r) + adapter, weighted accumulate ----
__global__ void final_kernel(const float* __restrict__ adapter, const int* __restrict__ dom,
                             float* __restrict__ out, int e) {
    int b = blockIdx.y;
    float w = g_wfull[b*Ee + e];
    if (w == 0.f) return;
    int idx = blockIdx.x * 256 + threadIdx.x;
    int c = idx / HW, p = idx % HW;
    size_t off = (size_t)b * Cc * HW + idx;
    float v = g_bufB[off] * g_ca[b*Cc + c] * g_sa[(size_t)b*HW + p] + g_bufC[off];
    v = fmaxf(v, 0.f) + adapter[((size_t)e*Dd + dom[b])*Cc + c];
    out[off] += w * v;
}

// ---------------- launch -----------------------------------------------------
extern "C" void kernel_launch(void* const* d_in, const int* in_sizes, int n_in,
                              void* d_out, int out_size) {
    const float* x        = (const float*)d_in[0];
    const int*   dom      = (const int*)  d_in[1];
    const float* g_w1     = (const float*)d_in[2];
    const float* g_b1     = (const float*)d_in[3];
    const float* ln_s     = (const float*)d_in[4];
    const float* ln_b     = (const float*)d_in[5];
    const float* g_w2     = (const float*)d_in[6];
    const float* g_b2     = (const float*)d_in[7];
    const float* dom_emb  = (const float*)d_in[8];
    const float* dt_w1    = (const float*)d_in[9];
    const float* dt_bn1s  = (const float*)d_in[10];
    const float* dt_bn1b  = (const float*)d_in[11];
    const float* dt_w2    = (const float*)d_in[12];
    const float* dt_bn2s  = (const float*)d_in[13];
    const float* dt_bn2b  = (const float*)d_in[14];
    const float* gate_w   = (const float*)d_in[15];
    const float* gate_b   = (const float*)d_in[16];
    const float* c1_w     = (const float*)d_in[17];
    const float* c1_b     = (const float*)d_in[18];
    const float* bn1s     = (const float*)d_in[19];
    const float* bn1b     = (const float*)d_in[20];
    const float* c2_w     = (const float*)d_in[21];
    const float* c2_b     = (const float*)d_in[22];
    const float* bn2s     = (const float*)d_in[23];
    const float* bn2b     = (const float*)d_in[24];
    const float* ca_w1    = (const float*)d_in[25];
    const float* ca_w2    = (const float*)d_in[26];
    const float* sa_w     = (const float*)d_in[27];
    const float* adapter  = (const float*)d_in[28];
    float* out = (float*)d_out;

    float *bufA, *bufB, *bufC, *pxavg, *pxmax, *pstat1, *pstat2;
    cudaGetSymbolAddress((void**)&bufA,  g_bufA);
    cudaGetSymbolAddress((void**)&bufB,  g_bufB);
    cudaGetSymbolAddress((void**)&bufC,  g_bufC);
    cudaGetSymbolAddress((void**)&pxavg, g_xavg);
    cudaGetSymbolAddress((void**)&pxmax, g_xmax);
    cudaGetSymbolAddress((void**)&pstat1, g_stat1);
    cudaGetSymbolAddress((void**)&pstat2, g_stat2);

    int ntot = Bz * Cc * HW;
    zero_kernel<<<(ntot + 255) / 256, 256>>>(out, ntot);

    // gate first (enables top-2 skip everywhere downstream)
    stats_kernel<<<Bz*Cc, 256>>>(x, pxavg, pxmax, -1);
    gate_kernel<<<1, 256>>>(dom, g_w1, g_b1, ln_s, ln_b, g_w2, g_b2, dom_emb);

    dim3 cgrid(Ww/TW, Hh/TH, Bz * (Cc/CO_TILE));
    dim3 egrid(Cc*HW/256, Bz);
    dim3 sgrid(HW/256, Bz);

    for (int e = 0; e < Ee; e++) {
        conv3x3_kernel<<<cgrid, 256>>>(x,    dt_w1, nullptr, dt_bn1s, dt_bn1b, bufA, e, MODE_GELU);
        conv3x3_kernel<<<cgrid, 256>>>(bufA, dt_w2, nullptr, dt_bn2s, dt_bn2b, bufB, e, MODE_NONE);
        stats_kernel<<<Bz*Cc, 256>>>(bufB, pstat1, nullptr, e);
        dgate_kernel<<<Bz, 256>>>(gate_w, gate_b, e);
        axpy_kernel<<<egrid, 256>>>(x, e);
        conv3x3_kernel<<<cgrid, 256>>>(bufC, c1_w, c1_b, bn1s, bn1b, bufA, e, MODE_RELU);
        conv3x3_kernel<<<cgrid, 256>>>(bufA, c2_w, c2_b, bn2s, bn2b, bufB, e, MODE_NONE);
        stats_kernel<<<Bz*Cc, 256>>>(bufB, pstat1, pstat2, e);
        camlp_kernel<<<Bz, 256>>>(ca_w1, ca_w2, e);
        sastats_kernel<<<sgrid, 256>>>(e);
        saconv_kernel<<<sgrid, 256>>>(sa_w, e);
        final_kernel<<<egrid, 256>>>(adapter, dom, out, e);
    }
}

// round 4
// speedup vs baseline: 1.9381x; 1.9381x over previous
#include <cuda_runtime.h>
#include <cuda_bf16.h>
#include <math.h>
#include <stdint.h>

// Problem constants
#define Bz   8
#define Cc   256
#define Hh   64
#define Ww   64
#define HW   (Hh*Ww)
#define Ee   4
#define Dd   4
#define CRr  16
#define GIN  (2*Cc+16)   // 528

// Conv-GEMM constants
#define KTOT   2304          // 9 taps * 256 ci
#define KCH    32            // K per chunk
#define NCHUNK (KTOT/KCH)    // 72
#define PW     66            // padded width/height
#define PIMG   (PW*PW)       // 4356 per (b,c)

// smem strides (in uint16 units), padded for conflict-free ldmatrix
#define SA_STR 40            // 32 k + 8 pad -> 80B rows
#define SB_STR 136           // 128 px + 8 pad -> 272B rows

// ---------------- scratch (static device globals; zero-initialized) ---------
__device__ float    g_bufB[Bz*Cc*HW];
__device__ float    g_bufC[Bz*Cc*HW];
__device__ uint32_t g_xpk [Bz*Cc*PIMG];    // packed hi/lo padded input (borders stay 0)
__device__ uint32_t g_pkA [Bz*Cc*PIMG];
__device__ uint32_t g_pkC [Bz*Cc*PIMG];
__device__ uint32_t g_wpk [16*Cc*KTOT];    // [conv*4+e][co][k] packed hi/lo
__device__ float g_xavg[Bz*Cc];
__device__ float g_xmax[Bz*Cc];
__device__ float g_stat1[Bz*Cc];
__device__ float g_stat2[Bz*Cc];
__device__ float g_wfull[Bz*Ee];
__device__ float g_g1[Bz];
__device__ float g_ca[Bz*Cc];
__device__ float g_sain[Bz*2*HW];
__device__ float g_sa[Bz*HW];

// ---------------- helpers ----------------------------------------------------
__device__ __forceinline__ float sigmoidf_(float x) { return 1.f / (1.f + __expf(-x)); }
__device__ __forceinline__ float gelu_tanh(float v) {
    float x3 = v * v * v;
    return 0.5f * v * (1.f + tanhf(0.7978845608028654f * (v + 0.044715f * x3)));
}
__device__ __forceinline__ uint32_t pack_hilo(float v) {
    __nv_bfloat16 h = __float2bfloat16(v);
    float r = v - __bfloat162float(h);
    __nv_bfloat16 l = __float2bfloat16(r);
    return (uint32_t)__bfloat16_as_ushort(h) | ((uint32_t)__bfloat16_as_ushort(l) << 16);
}
__device__ __forceinline__ uint32_t sptr(const void* p) {
    return (uint32_t)__cvta_generic_to_shared(p);
}

#define LDSM4(r, addr) \
    asm volatile("ldmatrix.sync.aligned.m8n8.x4.shared.b16 {%0,%1,%2,%3}, [%4];" \
        : "=r"((r)[0]), "=r"((r)[1]), "=r"((r)[2]), "=r"((r)[3]) : "r"(addr))
#define LDSM4T(r, addr) \
    asm volatile("ldmatrix.sync.aligned.m8n8.x4.trans.shared.b16 {%0,%1,%2,%3}, [%4];" \
        : "=r"((r)[0]), "=r"((r)[1]), "=r"((r)[2]), "=r"((r)[3]) : "r"(addr))
#define MMA16816(d, a, b0_, b1_) \
    asm volatile("mma.sync.aligned.m16n8k16.row.col.f32.bf16.bf16.f32 " \
        "{%0,%1,%2,%3}, {%4,%5,%6,%7}, {%8,%9}, {%0,%1,%2,%3};" \
        : "+f"((d)[0]), "+f"((d)[1]), "+f"((d)[2]), "+f"((d)[3]) \
        : "r"((a)[0]), "r"((a)[1]), "r"((a)[2]), "r"((a)[3]), "r"(b0_), "r"(b1_))

// ---------------- zero init --------------------------------------------------
__global__ void zero_kernel(float* out, int n) {
    int i = blockIdx.x * blockDim.x + threadIdx.x;
    if (i < n) out[i] = 0.f;
}

// ---------------- weight pack: fp32 [E][co][ci][9] -> hi/lo [E][co][tap*256+ci]
__global__ void packw_kernel(const float* __restrict__ w, uint32_t* __restrict__ out) {
    int idx = blockIdx.x * 256 + threadIdx.x;
    if (idx >= Ee * Cc * KTOT) return;
    int k  = idx % KTOT;
    int co = (idx / KTOT) % Cc;
    int e  = idx / (KTOT * Cc);
    int d  = k >> 8, ci = k & 255;
    float v = w[(((size_t)e * Cc + co) * Cc + ci) * 9 + d];
    out[idx] = pack_hilo(v);
}

// ---------------- x pack: fp32 [b][c][64][64] -> padded packed ---------------
__global__ void packx_kernel(const float* __restrict__ x, uint32_t* __restrict__ out) {
    int idx = blockIdx.x * 256 + threadIdx.x;
    int p = idx & 4095, c = idx >> 12;
    int y = p >> 6, xx = p & 63;
    out[(size_t)c * PIMG + (y + 1) * PW + xx + 1] = pack_hilo(x[idx]);
}

// ---------------- spatial avg/max stats per (b,c) ----------------------------
__global__ void stats_kernel(const float* __restrict__ in,
                             float* __restrict__ avg, float* __restrict__ mx,
                             int expert) {
    int bc = blockIdx.x;
    int b  = bc / Cc;
    if (expert >= 0 && g_wfull[b*Ee + expert] == 0.f) return;
    const float* p = in + (size_t)bc * HW;
    float s = 0.f, m = -INFINITY;
    for (int i = threadIdx.x; i < HW; i += 256) {
        float v = p[i];
        s += v; m = fmaxf(m, v);
    }
    __shared__ float ss[256], sm[256];
    int t = threadIdx.x;
    ss[t] = s; sm[t] = m; __syncthreads();
    for (int k = 128; k; k >>= 1) {
        if (t < k) { ss[t] += ss[t+k]; sm[t] = fmaxf(sm[t], sm[t+k]); }
        __syncthreads();
    }
    if (t == 0) {
        avg[bc] = ss[0] * (1.f / HW);
        if (mx) mx[bc] = sm[0];
    }
}

// ---------------- gate network -----------------------------------------------
__global__ void gate_kernel(const int* __restrict__ dom,
                            const float* __restrict__ w1, const float* __restrict__ b1,
                            const float* __restrict__ lns, const float* __restrict__ lnb,
                            const float* __restrict__ w2, const float* __restrict__ b2,
                            const float* __restrict__ dom_emb) {
    __shared__ float gi[GIN];
    __shared__ float red[256];
    __shared__ float logit[Ee];
    int t = threadIdx.x;
    for (int b = 0; b < Bz; b++) {
        for (int k = t; k < GIN; k += 256) {
            float v;
            if (k < Cc)        v = g_xavg[b*Cc + k];
            else if (k < 2*Cc) v = g_xmax[b*Cc + k - Cc];
            else               v = dom_emb[dom[b]*16 + (k - 2*Cc)];
            gi[k] = v;
        }
        __syncthreads();
        float acc = b1[t];
        for (int k = 0; k < GIN; k++) acc += gi[k] * w1[k*Cc + t];
        red[t] = acc; __syncthreads();
        for (int k = 128; k; k >>= 1) { if (t < k) red[t] += red[t+k]; __syncthreads(); }
        float mu = red[0] * (1.f / Cc);
        __syncthreads();
        red[t] = acc * acc; __syncthreads();
        for (int k = 128; k; k >>= 1) { if (t < k) red[t] += red[t+k]; __syncthreads(); }
        float var = red[0] * (1.f / Cc) - mu * mu;
        __syncthreads();
        float h = (acc - mu) * rsqrtf(var + 1e-5f) * lns[t] + lnb[t];
        h = fmaxf(h, 0.f);
        for (int e = 0; e < Ee; e++) {
            red[t] = h * w2[t*Ee + e]; __syncthreads();
            for (int k = 128; k; k >>= 1) { if (t < k) red[t] += red[t+k]; __syncthreads(); }
            if (t == 0) logit[e] = red[0] + b2[e];
            __syncthreads();
        }
        if (t == 0) {
            float mx = logit[0];
            for (int e = 1; e < Ee; e++) mx = fmaxf(mx, logit[e]);
            float pr[Ee], s = 0.f;
            for (int e = 0; e < Ee; e++) { pr[e] = __expf(logit[e] - mx); s += pr[e]; }
            for (int e = 0; e < Ee; e++) pr[e] /= s;
            int i1 = 0;
            for (int e = 1; e < Ee; e++) if (pr[e] > pr[i1]) i1 = e;
            int i2 = -1;
            for (int e = 0; e < Ee; e++) if (e != i1 && (i2 < 0 || pr[e] > pr[i2])) i2 = e;
            float s2 = pr[i1] + pr[i2];
            for (int e = 0; e < Ee; e++) g_wfull[b*Ee + e] = 0.f;
            g_wfull[b*Ee + i1] = pr[i1] / s2;
            g_wfull[b*Ee + i2] = pr[i2] / s2;
        }
        __syncthreads();
    }
}

// ---------------- conv 3x3 via mma.sync bf16x3 GEMM --------------------------
// C[128co x 128px] block, grid (32 px-tiles, 2 co-tiles, 8 batch), 256 thr.
#define MODE_GELU 0
#define MODE_NONE 1
#define MODE_RELU 2

__device__ __forceinline__ void stage_load(
    const uint32_t* __restrict__ wp, const uint32_t* __restrict__ bp,
    uint32_t (&a0)[8], uint32_t (&a1)[8], uint32_t (&b0)[8], uint32_t (&b1)[8])
{
    #pragma unroll
    for (int it = 0; it < 8; it++) {
        uint2 v = *(const uint2*)(wp + (size_t)it * 16 * KTOT);
        a0[it] = (v.x & 0xFFFFu) | (v.y << 16);
        a1[it] = (v.x >> 16)     | (v.y & 0xFFFF0000u);
    }
    #pragma unroll
    for (int i = 0; i < 8; i++) {
        uint32_t u = bp[2*i], w = bp[2*i+1];
        b0[i] = (u & 0xFFFFu) | (w << 16);
        b1[i] = (u >> 16)     | (w & 0xFFFF0000u);
    }
}

__global__ __launch_bounds__(256, 1) void conv_mma_kernel(
    const uint32_t* __restrict__ pkin, const uint32_t* __restrict__ wpk,
    int convIdx, const float* __restrict__ bias,
    const float* __restrict__ bns, const float* __restrict__ bnb,
    float* __restrict__ f32out, uint32_t* __restrict__ pkout,
    int e, int mode)
{
    int b = blockIdx.z;
    if (g_wfull[b*Ee + e] == 0.f) return;
    int cob = blockIdx.y * 128;
    int pxb = blockIdx.x * 128;
    int y0  = blockIdx.x * 2;

    __shared__ __align__(16) uint16_t sAh[128*SA_STR];
    __shared__ __align__(16) uint16_t sAl[128*SA_STR];
    __shared__ __align__(16) uint16_t sBh[32*SB_STR];
    __shared__ __align__(16) uint16_t sBl[32*SB_STR];

    int tid  = threadIdx.x;
    int lane = tid & 31, wid = tid >> 5;
    int wco  = (wid & 3) * 32;           // warp co offset within 128
    int wpx  = (wid >> 2) * 64;          // warp px offset within 128

    const uint32_t* wrow = wpk + ((size_t)(convIdx*Ee + e) * Cc + cob) * KTOT;
    const uint32_t* prow = pkin + (size_t)b * Cc * PIMG;

    // staging-role constants
    int kpair = tid & 15, cog = tid >> 4;           // A: 2k per thread, 16 co groups
    int kB = tid >> 3,  pB = (tid & 7) * 16;        // B: 1 k-row, 16 px per thread
    int yB = y0 + (pB >> 6) + 1;                    // +1: padded-border offset (ky adds -1..+1 via tap)
    int xB = (pB & 63) + 1;

    float acc[2][8][4];
    #pragma unroll
    for (int mt = 0; mt < 2; mt++)
        #pragma unroll
        for (int nt = 0; nt < 8; nt++)
            #pragma unroll
            for (int q = 0; q < 4; q++) acc[mt][nt][q] = 0.f;

    uint32_t a0[8], a1[8], b0v[8], b1v[8];
    // preload chunk 0: d=0 -> ky=0,kx=0 (tap offset -1,-1 handled by padded addressing)
    {
        const uint32_t* wp = wrow + (size_t)cog * KTOT + 2*kpair;
        const uint32_t* bp = prow + (size_t)kB * PIMG + (yB - 1) * PW + (xB - 1);
        stage_load(wp, bp, a0, a1, b0v, b1v);
    }

    for (int c = 0; c < NCHUNK; c++) {
        __syncthreads();   // previous chunk's compute finished
        // regs -> smem
        #pragma unroll
        for (int it = 0; it < 8; it++) {
            *(uint32_t*)(sAh + (cog + it*16)*SA_STR + 2*kpair) = a0[it];
            *(uint32_t*)(sAl + (cog + it*16)*SA_STR + 2*kpair) = a1[it];
        }
        #pragma unroll
        for (int i = 0; i < 8; i++) {
            *(uint32_t*)(sBh + kB*SB_STR + pB + 2*i) = b0v[i];
            *(uint32_t*)(sBl + kB*SB_STR + pB + 2*i) = b1v[i];
        }
        __syncthreads();

        // prefetch next chunk into regs (overlaps with compute below)
        if (c + 1 < NCHUNK) {
            int cn = c + 1;
            int d  = cn >> 3;               // tap 0..8
            int ky = d / 3, kx = d - 3*ky;  // 0..2 each
            int ci0 = (cn & 7) << 5;
            const uint32_t* wp = wrow + (size_t)cog * KTOT + cn*KCH + 2*kpair;
            const uint32_t* bp = prow + (size_t)(ci0 + kB) * PIMG + (yB + ky - 1) * PW + (xB + kx - 1);
            stage_load(wp, bp, a0, a1, b0v, b1v);
        }

        // compute chunk c from smem
        #pragma unroll
        for (int ks = 0; ks < 2; ks++) {
            int kO = ks * 16;
            uint32_t ah[2][4], al[2][4], bh[4][4], bl[4][4];
            #pragma unroll
            for (int mt = 0; mt < 2; mt++) {
                uint32_t ad = sptr(sAh + (wco + mt*16 + (lane & 15))*SA_STR + kO + (lane >> 4)*8);
                LDSM4(ah[mt], ad);
                ad = sptr(sAl + (wco + mt*16 + (lane & 15))*SA_STR + kO + (lane >> 4)*8);
                LDSM4(al[mt], ad);
            }
            #pragma unroll
            for (int nt = 0; nt < 4; nt++) {
                uint32_t bd = sptr(sBh + (kO + (lane & 15))*SB_STR + wpx + nt*16 + (lane >> 4)*8);
                LDSM4T(bh[nt], bd);
                bd = sptr(sBl + (kO + (lane & 15))*SB_STR + wpx + nt*16 + (lane >> 4)*8);
                LDSM4T(bl[nt], bd);
            }
            #pragma unroll
            for (int mt = 0; mt < 2; mt++) {
                #pragma unroll
                for (int n8 = 0; n8 < 8; n8++) {
                    uint32_t bh0 = bh[n8 >> 1][(n8 & 1)*2], bh1 = bh[n8 >> 1][(n8 & 1)*2 + 1];
                    uint32_t bl0 = bl[n8 >> 1][(n8 & 1)*2], bl1 = bl[n8 >> 1][(n8 & 1)*2 + 1];
                    MMA16816(acc[mt][n8], ah[mt], bh0, bh1);
                    MMA16816(acc[mt][n8], ah[mt], bl0, bl1);
                    MMA16816(acc[mt][n8], al[mt], bh0, bh1);
                }
            }
        }
    }

    // epilogue: bias -> BN -> act -> store f32 and/or packed
    int r  = lane >> 2;
    int cp = (lane & 3) * 2;
    #pragma unroll
    for (int mt = 0; mt < 2; mt++) {
        #pragma unroll
        for (int hf = 0; hf < 2; hf++) {
            int co = cob + wco + mt*16 + r + hf*8;
            float bsc = bns[e*Cc + co];
            float bsh = bnb[e*Cc + co];
            float bi  = bias ? bias[e*Cc + co] : 0.f;
            #pragma unroll
            for (int n8 = 0; n8 < 8; n8++) {
                int px = pxb + wpx + n8*8 + cp;
                float v0 = (acc[mt][n8][hf*2 + 0] + bi) * bsc + bsh;
                float v1 = (acc[mt][n8][hf*2 + 1] + bi) * bsc + bsh;
                if (mode == MODE_GELU)      { v0 = gelu_tanh(v0); v1 = gelu_tanh(v1); }
                else if (mode == MODE_RELU) { v0 = fmaxf(v0, 0.f); v1 = fmaxf(v1, 0.f); }
                if (f32out) {
                    float2 f2 = make_float2(v0, v1);
                    *(float2*)(f32out + (size_t)(b*Cc + co)*HW + px) = f2;
                }
                if (pkout) {
                    int y = px >> 6, x = px & 63;
                    size_t o = (size_t)(b*Cc + co)*PIMG + (y + 1)*PW + x + 1;
                    pkout[o]     = pack_hilo(v0);
                    pkout[o + 1] = pack_hilo(v1);
                }
            }
        }
    }
}

// ---------------- domain gate ------------------------------------------------
__global__ void dgate_kernel(const float* __restrict__ gw, const float* __restrict__ gb, int e) {
    int b = blockIdx.x;
    if (g_wfull[b*Ee + e] == 0.f) return;
    int t = threadIdx.x;
    __shared__ float red[256];
    red[t] = g_stat1[b*Cc + t] * gw[e*Cc + t];
    __syncthreads();
    for (int k = 128; k; k >>= 1) { if (t < k) red[t] += red[t+k]; __syncthreads(); }
    if (t == 0) g_g1[b] = sigmoidf_(red[0] + gb[e]);
}

// ---------------- bufC = x + g1*bufB; also emit packed padded ----------------
__global__ void axpy_kernel(const float* __restrict__ x, int e) {
    int b = blockIdx.y;
    if (g_wfull[b*Ee + e] == 0.f) return;
    int i = blockIdx.x * 256 + threadIdx.x;
    size_t off = (size_t)b * Cc * HW + i;
    float v = x[off] + g_g1[b] * g_bufB[off];
    g_bufC[off] = v;
    int c = i >> 12, p = i & 4095;
    g_pkC[((size_t)b*Cc + c) * PIMG + ((p>>6) + 1) * PW + (p & 63) + 1] = pack_hilo(v);
}

// ---------------- channel attention MLP --------------------------------------
__global__ void camlp_kernel(const float* __restrict__ w1, const float* __restrict__ w2, int e) {
    int b = blockIdx.x;
    if (g_wfull[b*Ee + e] == 0.f) return;
    int t = threadIdx.x;
    __shared__ float hs[CRr];
    if (t < CRr) {
        float sa_ = 0.f, sm_ = 0.f;
        const float* w1r = w1 + ((size_t)e*CRr + t) * Cc;
        for (int c = 0; c < Cc; c++) {
            sa_ += g_stat1[b*Cc + c] * w1r[c];
            sm_ += g_stat2[b*Cc + c] * w1r[c];
        }
        hs[t] = fmaxf(sa_, 0.f) + fmaxf(sm_, 0.f);
    }
    __syncthreads();
    float o = 0.f;
    const float* w2r = w2 + ((size_t)e*Cc + t) * CRr;
    #pragma unroll
    for (int j = 0; j < CRr; j++) o += hs[j] * w2r[j];
    g_ca[b*Cc + t] = sigmoidf_(o);
}

// ---------------- SA input stats ---------------------------------------------
__global__ void sastats_kernel(int e) {
    int b = blockIdx.y;
    if (g_wfull[b*Ee + e] == 0.f) return;
    __shared__ float sca[Cc];
    int t = threadIdx.x;
    sca[t] = g_ca[b*Cc + t];
    __syncthreads();
    int p = blockIdx.x * 256 + t;
    float s = 0.f, m = -INFINITY;
    for (int c = 0; c < Cc; c++) {
        float v = g_bufB[((size_t)b*Cc + c)*HW + p] * sca[c];
        s += v; m = fmaxf(m, v);
    }
    g_sain[((size_t)b*2    )*HW + p] = s * (1.f / Cc);
    g_sain[((size_t)b*2 + 1)*HW + p] = m;
}

// ---------------- SA 7x7 conv ------------------------------------------------
__global__ void saconv_kernel(const float* __restrict__ saw, int e) {
    int b = blockIdx.y;
    if (g_wfull[b*Ee + e] == 0.f) return;
    __shared__ float sw[2*49];
    int t = threadIdx.x;
    if (t < 98) sw[t] = saw[e*98 + t];
    __syncthreads();
    int p = blockIdx.x * 256 + t;
    int y = p >> 6, x = p & 63;
    float a = 0.f;
    #pragma unroll
    for (int ch = 0; ch < 2; ch++)
        for (int ky = 0; ky < 7; ky++) {
            int gy = y + ky - 3;
            if (gy < 0 || gy >= Hh) continue;
            for (int kx = 0; kx < 7; kx++) {
                int gx = x + kx - 3;
                if (gx < 0 || gx >= Ww) continue;
                a += g_sain[((size_t)b*2 + ch)*HW + gy*Ww + gx] * sw[ch*49 + ky*7 + kx];
            }
        }
    g_sa[(size_t)b*HW + p] = sigmoidf_(a);
}

// ---------------- final accumulate -------------------------------------------
__global__ void final_kernel(const float* __restrict__ adapter, const int* __restrict__ dom,
                             float* __restrict__ out, int e) {
    int b = blockIdx.y;
    float w = g_wfull[b*Ee + e];
    if (w == 0.f) return;
    int idx = blockIdx.x * 256 + threadIdx.x;
    int c = idx / HW, p = idx % HW;
    size_t off = (size_t)b * Cc * HW + idx;
    float v = g_bufB[off] * g_ca[b*Cc + c] * g_sa[(size_t)b*HW + p] + g_bufC[off];
    v = fmaxf(v, 0.f) + adapter[((size_t)e*Dd + dom[b])*Cc + c];
    out[off] += w * v;
}

// ---------------- launch -----------------------------------------------------
extern "C" void kernel_launch(void* const* d_in, const int* in_sizes, int n_in,
                              void* d_out, int out_size) {
    const float* x        = (const float*)d_in[0];
    const int*   dom      = (const int*)  d_in[1];
    const float* g_w1     = (const float*)d_in[2];
    const float* g_b1     = (const float*)d_in[3];
    const float* ln_s     = (const float*)d_in[4];
    const float* ln_b     = (const float*)d_in[5];
    const float* g_w2     = (const float*)d_in[6];
    const float* g_b2     = (const float*)d_in[7];
    const float* dom_emb  = (const float*)d_in[8];
    const float* dt_w1    = (const float*)d_in[9];
    const float* dt_bn1s  = (const float*)d_in[10];
    const float* dt_bn1b  = (const float*)d_in[11];
    const float* dt_w2    = (const float*)d_in[12];
    const float* dt_bn2s  = (const float*)d_in[13];
    const float* dt_bn2b  = (const float*)d_in[14];
    const float* gate_w   = (const float*)d_in[15];
    const float* gate_b   = (const float*)d_in[16];
    const float* c1_w     = (const float*)d_in[17];
    const float* c1_b     = (const float*)d_in[18];
    const float* bn1s     = (const float*)d_in[19];
    const float* bn1b     = (const float*)d_in[20];
    const float* c2_w     = (const float*)d_in[21];
    const float* c2_b     = (const float*)d_in[22];
    const float* bn2s     = (const float*)d_in[23];
    const float* bn2b     = (const float*)d_in[24];
    const float* ca_w1    = (const float*)d_in[25];
    const float* ca_w2    = (const float*)d_in[26];
    const float* sa_w     = (const float*)d_in[27];
    const float* adapter  = (const float*)d_in[28];
    float* out = (float*)d_out;

    float *bufB, *pxavg, *pxmax, *pstat1, *pstat2;
    uint32_t *xpk, *pkA, *pkC, *wpk;
    cudaGetSymbolAddress((void**)&bufB,  g_bufB);
    cudaGetSymbolAddress((void**)&pxavg, g_xavg);
    cudaGetSymbolAddress((void**)&pxmax, g_xmax);
    cudaGetSymbolAddress((void**)&pstat1, g_stat1);
    cudaGetSymbolAddress((void**)&pstat2, g_stat2);
    cudaGetSymbolAddress((void**)&xpk, g_xpk);
    cudaGetSymbolAddress((void**)&pkA, g_pkA);
    cudaGetSymbolAddress((void**)&pkC, g_pkC);
    cudaGetSymbolAddress((void**)&wpk, g_wpk);

    int ntot = Bz * Cc * HW;
    zero_kernel<<<(ntot + 255) / 256, 256>>>(out, ntot);

    // gate first (enables top-2 skip everywhere downstream)
    stats_kernel<<<Bz*Cc, 256>>>(x, pxavg, pxmax, -1);
    gate_kernel<<<1, 256>>>(dom, g_w1, g_b1, ln_s, ln_b, g_w2, g_b2, dom_emb);

    // weight + input packing (hi/lo bf16)
    int nw = Ee * Cc * KTOT;
    packw_kernel<<<(nw + 255) / 256, 256>>>(dt_w1, wpk + 0 * (size_t)nw);
    packw_kernel<<<(nw + 255) / 256, 256>>>(dt_w2, wpk + 1 * (size_t)nw);
    packw_kernel<<<(nw + 255) / 256, 256>>>(c1_w,  wpk + 2 * (size_t)nw);
    packw_kernel<<<(nw + 255) / 256, 256>>>(c2_w,  wpk + 3 * (size_t)nw);
    packx_kernel<<<ntot / 256, 256>>>(x, xpk);

    dim3 cgrid(32, 2, Bz);
    dim3 egrid(Cc*HW/256, Bz);
    dim3 sgrid(HW/256, Bz);

    for (int e = 0; e < Ee; e++) {
        conv_mma_kernel<<<cgrid, 256>>>(xpk, wpk, 0, nullptr, dt_bn1s, dt_bn1b,
                                        nullptr, pkA, e, MODE_GELU);
        conv_mma_kernel<<<cgrid, 256>>>(pkA, wpk, 1, nullptr, dt_bn2s, dt_bn2b,
                                        bufB, nullptr, e, MODE_NONE);
        stats_kernel<<<Bz*Cc, 256>>>(bufB, pstat1, nullptr, e);
        dgate_kernel<<<Bz, 256>>>(gate_w, gate_b, e);
        axpy_kernel<<<egrid, 256>>>(x, e);
        conv_mma_kernel<<<cgrid, 256>>>(pkC, wpk, 2, c1_b, bn1s, bn1b,
                                        nullptr, pkA, e, MODE_RELU);
        conv_mma_kernel<<<cgrid, 256>>>(pkA, wpk, 3, c2_b, bn2s, bn2b,
                                        bufB, nullptr, e, MODE_NONE);
        stats_kernel<<<Bz*Cc, 256>>>(bufB, pstat1, pstat2, e);
        camlp_kernel<<<Bz, 256>>>(ca_w1, ca_w2, e);
        sastats_kernel<<<sgrid, 256>>>(e);
        saconv_kernel<<<sgrid, 256>>>(sa_w, e);
        final_kernel<<<egrid, 256>>>(adapter, dom, out, e);
    }
}

// round 5
// speedup vs baseline: 2.3674x; 1.2215x over previous
#include <cuda_runtime.h>
#include <cuda_bf16.h>
#include <math.h>
#include <stdint.h>

// Problem constants
#define Bz   8
#define Cc   256
#define Hh   64
#define Ww   64
#define HW   (Hh*Ww)
#define Ee   4
#define Dd   4
#define CRr  16
#define GIN  (2*Cc+16)   // 528
#define NPAIR 16         // exactly 2 experts per batch item

// Conv-GEMM constants
#define KTOT   2304          // 9 taps * 256 ci
#define KCH    32            // K per chunk
#define NCHUNK (KTOT/KCH)    // 72
#define PW     66            // padded width/height
#define PIMG   (PW*PW)       // 4356 per (b,c)

// smem strides (u16 units), padded for conflict-free ldmatrix
#define SA_STR 40            // 32 k + 8 pad -> 80B rows
#define SB_STR 136           // 128 px + 8 pad -> 272B rows
#define A_PL   (128*SA_STR*2)        // 10240 B per A plane
#define B_PL   (32*SB_STR*2)         // 8704 B per B plane
#define STG_BYTES (2*A_PL + 2*B_PL)  // 37888 per stage
#define SMEM_TOTAL (2*STG_BYTES)     // 75776

// ---------------- scratch (static device globals; zero-initialized) ---------
__device__ float    g_bufB[NPAIR*Cc*HW];
__device__ float    g_bufC[NPAIR*Cc*HW];
__device__ uint32_t g_xpk [Bz*Cc*PIMG];      // packed hi/lo padded input
__device__ uint32_t g_pkA [NPAIR*Cc*PIMG];
__device__ uint32_t g_pkC [NPAIR*Cc*PIMG];
__device__ uint16_t g_wh  [16*Cc*KTOT];      // [conv*4+e][co][k] hi
__device__ uint16_t g_wl  [16*Cc*KTOT];      // lo
__device__ float g_xavg[Bz*Cc];
__device__ float g_xmax[Bz*Cc];
__device__ float g_stat1[NPAIR*Cc];
__device__ float g_stat2[NPAIR*Cc];
__device__ int   g_pairs[NPAIR];             // b*4+e
__device__ float g_wpair[NPAIR];             // routing weight
__device__ float g_g1[NPAIR];
__device__ float g_ca[NPAIR*Cc];
__device__ float g_sain[NPAIR*2*HW];
__device__ float g_sa[NPAIR*HW];

// ---------------- helpers ----------------------------------------------------
__device__ __forceinline__ float sigmoidf_(float x) { return 1.f / (1.f + __expf(-x)); }
__device__ __forceinline__ float gelu_tanh(float v) {
    float x3 = v * v * v;
    return 0.5f * v * (1.f + tanhf(0.7978845608028654f * (v + 0.044715f * x3)));
}
__device__ __forceinline__ uint32_t pack_hilo(float v) {
    __nv_bfloat16 h = __float2bfloat16(v);
    float r = v - __bfloat162float(h);
    __nv_bfloat16 l = __float2bfloat16(r);
    return (uint32_t)__bfloat16_as_ushort(h) | ((uint32_t)__bfloat16_as_ushort(l) << 16);
}
__device__ __forceinline__ uint32_t sptr(const void* p) {
    return (uint32_t)__cvta_generic_to_shared(p);
}

#define CP_ASYNC16(dst, src) \
    asm volatile("cp.async.cg.shared.global [%0], [%1], 16;" :: "r"(dst), "l"(src))
#define CP_COMMIT() asm volatile("cp.async.commit_group;" ::: "memory")
#define CP_WAIT0()  asm volatile("cp.async.wait_group 0;" ::: "memory")

#define LDSM4(r, addr) \
    asm volatile("ldmatrix.sync.aligned.m8n8.x4.shared.b16 {%0,%1,%2,%3}, [%4];" \
        : "=r"((r)[0]), "=r"((r)[1]), "=r"((r)[2]), "=r"((r)[3]) : "r"(addr))
#define LDSM4T(r, addr) \
    asm volatile("ldmatrix.sync.aligned.m8n8.x4.trans.shared.b16 {%0,%1,%2,%3}, [%4];" \
        : "=r"((r)[0]), "=r"((r)[1]), "=r"((r)[2]), "=r"((r)[3]) : "r"(addr))
#define MMA16816(d, a, b0_, b1_) \
    asm volatile("mma.sync.aligned.m16n8k16.row.col.f32.bf16.bf16.f32 " \
        "{%0,%1,%2,%3}, {%4,%5,%6,%7}, {%8,%9}, {%0,%1,%2,%3};" \
        : "+f"((d)[0]), "+f"((d)[1]), "+f"((d)[2]), "+f"((d)[3]) \
        : "r"((a)[0]), "r"((a)[1]), "r"((a)[2]), "r"((a)[3]), "r"(b0_), "r"(b1_))

// ---------------- zero init --------------------------------------------------
__global__ void zero_kernel(float* out, int n) {
    int i = blockIdx.x * blockDim.x + threadIdx.x;
    if (i < n) out[i] = 0.f;
}

// ---------------- weight pack: fp32 [E][co][ci][9] -> hi/lo split planes -----
__global__ void packw_kernel(const float* __restrict__ w,
                             uint16_t* __restrict__ oh, uint16_t* __restrict__ ol) {
    int idx = blockIdx.x * 256 + threadIdx.x;
    if (idx >= Ee * Cc * KTOT) return;
    int k  = idx % KTOT;
    int co = (idx / KTOT) % Cc;
    int e  = idx / (KTOT * Cc);
    int d  = k >> 8, ci = k & 255;
    float v = w[(((size_t)e * Cc + co) * Cc + ci) * 9 + d];
    __nv_bfloat16 h = __float2bfloat16(v);
    float r = v - __bfloat162float(h);
    __nv_bfloat16 l = __float2bfloat16(r);
    oh[idx] = __bfloat16_as_ushort(h);
    ol[idx] = __bfloat16_as_ushort(l);
}

// ---------------- x pack: fp32 -> padded packed hi/lo ------------------------
__global__ void packx_kernel(const float* __restrict__ x, uint32_t* __restrict__ out) {
    int idx = blockIdx.x * 256 + threadIdx.x;
    int p = idx & 4095, c = idx >> 12;
    int y = p >> 6, xx = p & 63;
    out[(size_t)c * PIMG + (y + 1) * PW + xx + 1] = pack_hilo(x[idx]);
}

// ---------------- spatial avg/max stats per (slot,c) -------------------------
__global__ void stats_kernel(const float* __restrict__ in,
                             float* __restrict__ avg, float* __restrict__ mx) {
    int bc = blockIdx.x;
    const float* p = in + (size_t)bc * HW;
    float s = 0.f, m = -INFINITY;
    for (int i = threadIdx.x; i < HW; i += 256) {
        float v = p[i];
        s += v; m = fmaxf(m, v);
    }
    __shared__ float ss[256], sm[256];
    int t = threadIdx.x;
    ss[t] = s; sm[t] = m; __syncthreads();
    for (int k = 128; k; k >>= 1) {
        if (t < k) { ss[t] += ss[t+k]; sm[t] = fmaxf(sm[t], sm[t+k]); }
        __syncthreads();
    }
    if (t == 0) {
        avg[bc] = ss[0] * (1.f / HW);
        if (mx) mx[bc] = sm[0];
    }
}

// ---------------- gate network + pair compaction -----------------------------
__global__ void gate_kernel(const int* __restrict__ dom,
                            const float* __restrict__ w1, const float* __restrict__ b1,
                            const float* __restrict__ lns, const float* __restrict__ lnb,
                            const float* __restrict__ w2, const float* __restrict__ b2,
                            const float* __restrict__ dom_emb) {
    __shared__ float gi[GIN];
    __shared__ float red[256];
    __shared__ float logit[Ee];
    int t = threadIdx.x;
    for (int b = 0; b < Bz; b++) {
        for (int k = t; k < GIN; k += 256) {
            float v;
            if (k < Cc)        v = g_xavg[b*Cc + k];
            else if (k < 2*Cc) v = g_xmax[b*Cc + k - Cc];
            else               v = dom_emb[dom[b]*16 + (k - 2*Cc)];
            gi[k] = v;
        }
        __syncthreads();
        float acc = b1[t];
        for (int k = 0; k < GIN; k++) acc += gi[k] * w1[k*Cc + t];
        red[t] = acc; __syncthreads();
        for (int k = 128; k; k >>= 1) { if (t < k) red[t] += red[t+k]; __syncthreads(); }
        float mu = red[0] * (1.f / Cc);
        __syncthreads();
        red[t] = acc * acc; __syncthreads();
        for (int k = 128; k; k >>= 1) { if (t < k) red[t] += red[t+k]; __syncthreads(); }
        float var = red[0] * (1.f / Cc) - mu * mu;
        __syncthreads();
        float h = (acc - mu) * rsqrtf(var + 1e-5f) * lns[t] + lnb[t];
        h = fmaxf(h, 0.f);
        for (int e = 0; e < Ee; e++) {
            red[t] = h * w2[t*Ee + e]; __syncthreads();
            for (int k = 128; k; k >>= 1) { if (t < k) red[t] += red[t+k]; __syncthreads(); }
            if (t == 0) logit[e] = red[0] + b2[e];
            __syncthreads();
        }
        if (t == 0) {
            float mx = logit[0];
            for (int e = 1; e < Ee; e++) mx = fmaxf(mx, logit[e]);
            float pr[Ee], s = 0.f;
            for (int e = 0; e < Ee; e++) { pr[e] = __expf(logit[e] - mx); s += pr[e]; }
            for (int e = 0; e < Ee; e++) pr[e] /= s;
            int i1 = 0;
            for (int e = 1; e < Ee; e++) if (pr[e] > pr[i1]) i1 = e;
            int i2 = -1;
            for (int e = 0; e < Ee; e++) if (e != i1 && (i2 < 0 || pr[e] > pr[i2])) i2 = e;
            float s2 = pr[i1] + pr[i2];
            int lo = i1 < i2 ? i1 : i2;
            int hi = i1 < i2 ? i2 : i1;
            g_pairs[b*2 + 0] = b*4 + lo;  g_wpair[b*2 + 0] = pr[lo] / s2;
            g_pairs[b*2 + 1] = b*4 + hi;  g_wpair[b*2 + 1] = pr[hi] / s2;
        }
        __syncthreads();
    }
}

// ---------------- conv 3x3 via mma.sync bf16x3, cp.async pipelined -----------
#define MODE_GELU 0
#define MODE_NONE 1
#define MODE_RELU 2

__global__ __launch_bounds__(256, 1) void conv_mma_kernel(
    const uint32_t* __restrict__ pkin, int inByPair,
    const uint16_t* __restrict__ wh, const uint16_t* __restrict__ wl,
    int convIdx, const float* __restrict__ bias,
    const float* __restrict__ bns, const float* __restrict__ bnb,
    float* __restrict__ f32out, uint32_t* __restrict__ pkout, int mode)
{
    int pair = blockIdx.z;
    int pe = g_pairs[pair];
    int b = pe >> 2, e = pe & 3;
    int cob = blockIdx.y * 128;
    int pxb = blockIdx.x * 128;
    int y0  = blockIdx.x * 2;

    extern __shared__ __align__(16) char smem[];

    int tid  = threadIdx.x;
    int lane = tid & 31, wid = tid >> 5;
    int wco  = (wid & 3) * 32;
    int wpx  = (wid >> 2) * 64;

    const uint16_t* whrow = wh + ((size_t)(convIdx*Ee + e) * Cc + cob) * KTOT;
    const uint16_t* wlrow = wl + ((size_t)(convIdx*Ee + e) * Cc + cob) * KTOT;
    const uint32_t* prow  = pkin + (size_t)(inByPair ? pair : b) * Cc * PIMG;

    // A cp.async roles: granule (co, j): row = 64B = 4 granules of 16B
    int coG = tid >> 2, jG = tid & 3;
    // B staging roles
    int kB = tid >> 3, pB = (tid & 7) * 16;
    int yB = y0 + (pB >> 6) + 1;
    int xB = (pB & 63) + 1;

    float acc[2][8][4];
    #pragma unroll
    for (int mt = 0; mt < 2; mt++)
        #pragma unroll
        for (int nt = 0; nt < 8; nt++)
            #pragma unroll
            for (int q = 0; q < 4; q++) acc[mt][nt][q] = 0.f;

    uint32_t rbh[8], rbl[8];

    // --- issue A (cp.async) for chunk c into stage s ---
    #define ISSUE_A(c, s) do { \
        char* _ab = smem + (s)*STG_BYTES; \
        size_t _kb = (size_t)(c) * KCH + jG*8; \
        CP_ASYNC16(sptr(_ab + coG*80 + jG*16),            whrow + (size_t)coG*KTOT + _kb); \
        CP_ASYNC16(sptr(_ab + (coG+64)*80 + jG*16),       whrow + (size_t)(coG+64)*KTOT + _kb); \
        CP_ASYNC16(sptr(_ab + A_PL + coG*80 + jG*16),     wlrow + (size_t)coG*KTOT + _kb); \
        CP_ASYNC16(sptr(_ab + A_PL + (coG+64)*80 + jG*16),wlrow + (size_t)(coG+64)*KTOT + _kb); \
    } while (0)

    // --- load B regs for chunk c ---
    #define LOAD_B(c) do { \
        int _d = (c) >> 3, _ci0 = ((c) & 7) << 5; \
        int _ky = _d / 3, _kx = _d - 3*_ky; \
        const uint32_t* _bp = prow + (size_t)(_ci0 + kB)*PIMG + (yB + _ky - 1)*PW + (xB + _kx - 1); \
        _Pragma("unroll") \
        for (int _i = 0; _i < 8; _i++) { \
            uint32_t _u = _bp[2*_i], _w = _bp[2*_i+1]; \
            rbh[_i] = (_u & 0xFFFFu) | (_w << 16); \
            rbl[_i] = (_u >> 16)     | (_w & 0xFFFF0000u); \
        } \
    } while (0)

    #define STS_B(s) do { \
        uint16_t* _sbh = (uint16_t*)(smem + (s)*STG_BYTES + 2*A_PL); \
        uint16_t* _sbl = (uint16_t*)(smem + (s)*STG_BYTES + 2*A_PL + B_PL); \
        _Pragma("unroll") \
        for (int _i = 0; _i < 8; _i++) { \
            *(uint32_t*)(_sbh + kB*SB_STR + pB + 2*_i) = rbh[_i]; \
            *(uint32_t*)(_sbl + kB*SB_STR + pB + 2*_i) = rbl[_i]; \
        } \
    } while (0)

    // prologue
    ISSUE_A(0, 0); CP_COMMIT();
    LOAD_B(0);
    STS_B(0);

    for (int c = 0; c < NCHUNK; c++) {
        int s = c & 1;
        CP_WAIT0();
        __syncthreads();
        if (c + 1 < NCHUNK) {
            ISSUE_A(c + 1, s ^ 1); CP_COMMIT();
            LOAD_B(c + 1);
        }
        // compute chunk c from stage s
        uint16_t* sAh = (uint16_t*)(smem + s*STG_BYTES);
        uint16_t* sAl = (uint16_t*)(smem + s*STG_BYTES + A_PL);
        uint16_t* sBh = (uint16_t*)(smem + s*STG_BYTES + 2*A_PL);
        uint16_t* sBl = (uint16_t*)(smem + s*STG_BYTES + 2*A_PL + B_PL);
        #pragma unroll
        for (int ks = 0; ks < 2; ks++) {
            int kO = ks * 16;
            uint32_t ah[2][4], al[2][4], bh[4][4], bl[4][4];
            #pragma unroll
            for (int mt = 0; mt < 2; mt++) {
                uint32_t ad = sptr(sAh + (wco + mt*16 + (lane & 15))*SA_STR + kO + (lane >> 4)*8);
                LDSM4(ah[mt], ad);
                ad = sptr(sAl + (wco + mt*16 + (lane & 15))*SA_STR + kO + (lane >> 4)*8);
                LDSM4(al[mt], ad);
            }
            #pragma unroll
            for (int nt = 0; nt < 4; nt++) {
                uint32_t bd = sptr(sBh + (kO + (lane & 15))*SB_STR + wpx + nt*16 + (lane >> 4)*8);
                LDSM4T(bh[nt], bd);
                bd = sptr(sBl + (kO + (lane & 15))*SB_STR + wpx + nt*16 + (lane >> 4)*8);
                LDSM4T(bl[nt], bd);
            }
            #pragma unroll
            for (int mt = 0; mt < 2; mt++) {
                #pragma unroll
                for (int n8 = 0; n8 < 8; n8++) {
                    uint32_t bh0 = bh[n8 >> 1][(n8 & 1)*2], bh1 = bh[n8 >> 1][(n8 & 1)*2 + 1];
                    uint32_t bl0 = bl[n8 >> 1][(n8 & 1)*2], bl1 = bl[n8 >> 1][(n8 & 1)*2 + 1];
                    MMA16816(acc[mt][n8], ah[mt], bh0, bh1);
                    MMA16816(acc[mt][n8], ah[mt], bl0, bl1);
                    MMA16816(acc[mt][n8], al[mt], bh0, bh1);
                }
            }
        }
        if (c + 1 < NCHUNK) STS_B(s ^ 1);
    }

    // epilogue: bias -> BN -> act -> store f32 and/or packed
    int r  = lane >> 2;
    int cp = (lane & 3) * 2;
    #pragma unroll
    for (int mt = 0; mt < 2; mt++) {
        #pragma unroll
        for (int hf = 0; hf < 2; hf++) {
            int co = cob + wco + mt*16 + r + hf*8;
            float bsc = bns[e*Cc + co];
            float bsh = bnb[e*Cc + co];
            float bi  = bias ? bias[e*Cc + co] : 0.f;
            #pragma unroll
            for (int n8 = 0; n8 < 8; n8++) {
                int px = pxb + wpx + n8*8 + cp;
                float v0 = (acc[mt][n8][hf*2 + 0] + bi) * bsc + bsh;
                float v1 = (acc[mt][n8][hf*2 + 1] + bi) * bsc + bsh;
                if (mode == MODE_GELU)      { v0 = gelu_tanh(v0); v1 = gelu_tanh(v1); }
                else if (mode == MODE_RELU) { v0 = fmaxf(v0, 0.f); v1 = fmaxf(v1, 0.f); }
                if (f32out) {
                    float2 f2 = make_float2(v0, v1);
                    *(float2*)(f32out + (size_t)(pair*Cc + co)*HW + px) = f2;
                }
                if (pkout) {
                    int y = px >> 6, x = px & 63;
                    size_t o = (size_t)(pair*Cc + co)*PIMG + (y + 1)*PW + x + 1;
                    pkout[o]     = pack_hilo(v0);
                    pkout[o + 1] = pack_hilo(v1);
                }
            }
        }
    }
    #undef ISSUE_A
    #undef LOAD_B
    #undef STS_B
}

// ---------------- domain gate (per pair) -------------------------------------
__global__ void dgate_kernel(const float* __restrict__ gw, const float* __restrict__ gb) {
    int pair = blockIdx.x;
    int e = g_pairs[pair] & 3;
    int t = threadIdx.x;
    __shared__ float red[256];
    red[t] = g_stat1[pair*Cc + t] * gw[e*Cc + t];
    __syncthreads();
    for (int k = 128; k; k >>= 1) { if (t < k) red[t] += red[t+k]; __syncthreads(); }
    if (t == 0) g_g1[pair] = sigmoidf_(red[0] + gb[e]);
}

// ---------------- bufC = x + g1*bufB; emit packed padded ---------------------
__global__ void axpy_kernel(const float* __restrict__ x) {
    int pair = blockIdx.y;
    int b = g_pairs[pair] >> 2;
    int i = blockIdx.x * 256 + threadIdx.x;
    size_t po = (size_t)pair * Cc * HW + i;
    float v = x[(size_t)b * Cc * HW + i] + g_g1[pair] * g_bufB[po];
    g_bufC[po] = v;
    int c = i >> 12, p = i & 4095;
    g_pkC[((size_t)pair*Cc + c) * PIMG + ((p>>6) + 1) * PW + (p & 63) + 1] = pack_hilo(v);
}

// ---------------- channel attention MLP --------------------------------------
__global__ void camlp_kernel(const float* __restrict__ w1, const float* __restrict__ w2) {
    int pair = blockIdx.x;
    int e = g_pairs[pair] & 3;
    int t = threadIdx.x;
    __shared__ float hs[CRr];
    if (t < CRr) {
        float sa_ = 0.f, sm_ = 0.f;
        const float* w1r = w1 + ((size_t)e*CRr + t) * Cc;
        for (int c = 0; c < Cc; c++) {
            sa_ += g_stat1[pair*Cc + c] * w1r[c];
            sm_ += g_stat2[pair*Cc + c] * w1r[c];
        }
        hs[t] = fmaxf(sa_, 0.f) + fmaxf(sm_, 0.f);
    }
    __syncthreads();
    float o = 0.f;
    const float* w2r = w2 + ((size_t)e*Cc + t) * CRr;
    #pragma unroll
    for (int j = 0; j < CRr; j++) o += hs[j] * w2r[j];
    g_ca[pair*Cc + t] = sigmoidf_(o);
}

// ---------------- SA input stats ---------------------------------------------
__global__ void sastats_kernel() {
    int pair = blockIdx.y;
    __shared__ float sca[Cc];
    int t = threadIdx.x;
    sca[t] = g_ca[pair*Cc + t];
    __syncthreads();
    int p = blockIdx.x * 256 + t;
    float s = 0.f, m = -INFINITY;
    for (int c = 0; c < Cc; c++) {
        float v = g_bufB[((size_t)pair*Cc + c)*HW + p] * sca[c];
        s += v; m = fmaxf(m, v);
    }
    g_sain[((size_t)pair*2    )*HW + p] = s * (1.f / Cc);
    g_sain[((size_t)pair*2 + 1)*HW + p] = m;
}

// ---------------- SA 7x7 conv ------------------------------------------------
__global__ void saconv_kernel(const float* __restrict__ saw) {
    int pair = blockIdx.y;
    int e = g_pairs[pair] & 3;
    __shared__ float sw[2*49];
    int t = threadIdx.x;
    if (t < 98) sw[t] = saw[e*98 + t];
    __syncthreads();
    int p = blockIdx.x * 256 + t;
    int y = p >> 6, x = p & 63;
    float a = 0.f;
    #pragma unroll
    for (int ch = 0; ch < 2; ch++)
        for (int ky = 0; ky < 7; ky++) {
            int gy = y + ky - 3;
            if (gy < 0 || gy >= Hh) continue;
            for (int kx = 0; kx < 7; kx++) {
                int gx = x + kx - 3;
                if (gx < 0 || gx >= Ww) continue;
                a += g_sain[((size_t)pair*2 + ch)*HW + gy*Ww + gx] * sw[ch*49 + ky*7 + kx];
            }
        }
    g_sa[(size_t)pair*HW + p] = sigmoidf_(a);
}

// ---------------- final accumulate (2 commutative adds per elem) -------------
__global__ void final_kernel(const float* __restrict__ adapter, const int* __restrict__ dom,
                             float* __restrict__ out) {
    int pair = blockIdx.y;
    int pe = g_pairs[pair];
    int b = pe >> 2, e = pe & 3;
    float w = g_wpair[pair];
    int idx = blockIdx.x * 256 + threadIdx.x;
    int c = idx / HW, p = idx % HW;
    size_t po = (size_t)pair * Cc * HW + idx;
    float v = g_bufB[po] * g_ca[pair*Cc + c] * g_sa[(size_t)pair*HW + p] + g_bufC[po];
    v = fmaxf(v, 0.f) + adapter[((size_t)e*Dd + dom[b])*Cc + c];
    atomicAdd(out + (size_t)b * Cc * HW + idx, w * v);
}

// ---------------- launch -----------------------------------------------------
extern "C" void kernel_launch(void* const* d_in, const int* in_sizes, int n_in,
                              void* d_out, int out_size) {
    const float* x        = (const float*)d_in[0];
    const int*   dom      = (const int*)  d_in[1];
    const float* g_w1     = (const float*)d_in[2];
    const float* g_b1     = (const float*)d_in[3];
    const float* ln_s     = (const float*)d_in[4];
    const float* ln_b     = (const float*)d_in[5];
    const float* g_w2     = (const float*)d_in[6];
    const float* g_b2     = (const float*)d_in[7];
    const float* dom_emb  = (const float*)d_in[8];
    const float* dt_w1    = (const float*)d_in[9];
    const float* dt_bn1s  = (const float*)d_in[10];
    const float* dt_bn1b  = (const float*)d_in[11];
    const float* dt_w2    = (const float*)d_in[12];
    const float* dt_bn2s  = (const float*)d_in[13];
    const float* dt_bn2b  = (const float*)d_in[14];
    const float* gate_w   = (const float*)d_in[15];
    const float* gate_b   = (const float*)d_in[16];
    const float* c1_w     = (const float*)d_in[17];
    const float* c1_b     = (const float*)d_in[18];
    const float* bn1s     = (const float*)d_in[19];
    const float* bn1b     = (const float*)d_in[20];
    const float* c2_w     = (const float*)d_in[21];
    const float* c2_b     = (const float*)d_in[22];
    const float* bn2s     = (const float*)d_in[23];
    const float* bn2b     = (const float*)d_in[24];
    const float* ca_w1    = (const float*)d_in[25];
    const float* ca_w2    = (const float*)d_in[26];
    const float* sa_w     = (const float*)d_in[27];
    const float* adapter  = (const float*)d_in[28];
    float* out = (float*)d_out;

    float *bufB, *pxavg, *pxmax, *pstat1, *pstat2;
    uint32_t *xpk, *pkA, *pkC;
    uint16_t *wh, *wl;
    cudaGetSymbolAddress((void**)&bufB,  g_bufB);
    cudaGetSymbolAddress((void**)&pxavg, g_xavg);
    cudaGetSymbolAddress((void**)&pxmax, g_xmax);
    cudaGetSymbolAddress((void**)&pstat1, g_stat1);
    cudaGetSymbolAddress((void**)&pstat2, g_stat2);
    cudaGetSymbolAddress((void**)&xpk, g_xpk);
    cudaGetSymbolAddress((void**)&pkA, g_pkA);
    cudaGetSymbolAddress((void**)&pkC, g_pkC);
    cudaGetSymbolAddress((void**)&wh, g_wh);
    cudaGetSymbolAddress((void**)&wl, g_wl);

    static int smem_set = 0;
    if (!smem_set) {
        cudaFuncSetAttribute(conv_mma_kernel,
                             cudaFuncAttributeMaxDynamicSharedMemorySize, SMEM_TOTAL);
        smem_set = 1;
    }

    int ntot = Bz * Cc * HW;
    zero_kernel<<<(ntot + 255) / 256, 256>>>(out, ntot);

    // gate first (top-2 pair compaction enables all downstream batching)
    stats_kernel<<<Bz*Cc, 256>>>(x, pxavg, pxmax);
    gate_kernel<<<1, 256>>>(dom, g_w1, g_b1, ln_s, ln_b, g_w2, g_b2, dom_emb);

    // weight + input packing (split hi/lo planes for weights)
    int nw = Ee * Cc * KTOT;
    packw_kernel<<<(nw + 255) / 256, 256>>>(dt_w1, wh + 0 * (size_t)nw, wl + 0 * (size_t)nw);
    packw_kernel<<<(nw + 255) / 256, 256>>>(dt_w2, wh + 1 * (size_t)nw, wl + 1 * (size_t)nw);
    packw_kernel<<<(nw + 255) / 256, 256>>>(c1_w,  wh + 2 * (size_t)nw, wl + 2 * (size_t)nw);
    packw_kernel<<<(nw + 255) / 256, 256>>>(c2_w,  wh + 3 * (size_t)nw, wl + 3 * (size_t)nw);
    packx_kernel<<<ntot / 256, 256>>>(x, xpk);

    dim3 cgrid(32, 2, NPAIR);
    dim3 egrid(Cc*HW/256, NPAIR);
    dim3 sgrid(HW/256, NPAIR);

    // stage-batched over all 16 active (b,e) pairs
    conv_mma_kernel<<<cgrid, 256, SMEM_TOTAL>>>(xpk, 0, wh, wl, 0, nullptr, dt_bn1s, dt_bn1b,
                                                nullptr, pkA, MODE_GELU);
    conv_mma_kernel<<<cgrid, 256, SMEM_TOTAL>>>(pkA, 1, wh, wl, 1, nullptr, dt_bn2s, dt_bn2b,
                                                bufB, nullptr, MODE_NONE);
    stats_kernel<<<NPAIR*Cc, 256>>>(bufB, pstat1, nullptr);
    dgate_kernel<<<NPAIR, 256>>>(gate_w, gate_b);
    axpy_kernel<<<egrid, 256>>>(x);
    conv_mma_kernel<<<cgrid, 256, SMEM_TOTAL>>>(pkC, 1, wh, wl, 2, c1_b, bn1s, bn1b,
                                                nullptr, pkA, MODE_RELU);
    conv_mma_kernel<<<cgrid, 256, SMEM_TOTAL>>>(pkA, 1, wh, wl, 3, c2_b, bn2s, bn2b,
                                                bufB, nullptr, MODE_NONE);
    stats_kernel<<<NPAIR*Cc, 256>>>(bufB, pstat1, pstat2);
    camlp_kernel<<<NPAIR, 256>>>(ca_w1, ca_w2);
    sastats_kernel<<<sgrid, 256>>>();
    saconv_kernel<<<sgrid, 256>>>(sa_w);
    final_kernel<<<egrid, 256>>>(adapter, dom, out);
}

// round 8
// speedup vs baseline: 2.6942x; 1.1380x over previous
#include <cuda_runtime.h>
#include <cuda_bf16.h>
#include <math.h>
#include <stdint.h>

// Problem constants
#define Bz   8
#define Cc   256
#define Hh   64
#define Ww   64
#define HW   (Hh*Ww)
#define Ee   4
#define Dd   4
#define CRr  16
#define GIN  (2*Cc+16)   // 528
#define NPAIR 16         // exactly 2 experts per batch item

// Conv-GEMM constants
#define KTOT   2304          // 9 taps * 256 ci
#define KCH    64            // K per chunk
#define NCHUNK (KTOT/KCH)    // 36
#define PW     66            // padded width/height
#define PIMG   (PW*PW)       // 4356 per (b,c)

// smem strides (u16 units), padded for conflict-free ldmatrix, rows 16B-aligned
#define SA_STR 72            // 64 k + 8 pad -> 144B rows (16B aligned, distinct banks)
#define SB_STR 136           // 128 px + 8 pad -> 272B rows
#define A_PL   (128*SA_STR*2)        // 18432 B per A plane
#define B_PL   (64*SB_STR*2)         // 17408 B per B plane
#define STG_BYTES (2*A_PL + 2*B_PL)  // 71680 per stage
#define SMEM_TOTAL (2*STG_BYTES)     // 143360

// ---------------- scratch (static device globals; zero-initialized) ---------
__device__ float    g_bufB[NPAIR*Cc*HW];
__device__ float    g_bufC[NPAIR*Cc*HW];
__device__ uint32_t g_xpk [Bz*Cc*PIMG];      // packed hi/lo padded input
__device__ uint32_t g_pkA [NPAIR*Cc*PIMG];
__device__ uint32_t g_pkC [NPAIR*Cc*PIMG];
__device__ __align__(16) uint16_t g_wh[16*Cc*KTOT];   // [conv*4+e][co][k] hi
__device__ __align__(16) uint16_t g_wl[16*Cc*KTOT];   // lo
__device__ float g_xavg[Bz*Cc];
__device__ float g_xmax[Bz*Cc];
__device__ float g_stat1[NPAIR*Cc];
__device__ float g_stat2[NPAIR*Cc];
__device__ int   g_pairs[NPAIR];             // b*4+e
__device__ float g_wpair[NPAIR];             // routing weight
__device__ float g_g1[NPAIR];
__device__ float g_ca[NPAIR*Cc];
__device__ float g_sain[NPAIR*2*HW];
__device__ float g_sa[NPAIR*HW];

// ---------------- helpers ----------------------------------------------------
__device__ __forceinline__ float sigmoidf_(float x) { return 1.f / (1.f + __expf(-x)); }
__device__ __forceinline__ float gelu_tanh(float v) {
    float x3 = v * v * v;
    return 0.5f * v * (1.f + tanhf(0.7978845608028654f * (v + 0.044715f * x3)));
}
__device__ __forceinline__ uint32_t pack_hilo(float v) {
    __nv_bfloat16 h = __float2bfloat16(v);
    float r = v - __bfloat162float(h);
    __nv_bfloat16 l = __float2bfloat16(r);
    return (uint32_t)__bfloat16_as_ushort(h) | ((uint32_t)__bfloat16_as_ushort(l) << 16);
}
__device__ __forceinline__ uint32_t sptr(const void* p) {
    return (uint32_t)__cvta_generic_to_shared(p);
}

#define CP_ASYNC16(dst, src) \
    asm volatile("cp.async.cg.shared.global [%0], [%1], 16;" :: "r"(dst), "l"(src))
#define CP_COMMIT() asm volatile("cp.async.commit_group;" ::: "memory")
#define CP_WAIT0()  asm volatile("cp.async.wait_group 0;" ::: "memory")

#define LDSM4(r, addr) \
    asm volatile("ldmatrix.sync.aligned.m8n8.x4.shared.b16 {%0,%1,%2,%3}, [%4];" \
        : "=r"((r)[0]), "=r"((r)[1]), "=r"((r)[2]), "=r"((r)[3]) : "r"(addr))
#define LDSM4T(r, addr) \
    asm volatile("ldmatrix.sync.aligned.m8n8.x4.trans.shared.b16 {%0,%1,%2,%3}, [%4];" \
        : "=r"((r)[0]), "=r"((r)[1]), "=r"((r)[2]), "=r"((r)[3]) : "r"(addr))
#define MMA16816(d, a, b0_, b1_) \
    asm volatile("mma.sync.aligned.m16n8k16.row.col.f32.bf16.bf16.f32 " \
        "{%0,%1,%2,%3}, {%4,%5,%6,%7}, {%8,%9}, {%0,%1,%2,%3};" \
        : "+f"((d)[0]), "+f"((d)[1]), "+f"((d)[2]), "+f"((d)[3]) \
        : "r"((a)[0]), "r"((a)[1]), "r"((a)[2]), "r"((a)[3]), "r"(b0_), "r"(b1_))

// ---------------- zero init --------------------------------------------------
__global__ void zero_kernel(float* out, int n) {
    int i = blockIdx.x * blockDim.x + threadIdx.x;
    if (i < n) out[i] = 0.f;
}

// ---------------- weight pack: fp32 [E][co][ci][9] -> hi/lo split planes -----
__global__ void packw_kernel(const float* __restrict__ w,
                             uint16_t* __restrict__ oh, uint16_t* __restrict__ ol) {
    int idx = blockIdx.x * 256 + threadIdx.x;
    if (idx >= Ee * Cc * KTOT) return;
    int k  = idx % KTOT;
    int co = (idx / KTOT) % Cc;
    int e  = idx / (KTOT * Cc);
    int d  = k >> 8, ci = k & 255;
    float v = w[(((size_t)e * Cc + co) * Cc + ci) * 9 + d];
    __nv_bfloat16 h = __float2bfloat16(v);
    float r = v - __bfloat162float(h);
    __nv_bfloat16 l = __float2bfloat16(r);
    oh[idx] = __bfloat16_as_ushort(h);
    ol[idx] = __bfloat16_as_ushort(l);
}

// ---------------- x pack: fp32 -> padded packed hi/lo ------------------------
__global__ void packx_kernel(const float* __restrict__ x, uint32_t* __restrict__ out) {
    int idx = blockIdx.x * 256 + threadIdx.x;
    int p = idx & 4095, c = idx >> 12;
    int y = p >> 6, xx = p & 63;
    out[(size_t)c * PIMG + (y + 1) * PW + xx + 1] = pack_hilo(x[idx]);
}

// ---------------- spatial avg/max stats per (slot,c) -------------------------
__global__ void stats_kernel(const float* __restrict__ in,
                             float* __restrict__ avg, float* __restrict__ mx) {
    int bc = blockIdx.x;
    const float* p = in + (size_t)bc * HW;
    float s = 0.f, m = -INFINITY;
    for (int i = threadIdx.x; i < HW; i += 256) {
        float v = p[i];
        s += v; m = fmaxf(m, v);
    }
    __shared__ float ss[256], sm[256];
    int t = threadIdx.x;
    ss[t] = s; sm[t] = m; __syncthreads();
    for (int k = 128; k; k >>= 1) {
        if (t < k) { ss[t] += ss[t+k]; sm[t] = fmaxf(sm[t], sm[t+k]); }
        __syncthreads();
    }
    if (t == 0) {
        avg[bc] = ss[0] * (1.f / HW);
        if (mx) mx[bc] = sm[0];
    }
}

// ---------------- gate network + pair compaction -----------------------------
__global__ void gate_kernel(const int* __restrict__ dom,
                            const float* __restrict__ w1, const float* __restrict__ b1,
                            const float* __restrict__ lns, const float* __restrict__ lnb,
                            const float* __restrict__ w2, const float* __restrict__ b2,
                            const float* __restrict__ dom_emb) {
    __shared__ float gi[GIN];
    __shared__ float red[256];
    __shared__ float logit[Ee];
    int t = threadIdx.x;
    for (int b = 0; b < Bz; b++) {
        for (int k = t; k < GIN; k += 256) {
            float v;
            if (k < Cc)        v = g_xavg[b*Cc + k];
            else if (k < 2*Cc) v = g_xmax[b*Cc + k - Cc];
            else               v = dom_emb[dom[b]*16 + (k - 2*Cc)];
            gi[k] = v;
        }
        __syncthreads();
        float acc = b1[t];
        for (int k = 0; k < GIN; k++) acc += gi[k] * w1[k*Cc + t];
        red[t] = acc; __syncthreads();
        for (int k = 128; k; k >>= 1) { if (t < k) red[t] += red[t+k]; __syncthreads(); }
        float mu = red[0] * (1.f / Cc);
        __syncthreads();
        red[t] = acc * acc; __syncthreads();
        for (int k = 128; k; k >>= 1) { if (t < k) red[t] += red[t+k]; __syncthreads(); }
        float var = red[0] * (1.f / Cc) - mu * mu;
        __syncthreads();
        float h = (acc - mu) * rsqrtf(var + 1e-5f) * lns[t] + lnb[t];
        h = fmaxf(h, 0.f);
        for (int e = 0; e < Ee; e++) {
            red[t] = h * w2[t*Ee + e]; __syncthreads();
            for (int k = 128; k; k >>= 1) { if (t < k) red[t] += red[t+k]; __syncthreads(); }
            if (t == 0) logit[e] = red[0] + b2[e];
            __syncthreads();
        }
        if (t == 0) {
            float mx = logit[0];
            for (int e = 1; e < Ee; e++) mx = fmaxf(mx, logit[e]);
            float pr[Ee], s = 0.f;
            for (int e = 0; e < Ee; e++) { pr[e] = __expf(logit[e] - mx); s += pr[e]; }
            for (int e = 0; e < Ee; e++) pr[e] /= s;
            int i1 = 0;
            for (int e = 1; e < Ee; e++) if (pr[e] > pr[i1]) i1 = e;
            int i2 = -1;
            for (int e = 0; e < Ee; e++) if (e != i1 && (i2 < 0 || pr[e] > pr[i2])) i2 = e;
            float s2 = pr[i1] + pr[i2];
            int lo = i1 < i2 ? i1 : i2;
            int hi = i1 < i2 ? i2 : i1;
            g_pairs[b*2 + 0] = b*4 + lo;  g_wpair[b*2 + 0] = pr[lo] / s2;
            g_pairs[b*2 + 1] = b*4 + hi;  g_wpair[b*2 + 1] = pr[hi] / s2;
        }
        __syncthreads();
    }
}

// ---------------- conv 3x3 via mma.sync bf16x3, 512 thr, KCH=64 --------------
#define MODE_GELU 0
#define MODE_NONE 1
#define MODE_RELU 2

__global__ __launch_bounds__(512, 1) void conv_mma_kernel(
    const uint32_t* __restrict__ pkin, int inByPair,
    const uint16_t* __restrict__ wh, const uint16_t* __restrict__ wl,
    int convIdx, const float* __restrict__ bias,
    const float* __restrict__ bns, const float* __restrict__ bnb,
    float* __restrict__ f32out, uint32_t* __restrict__ pkout, int mode)
{
    int pair = blockIdx.z;
    int pe = g_pairs[pair];
    int b = pe >> 2, e = pe & 3;
    int cob = blockIdx.y * 128;
    int pxb = blockIdx.x * 128;
    int y0  = blockIdx.x * 2;

    extern __shared__ __align__(16) char smem[];

    int tid  = threadIdx.x;
    int lane = tid & 31, wid = tid >> 5;     // 16 warps
    int wco  = (wid & 3) * 32;               // warp co offset (4 groups)
    int wpx  = (wid >> 2) * 32;              // warp px offset (4 groups)

    const uint16_t* whrow = wh + ((size_t)(convIdx*Ee + e) * Cc + cob) * KTOT;
    const uint16_t* wlrow = wl + ((size_t)(convIdx*Ee + e) * Cc + cob) * KTOT;
    const uint32_t* prow  = pkin + (size_t)(inByPair ? pair : b) * Cc * PIMG;

    // A cp.async roles: 128 co-rows x 8 granules(16B) per plane; 512 thr -> 2 rows each
    int coG = tid >> 3, jG = tid & 7;
    // B staging roles: 64 k-rows x 128 px; thread: 1 row, 16 px
    int kB = tid >> 3, pB = (tid & 7) * 16;
    int yB = y0 + (pB >> 6) + 1;
    int xB = (pB & 63) + 1;

    float acc[2][4][4];
    #pragma unroll
    for (int mt = 0; mt < 2; mt++)
        #pragma unroll
        for (int nt = 0; nt < 4; nt++)
            #pragma unroll
            for (int q = 0; q < 4; q++) acc[mt][nt][q] = 0.f;

    uint32_t rbh[8], rbl[8];

    #define ISSUE_A(c, s) do { \
        char* _ab = smem + (s)*STG_BYTES; \
        size_t _kb = (size_t)(c) * KCH + jG*8; \
        CP_ASYNC16(sptr(_ab + coG*144 + jG*16),             whrow + (size_t)coG*KTOT + _kb); \
        CP_ASYNC16(sptr(_ab + (coG+64)*144 + jG*16),        whrow + (size_t)(coG+64)*KTOT + _kb); \
        CP_ASYNC16(sptr(_ab + A_PL + coG*144 + jG*16),      wlrow + (size_t)coG*KTOT + _kb); \
        CP_ASYNC16(sptr(_ab + A_PL + (coG+64)*144 + jG*16), wlrow + (size_t)(coG+64)*KTOT + _kb); \
    } while (0)

    #define LOAD_B(c) do { \
        int _tap = (c) >> 2; \
        int _ky = _tap / 3, _kx = _tap - 3*_ky; \
        int _ci = (((c) & 3) << 6) + kB; \
        const uint32_t* _bp = prow + (size_t)_ci*PIMG + (yB + _ky - 1)*PW + (xB + _kx - 1); \
        _Pragma("unroll") \
        for (int _i = 0; _i < 8; _i++) { \
            uint32_t _u = _bp[2*_i], _w = _bp[2*_i+1]; \
            rbh[_i] = (_u & 0xFFFFu) | (_w << 16); \
            rbl[_i] = (_u >> 16)     | (_w & 0xFFFF0000u); \
        } \
    } while (0)

    #define STS_B(s) do { \
        uint16_t* _sbh = (uint16_t*)(smem + (s)*STG_BYTES + 2*A_PL); \
        uint16_t* _sbl = (uint16_t*)(smem + (s)*STG_BYTES + 2*A_PL + B_PL); \
        _Pragma("unroll") \
        for (int _i = 0; _i < 8; _i++) { \
            *(uint32_t*)(_sbh + kB*SB_STR + pB + 2*_i) = rbh[_i]; \
            *(uint32_t*)(_sbl + kB*SB_STR + pB + 2*_i) = rbl[_i]; \
        } \
    } while (0)

    // prologue
    ISSUE_A(0, 0); CP_COMMIT();
    LOAD_B(0);
    STS_B(0);

    for (int c = 0; c < NCHUNK; c++) {
        int s = c & 1;
        CP_WAIT0();
        __syncthreads();
        if (c + 1 < NCHUNK) {
            ISSUE_A(c + 1, s ^ 1); CP_COMMIT();
            LOAD_B(c + 1);
        }
        uint16_t* sAh = (uint16_t*)(smem + s*STG_BYTES);
        uint16_t* sAl = (uint16_t*)(smem + s*STG_BYTES + A_PL);
        uint16_t* sBh = (uint16_t*)(smem + s*STG_BYTES + 2*A_PL);
        uint16_t* sBl = (uint16_t*)(smem + s*STG_BYTES + 2*A_PL + B_PL);
        #pragma unroll
        for (int ks = 0; ks < 4; ks++) {
            int kO = ks * 16;
            uint32_t ah[2][4], al[2][4], bh[2][4], bl[2][4];
            #pragma unroll
            for (int mt = 0; mt < 2; mt++) {
                uint32_t ad = sptr(sAh + (wco + mt*16 + (lane & 15))*SA_STR + kO + (lane >> 4)*8);
                LDSM4(ah[mt], ad);
                ad = sptr(sAl + (wco + mt*16 + (lane & 15))*SA_STR + kO + (lane >> 4)*8);
                LDSM4(al[mt], ad);
            }
            #pragma unroll
            for (int nt = 0; nt < 2; nt++) {
                uint32_t bd = sptr(sBh + (kO + (lane & 15))*SB_STR + wpx + nt*16 + (lane >> 4)*8);
                LDSM4T(bh[nt], bd);
                bd = sptr(sBl + (kO + (lane & 15))*SB_STR + wpx + nt*16 + (lane >> 4)*8);
                LDSM4T(bl[nt], bd);
            }
            #pragma unroll
            for (int mt = 0; mt < 2; mt++) {
                #pragma unroll
                for (int n8 = 0; n8 < 4; n8++) {
                    uint32_t bh0 = bh[n8 >> 1][(n8 & 1)*2], bh1 = bh[n8 >> 1][(n8 & 1)*2 + 1];
                    uint32_t bl0 = bl[n8 >> 1][(n8 & 1)*2], bl1 = bl[n8 >> 1][(n8 & 1)*2 + 1];
                    MMA16816(acc[mt][n8], ah[mt], bh0, bh1);
                    MMA16816(acc[mt][n8], ah[mt], bl0, bl1);
                    MMA16816(acc[mt][n8], al[mt], bh0, bh1);
                }
            }
        }
        if (c + 1 < NCHUNK) STS_B(s ^ 1);
    }

    // epilogue: bias -> BN -> act -> store f32 and/or packed
    int r  = lane >> 2;
    int cp = (lane & 3) * 2;
    #pragma unroll
    for (int mt = 0; mt < 2; mt++) {
        #pragma unroll
        for (int hf = 0; hf < 2; hf++) {
            int co = cob + wco + mt*16 + r + hf*8;
            float bsc = bns[e*Cc + co];
            float bsh = bnb[e*Cc + co];
            float bi  = bias ? bias[e*Cc + co] : 0.f;
            #pragma unroll
            for (int n8 = 0; n8 < 4; n8++) {
                int px = pxb + wpx + n8*8 + cp;
                float v0 = (acc[mt][n8][hf*2 + 0] + bi) * bsc + bsh;
                float v1 = (acc[mt][n8][hf*2 + 1] + bi) * bsc + bsh;
                if (mode == MODE_GELU)      { v0 = gelu_tanh(v0); v1 = gelu_tanh(v1); }
                else if (mode == MODE_RELU) { v0 = fmaxf(v0, 0.f); v1 = fmaxf(v1, 0.f); }
                if (f32out) {
                    float2 f2 = make_float2(v0, v1);
                    *(float2*)(f32out + (size_t)(pair*Cc + co)*HW + px) = f2;
                }
                if (pkout) {
                    int y = px >> 6, x = px & 63;
                    size_t o = (size_t)(pair*Cc + co)*PIMG + (y + 1)*PW + x + 1;
                    pkout[o]     = pack_hilo(v0);
                    pkout[o + 1] = pack_hilo(v1);
                }
            }
        }
    }
    #undef ISSUE_A
    #undef LOAD_B
    #undef STS_B
}

// ---------------- domain gate (per pair) -------------------------------------
__global__ void dgate_kernel(const float* __restrict__ gw, const float* __restrict__ gb) {
    int pair = blockIdx.x;
    int e = g_pairs[pair] & 3;
    int t = threadIdx.x;
    __shared__ float red[256];
    red[t] = g_stat1[pair*Cc + t] * gw[e*Cc + t];
    __syncthreads();
    for (int k = 128; k; k >>= 1) { if (t < k) red[t] += red[t+k]; __syncthreads(); }
    if (t == 0) g_g1[pair] = sigmoidf_(red[0] + gb[e]);
}

// ---------------- bufC = x + g1*bufB; emit packed padded ---------------------
__global__ void axpy_kernel(const float* __restrict__ x) {
    int pair = blockIdx.y;
    int b = g_pairs[pair] >> 2;
    int i = blockIdx.x * 256 + threadIdx.x;
    size_t po = (size_t)pair * Cc * HW + i;
    float v = x[(size_t)b * Cc * HW + i] + g_g1[pair] * g_bufB[po];
    g_bufC[po] = v;
    int c = i >> 12, p = i & 4095;
    g_pkC[((size_t)pair*Cc + c) * PIMG + ((p>>6) + 1) * PW + (p & 63) + 1] = pack_hilo(v);
}

// ---------------- channel attention MLP --------------------------------------
__global__ void camlp_kernel(const float* __restrict__ w1, const float* __restrict__ w2) {
    int pair = blockIdx.x;
    int e = g_pairs[pair] & 3;
    int t = threadIdx.x;
    __shared__ float hs[CRr];
    if (t < CRr) {
        float sa_ = 0.f, sm_ = 0.f;
        const float* w1r = w1 + ((size_t)e*CRr + t) * Cc;
        for (int c = 0; c < Cc; c++) {
            sa_ += g_stat1[pair*Cc + c] * w1r[c];
            sm_ += g_stat2[pair*Cc + c] * w1r[c];
        }
        hs[t] = fmaxf(sa_, 0.f) + fmaxf(sm_, 0.f);
    }
    __syncthreads();
    float o = 0.f;
    const float* w2r = w2 + ((size_t)e*Cc + t) * CRr;
    #pragma unroll
    for (int j = 0; j < CRr; j++) o += hs[j] * w2r[j];
    g_ca[pair*Cc + t] = sigmoidf_(o);
}

// ---------------- SA input stats ---------------------------------------------
__global__ void sastats_kernel() {
    int pair = blockIdx.y;
    __shared__ float sca[Cc];
    int t = threadIdx.x;
    sca[t] = g_ca[pair*Cc + t];
    __syncthreads();
    int p = blockIdx.x * 256 + t;
    float s = 0.f, m = -INFINITY;
    for (int c = 0; c < Cc; c++) {
        float v = g_bufB[((size_t)pair*Cc + c)*HW + p] * sca[c];
        s += v; m = fmaxf(m, v);
    }
    g_sain[((size_t)pair*2    )*HW + p] = s * (1.f / Cc);
    g_sain[((size_t)pair*2 + 1)*HW + p] = m;
}

// ---------------- SA 7x7 conv ------------------------------------------------
__global__ void saconv_kernel(const float* __restrict__ saw) {
    int pair = blockIdx.y;
    int e = g_pairs[pair] & 3;
    __shared__ float sw[2*49];
    int t = threadIdx.x;
    if (t < 98) sw[t] = saw[e*98 + t];
    __syncthreads();
    int p = blockIdx.x * 256 + t;
    int y = p >> 6, x = p & 63;
    float a = 0.f;
    #pragma unroll
    for (int ch = 0; ch < 2; ch++)
        for (int ky = 0; ky < 7; ky++) {
            int gy = y + ky - 3;
            if (gy < 0 || gy >= Hh) continue;
            for (int kx = 0; kx < 7; kx++) {
                int gx = x + kx - 3;
                if (gx < 0 || gx >= Ww) continue;
                a += g_sain[((size_t)pair*2 + ch)*HW + gy*Ww + gx] * sw[ch*49 + ky*7 + kx];
            }
        }
    g_sa[(size_t)pair*HW + p] = sigmoidf_(a);
}

// ---------------- final accumulate (2 commutative adds per elem) -------------
__global__ void final_kernel(const float* __restrict__ adapter, const int* __restrict__ dom,
                             float* __restrict__ out) {
    int pair = blockIdx.y;
    int pe = g_pairs[pair];
    int b = pe >> 2, e = pe & 3;
    float w = g_wpair[pair];
    int idx = blockIdx.x * 256 + threadIdx.x;
    int c = idx / HW, p = idx % HW;
    size_t po = (size_t)pair * Cc * HW + idx;
    float v = g_bufB[po] * g_ca[pair*Cc + c] * g_sa[(size_t)pair*HW + p] + g_bufC[po];
    v = fmaxf(v, 0.f) + adapter[((size_t)e*Dd + dom[b])*Cc + c];
    atomicAdd(out + (size_t)b * Cc * HW + idx, w * v);
}

// ---------------- launch -----------------------------------------------------
extern "C" void kernel_launch(void* const* d_in, const int* in_sizes, int n_in,
                              void* d_out, int out_size) {
    const float* x        = (const float*)d_in[0];
    const int*   dom      = (const int*)  d_in[1];
    const float* g_w1     = (const float*)d_in[2];
    const float* g_b1     = (const float*)d_in[3];
    const float* ln_s     = (const float*)d_in[4];
    const float* ln_b     = (const float*)d_in[5];
    const float* g_w2     = (const float*)d_in[6];
    const float* g_b2     = (const float*)d_in[7];
    const float* dom_emb  = (const float*)d_in[8];
    const float* dt_w1    = (const float*)d_in[9];
    const float* dt_bn1s  = (const float*)d_in[10];
    const float* dt_bn1b  = (const float*)d_in[11];
    const float* dt_w2    = (const float*)d_in[12];
    const float* dt_bn2s  = (const float*)d_in[13];
    const float* dt_bn2b  = (const float*)d_in[14];
    const float* gate_w   = (const float*)d_in[15];
    const float* gate_b   = (const float*)d_in[16];
    const float* c1_w     = (const float*)d_in[17];
    const float* c1_b     = (const float*)d_in[18];
    const float* bn1s     = (const float*)d_in[19];
    const float* bn1b     = (const float*)d_in[20];
    const float* c2_w     = (const float*)d_in[21];
    const float* c2_b     = (const float*)d_in[22];
    const float* bn2s     = (const float*)d_in[23];
    const float* bn2b     = (const float*)d_in[24];
    const float* ca_w1    = (const float*)d_in[25];
    const float* ca_w2    = (const float*)d_in[26];
    const float* sa_w     = (const float*)d_in[27];
    const float* adapter  = (const float*)d_in[28];
    float* out = (float*)d_out;

    float *bufB, *pxavg, *pxmax, *pstat1, *pstat2;
    uint32_t *xpk, *pkA, *pkC;
    uint16_t *wh, *wl;
    cudaGetSymbolAddress((void**)&bufB,  g_bufB);
    cudaGetSymbolAddress((void**)&pxavg, g_xavg);
    cudaGetSymbolAddress((void**)&pxmax, g_xmax);
    cudaGetSymbolAddress((void**)&pstat1, g_stat1);
    cudaGetSymbolAddress((void**)&pstat2, g_stat2);
    cudaGetSymbolAddress((void**)&xpk, g_xpk);
    cudaGetSymbolAddress((void**)&pkA, g_pkA);
    cudaGetSymbolAddress((void**)&pkC, g_pkC);
    cudaGetSymbolAddress((void**)&wh, g_wh);
    cudaGetSymbolAddress((void**)&wl, g_wl);

    static int smem_set = 0;
    if (!smem_set) {
        cudaFuncSetAttribute(conv_mma_kernel,
                             cudaFuncAttributeMaxDynamicSharedMemorySize, SMEM_TOTAL);
        smem_set = 1;
    }

    int ntot = Bz * Cc * HW;
    zero_kernel<<<(ntot + 255) / 256, 256>>>(out, ntot);

    // gate first (top-2 pair compaction enables all downstream batching)
    stats_kernel<<<Bz*Cc, 256>>>(x, pxavg, pxmax);
    gate_kernel<<<1, 256>>>(dom, g_w1, g_b1, ln_s, ln_b, g_w2, g_b2, dom_emb);

    // weight + input packing (split hi/lo planes for weights)
    int nw = Ee * Cc * KTOT;
    packw_kernel<<<(nw + 255) / 256, 256>>>(dt_w1, wh + 0 * (size_t)nw, wl + 0 * (size_t)nw);
    packw_kernel<<<(nw + 255) / 256, 256>>>(dt_w2, wh + 1 * (size_t)nw, wl + 1 * (size_t)nw);
    packw_kernel<<<(nw + 255) / 256, 256>>>(c1_w,  wh + 2 * (size_t)nw, wl + 2 * (size_t)nw);
    packw_kernel<<<(nw + 255) / 256, 256>>>(c2_w,  wh + 3 * (size_t)nw, wl + 3 * (size_t)nw);
    packx_kernel<<<ntot / 256, 256>>>(x, xpk);

    dim3 cgrid(32, 2, NPAIR);
    dim3 egrid(Cc*HW/256, NPAIR);
    dim3 sgrid(HW/256, NPAIR);

    // stage-batched over all 16 active (b,e) pairs
    conv_mma_kernel<<<cgrid, 512, SMEM_TOTAL>>>(xpk, 0, wh, wl, 0, nullptr, dt_bn1s, dt_bn1b,
                                                nullptr, pkA, MODE_GELU);
    conv_mma_kernel<<<cgrid, 512, SMEM_TOTAL>>>(pkA, 1, wh, wl, 1, nullptr, dt_bn2s, dt_bn2b,
                                                bufB, nullptr, MODE_NONE);
    stats_kernel<<<NPAIR*Cc, 256>>>(bufB, pstat1, nullptr);
    dgate_kernel<<<NPAIR, 256>>>(gate_w, gate_b);
    axpy_kernel<<<egrid, 256>>>(x);
    conv_mma_kernel<<<cgrid, 512, SMEM_TOTAL>>>(pkC, 1, wh, wl, 2, c1_b, bn1s, bn1b,
                                                nullptr, pkA, MODE_RELU);
    conv_mma_kernel<<<cgrid, 512, SMEM_TOTAL>>>(pkA, 1, wh, wl, 3, c2_b, bn2s, bn2b,
                                                bufB, nullptr, MODE_NONE);
    stats_kernel<<<NPAIR*Cc, 256>>>(bufB, pstat1, pstat2);
    camlp_kernel<<<NPAIR, 256>>>(ca_w1, ca_w2);
    sastats_kernel<<<sgrid, 256>>>();
    saconv_kernel<<<sgrid, 256>>>(sa_w);
    final_kernel<<<egrid, 256>>>(adapter, dom, out);
}

// round 9
// speedup vs baseline: 3.3025x; 1.2258x over previous
#include <cuda_runtime.h>
#include <cuda_bf16.h>
#include <math.h>
#include <stdint.h>

// Problem constants
#define Bz   8
#define Cc   256
#define Hh   64
#define Ww   64
#define HW   (Hh*Ww)
#define Ee   4
#define Dd   4
#define CRr  16
#define GIN  (2*Cc+16)   // 528
#define NPAIR 16         // exactly 2 experts per batch item

// Winograd constants
#define PW     66            // padded width/height
#define PIMG   (PW*PW)
#define NT     1024          // 32x32 output tiles of 2x2
#define WSLAB  (Cc*NT)       // 262144 elems per (slot,pos) slab
#define USLAB  (Cc*Cc)       // 65536 per (e,pos) U slab
#define WKT    256           // GEMM K
#define WKCH   64            // K per chunk
#define WNCH   (WKT/WKCH)    // 4

// smem strides (u16 units)
#define SA_STR 72            // 64 k + 8 pad -> 144B rows
#define SB_STR 136           // 128 n + 8 pad -> 272B rows
#define A_PL   (128*SA_STR*2)        // 18432 B
#define B_PL   (64*SB_STR*2)         // 17408 B
#define STG_BYTES (2*A_PL + 2*B_PL)  // 71680
#define SMEM_TOTAL (2*STG_BYTES)     // 143360

// ---------------- scratch (static device globals; zero-initialized) ---------
__device__ float    g_bufB[NPAIR*Cc*HW];
__device__ float    g_bufC[NPAIR*Cc*HW];
__device__ uint32_t g_xpk [Bz*Cc*PIMG];
__device__ uint32_t g_pkA [NPAIR*Cc*PIMG];
__device__ uint32_t g_pkC [NPAIR*Cc*PIMG];
__device__ __align__(16) uint16_t g_Uh[Ee*16*USLAB];      // 8MB
__device__ __align__(16) uint16_t g_Ul[Ee*16*USLAB];
__device__ __align__(16) uint16_t g_Vh[NPAIR*16*WSLAB];   // 134MB
__device__ __align__(16) uint16_t g_Vl[NPAIR*16*WSLAB];
__device__ float    g_M [NPAIR*16*WSLAB];                 // 268MB
__device__ float g_xavg[Bz*Cc];
__device__ float g_xmax[Bz*Cc];
__device__ float g_stat1[NPAIR*Cc];
__device__ float g_stat2[NPAIR*Cc];
__device__ int   g_pairs[NPAIR];             // b*4+e, stored b-major
__device__ float g_wpair[NPAIR];
__device__ float g_g1[NPAIR];
__device__ float g_ca[NPAIR*Cc];
__device__ float g_sain[NPAIR*2*HW];
__device__ float g_sa[NPAIR*HW];

// ---------------- helpers ----------------------------------------------------
__device__ __forceinline__ float sigmoidf_(float x) { return 1.f / (1.f + __expf(-x)); }
__device__ __forceinline__ float gelu_tanh(float v) {
    float x3 = v * v * v;
    return 0.5f * v * (1.f + tanhf(0.7978845608028654f * (v + 0.044715f * x3)));
}
__device__ __forceinline__ uint32_t pack_hilo(float v) {
    __nv_bfloat16 h = __float2bfloat16(v);
    float r = v - __bfloat162float(h);
    __nv_bfloat16 l = __float2bfloat16(r);
    return (uint32_t)__bfloat16_as_ushort(h) | ((uint32_t)__bfloat16_as_ushort(l) << 16);
}
__device__ __forceinline__ float unpack_hilo(uint32_t u) {
    return __bfloat162float(__ushort_as_bfloat16((uint16_t)u)) +
           __bfloat162float(__ushort_as_bfloat16((uint16_t)(u >> 16)));
}
__device__ __forceinline__ void split_hilo(float v, uint16_t& h, uint16_t& l) {
    __nv_bfloat16 hb = __float2bfloat16(v);
    float r = v - __bfloat162float(hb);
    h = __bfloat16_as_ushort(hb);
    l = __bfloat16_as_ushort(__float2bfloat16(r));
}
__device__ __forceinline__ uint32_t sptr(const void* p) {
    return (uint32_t)__cvta_generic_to_shared(p);
}

#define CP_ASYNC16(dst, src) \
    asm volatile("cp.async.cg.shared.global [%0], [%1], 16;" :: "r"(dst), "l"(src))
#define CP_COMMIT() asm volatile("cp.async.commit_group;" ::: "memory")
#define CP_WAIT0()  asm volatile("cp.async.wait_group 0;" ::: "memory")

#define LDSM4(r, addr) \
    asm volatile("ldmatrix.sync.aligned.m8n8.x4.shared.b16 {%0,%1,%2,%3}, [%4];" \
        : "=r"((r)[0]), "=r"((r)[1]), "=r"((r)[2]), "=r"((r)[3]) : "r"(addr))
#define LDSM4T(r, addr) \
    asm volatile("ldmatrix.sync.aligned.m8n8.x4.trans.shared.b16 {%0,%1,%2,%3}, [%4];" \
        : "=r"((r)[0]), "=r"((r)[1]), "=r"((r)[2]), "=r"((r)[3]) : "r"(addr))
#define MMA16816(d, a, b0_, b1_) \
    asm volatile("mma.sync.aligned.m16n8k16.row.col.f32.bf16.bf16.f32 " \
        "{%0,%1,%2,%3}, {%4,%5,%6,%7}, {%8,%9}, {%0,%1,%2,%3};" \
        : "+f"((d)[0]), "+f"((d)[1]), "+f"((d)[2]), "+f"((d)[3]) \
        : "r"((a)[0]), "r"((a)[1]), "r"((a)[2]), "r"((a)[3]), "r"(b0_), "r"(b1_))

// ---------------- x pack: fp32 -> padded packed hi/lo ------------------------
__global__ void packx_kernel(const float* __restrict__ x, uint32_t* __restrict__ out) {
    int idx = blockIdx.x * 256 + threadIdx.x;
    int p = idx & 4095, c = idx >> 12;
    int y = p >> 6, xx = p & 63;
    out[(size_t)c * PIMG + (y + 1) * PW + xx + 1] = pack_hilo(x[idx]);
}

// ---------------- Winograd weight transform: U = G g G^T ---------------------
__global__ void wtrans_kernel(const float* __restrict__ w,
                              uint16_t* __restrict__ Uh, uint16_t* __restrict__ Ul) {
    int idx = blockIdx.x * 256 + threadIdx.x;       // (e*256+co)*256+ci
    int ci = idx & 255, co = (idx >> 8) & 255, e = idx >> 16;
    const float* g = w + (size_t)idx * 9;
    float q[3][3];
    #pragma unroll
    for (int i = 0; i < 3; i++)
        #pragma unroll
        for (int j = 0; j < 3; j++) q[i][j] = g[i*3 + j];
    float t[4][3];
    #pragma unroll
    for (int c = 0; c < 3; c++) {
        t[0][c] = q[0][c];
        t[1][c] = 0.5f * (q[0][c] + q[1][c] + q[2][c]);
        t[2][c] = 0.5f * (q[0][c] - q[1][c] + q[2][c]);
        t[3][c] = q[2][c];
    }
    #pragma unroll
    for (int r = 0; r < 4; r++) {
        float u0 = t[r][0], u1 = 0.5f*(t[r][0]+t[r][1]+t[r][2]),
              u2 = 0.5f*(t[r][0]-t[r][1]+t[r][2]), u3 = t[r][2];
        float uu[4] = {u0, u1, u2, u3};
        #pragma unroll
        for (int c = 0; c < 4; c++) {
            uint16_t hh, ll; split_hilo(uu[c], hh, ll);
            size_t o = (size_t)(e*16 + r*4 + c) * USLAB + co*256 + ci;
            Uh[o] = hh; Ul[o] = ll;
        }
    }
}

// ---------------- Winograd input transform: V = B^T d B ----------------------
// grid: (1024, nslots); slot indexes the input image directly
__global__ void itrans_kernel(const uint32_t* __restrict__ pkin,
                              uint16_t* __restrict__ Vh, uint16_t* __restrict__ Vl) {
    int slot = blockIdx.y;
    int idx = blockIdx.x * 256 + threadIdx.x;   // ci*1024 + t
    int ci = idx >> 10, t = idx & 1023;
    int ty = t >> 5, tx = t & 31;
    const uint32_t* p = pkin + ((size_t)slot * Cc + ci) * PIMG + (2*ty) * PW + 2*tx;
    float d[4][4];
    #pragma unroll
    for (int r = 0; r < 4; r++)
        #pragma unroll
        for (int c = 0; c < 4; c++) d[r][c] = unpack_hilo(p[r*PW + c]);
    float tt[4][4];
    #pragma unroll
    for (int c = 0; c < 4; c++) {
        tt[0][c] = d[0][c] - d[2][c];
        tt[1][c] = d[1][c] + d[2][c];
        tt[2][c] = d[2][c] - d[1][c];
        tt[3][c] = d[1][c] - d[3][c];
    }
    size_t base = (size_t)slot * 16 * WSLAB + ci*1024 + t;
    #pragma unroll
    for (int r = 0; r < 4; r++) {
        float v0 = tt[r][0] - tt[r][2];
        float v1 = tt[r][1] + tt[r][2];
        float v2 = tt[r][2] - tt[r][1];
        float v3 = tt[r][1] - tt[r][3];
        float vv[4] = {v0, v1, v2, v3};
        #pragma unroll
        for (int c = 0; c < 4; c++) {
            uint16_t hh, ll; split_hilo(vv[c], hh, ll);
            size_t o = base + (size_t)(r*4 + c) * WSLAB;
            Vh[o] = hh; Vl[o] = ll;
        }
    }
}

// ---------------- Winograd GEMM: M[pos] = U[pos] * V[pos], bf16x3 ------------
// grid (8 tile-blocks, 2 co-blocks, NPAIR*16)
__global__ __launch_bounds__(512, 1) void wgemm_kernel(
    const uint16_t* __restrict__ Uh, const uint16_t* __restrict__ Ul,
    const uint16_t* __restrict__ Vh, const uint16_t* __restrict__ Vl,
    float* __restrict__ M, int vByBatch)
{
    int zb = blockIdx.z;
    int pair = zb >> 4, pos = zb & 15;
    int pe = g_pairs[pair];
    int e = pe & 3;
    int vslot = vByBatch ? (pe >> 2) : pair;
    int cob = blockIdx.y * 128;
    int tb  = blockIdx.x * 128;

    const uint16_t* Ahp = Uh + (size_t)(e*16 + pos) * USLAB + (size_t)cob * 256;
    const uint16_t* Alp = Ul + (size_t)(e*16 + pos) * USLAB + (size_t)cob * 256;
    const uint16_t* Bhp = Vh + (size_t)(vslot*16 + pos) * WSLAB + tb;
    const uint16_t* Blp = Vl + (size_t)(vslot*16 + pos) * WSLAB + tb;

    extern __shared__ __align__(16) char smem[];
    int tid  = threadIdx.x;
    int lane = tid & 31, wid = tid >> 5;
    int wco  = (wid & 3) * 32;
    int wpx  = (wid >> 2) * 32;
    int coG = tid >> 3, jG = tid & 7;   // A & B fill roles

    float acc[2][4][4];
    #pragma unroll
    for (int mt = 0; mt < 2; mt++)
        #pragma unroll
        for (int nt = 0; nt < 4; nt++)
            #pragma unroll
            for (int q = 0; q < 4; q++) acc[mt][nt][q] = 0.f;

    #define W_ISSUE(c, s) do { \
        char* _ab = smem + (s)*STG_BYTES; \
        size_t _ka = (size_t)(c) * WKCH + jG*8; \
        CP_ASYNC16(sptr(_ab + coG*144 + jG*16),             Ahp + (size_t)coG*256 + _ka); \
        CP_ASYNC16(sptr(_ab + (coG+64)*144 + jG*16),        Ahp + (size_t)(coG+64)*256 + _ka); \
        CP_ASYNC16(sptr(_ab + A_PL + coG*144 + jG*16),      Alp + (size_t)coG*256 + _ka); \
        CP_ASYNC16(sptr(_ab + A_PL + (coG+64)*144 + jG*16), Alp + (size_t)(coG+64)*256 + _ka); \
        char* _bb = _ab + 2*A_PL; \
        size_t _kb = (size_t)((c)*WKCH + coG) * 1024; \
        CP_ASYNC16(sptr(_bb + coG*272 + jG*16),         Bhp + _kb + jG*8); \
        CP_ASYNC16(sptr(_bb + coG*272 + jG*16 + 128),   Bhp + _kb + jG*8 + 64); \
        CP_ASYNC16(sptr(_bb + B_PL + coG*272 + jG*16),       Blp + _kb + jG*8); \
        CP_ASYNC16(sptr(_bb + B_PL + coG*272 + jG*16 + 128), Blp + _kb + jG*8 + 64); \
    } while (0)

    W_ISSUE(0, 0); CP_COMMIT();

    for (int c = 0; c < WNCH; c++) {
        int s = c & 1;
        CP_WAIT0();
        __syncthreads();
        if (c + 1 < WNCH) { W_ISSUE(c + 1, s ^ 1); CP_COMMIT(); }
        uint16_t* sAh = (uint16_t*)(smem + s*STG_BYTES);
        uint16_t* sAl = (uint16_t*)(smem + s*STG_BYTES + A_PL);
        uint16_t* sBh = (uint16_t*)(smem + s*STG_BYTES + 2*A_PL);
        uint16_t* sBl = (uint16_t*)(smem + s*STG_BYTES + 2*A_PL + B_PL);
        #pragma unroll
        for (int ks = 0; ks < 4; ks++) {
            int kO = ks * 16;
            uint32_t ah[2][4], al[2][4], bh[2][4], bl[2][4];
            #pragma unroll
            for (int mt = 0; mt < 2; mt++) {
                uint32_t ad = sptr(sAh + (wco + mt*16 + (lane & 15))*SA_STR + kO + (lane >> 4)*8);
                LDSM4(ah[mt], ad);
                ad = sptr(sAl + (wco + mt*16 + (lane & 15))*SA_STR + kO + (lane >> 4)*8);
                LDSM4(al[mt], ad);
            }
            #pragma unroll
            for (int nt = 0; nt < 2; nt++) {
                uint32_t bd = sptr(sBh + (kO + (lane & 15))*SB_STR + wpx + nt*16 + (lane >> 4)*8);
                LDSM4T(bh[nt], bd);
                bd = sptr(sBl + (kO + (lane & 15))*SB_STR + wpx + nt*16 + (lane >> 4)*8);
                LDSM4T(bl[nt], bd);
            }
            #pragma unroll
            for (int mt = 0; mt < 2; mt++) {
                #pragma unroll
                for (int n8 = 0; n8 < 4; n8++) {
                    uint32_t bh0 = bh[n8 >> 1][(n8 & 1)*2], bh1 = bh[n8 >> 1][(n8 & 1)*2 + 1];
                    uint32_t bl0 = bl[n8 >> 1][(n8 & 1)*2], bl1 = bl[n8 >> 1][(n8 & 1)*2 + 1];
                    MMA16816(acc[mt][n8], ah[mt], bh0, bh1);
                    MMA16816(acc[mt][n8], ah[mt], bl0, bl1);
                    MMA16816(acc[mt][n8], al[mt], bh0, bh1);
                }
            }
        }
    }
    #undef W_ISSUE

    // store raw M
    float* Mb = M + (size_t)zb * WSLAB;
    int r  = lane >> 2;
    int cp = (lane & 3) * 2;
    #pragma unroll
    for (int mt = 0; mt < 2; mt++) {
        #pragma unroll
        for (int hf = 0; hf < 2; hf++) {
            int co = cob + wco + mt*16 + r + hf*8;
            #pragma unroll
            for (int n8 = 0; n8 < 4; n8++) {
                int tile = tb + wpx + n8*8 + cp;
                float2 f2 = make_float2(acc[mt][n8][hf*2 + 0], acc[mt][n8][hf*2 + 1]);
                *(float2*)(Mb + (size_t)co*1024 + tile) = f2;
            }
        }
    }
}

// ---------------- Winograd output transform + epilogue -----------------------
#define MODE_GELU 0
#define MODE_NONE 1
#define MODE_RELU 2

__global__ void otrans_kernel(const float* __restrict__ M,
                              const float* __restrict__ bias,
                              const float* __restrict__ bns, const float* __restrict__ bnb,
                              float* __restrict__ f32out, uint32_t* __restrict__ pkout, int mode)
{
    int pair = blockIdx.y;
    int e = g_pairs[pair] & 3;
    int idx = blockIdx.x * 256 + threadIdx.x;   // co*1024 + t
    int co = idx >> 10, t = idx & 1023;
    int ty = t >> 5, tx = t & 31;
    const float* Mb = M + (size_t)pair * 16 * WSLAB + (size_t)co * 1024 + t;
    float m[4][4];
    #pragma unroll
    for (int pos = 0; pos < 16; pos++)
        m[pos >> 2][pos & 3] = Mb[(size_t)pos * WSLAB];
    float ta[2][4];
    #pragma unroll
    for (int c = 0; c < 4; c++) {
        ta[0][c] = m[0][c] + m[1][c] + m[2][c];
        ta[1][c] = m[1][c] - m[2][c] - m[3][c];
    }
    float Y[2][2];
    #pragma unroll
    for (int i = 0; i < 2; i++) {
        Y[i][0] = ta[i][0] + ta[i][1] + ta[i][2];
        Y[i][1] = ta[i][1] - ta[i][2] - ta[i][3];
    }
    float bsc = bns[e*Cc + co], bsh = bnb[e*Cc + co];
    float bi  = bias ? bias[e*Cc + co] : 0.f;
    #pragma unroll
    for (int dy = 0; dy < 2; dy++)
        #pragma unroll
        for (int dx = 0; dx < 2; dx++) {
            float v = (Y[dy][dx] + bi) * bsc + bsh;
            if (mode == MODE_GELU)      v = gelu_tanh(v);
            else if (mode == MODE_RELU) v = fmaxf(v, 0.f);
            int py = 2*ty + dy, px = 2*tx + dx;
            if (f32out)
                f32out[((size_t)pair*Cc + co)*HW + py*Ww + px] = v;
            if (pkout)
                pkout[((size_t)pair*Cc + co)*PIMG + (py + 1)*PW + px + 1] = pack_hilo(v);
        }
}

// ---------------- spatial avg/max stats per (slot,c) -------------------------
__global__ void stats_kernel(const float* __restrict__ in,
                             float* __restrict__ avg, float* __restrict__ mx) {
    int bc = blockIdx.x;
    const float* p = in + (size_t)bc * HW;
    float s = 0.f, m = -INFINITY;
    for (int i = threadIdx.x; i < HW; i += 256) {
        float v = p[i];
        s += v; m = fmaxf(m, v);
    }
    __shared__ float ss[256], sm[256];
    int t = threadIdx.x;
    ss[t] = s; sm[t] = m; __syncthreads();
    for (int k = 128; k; k >>= 1) {
        if (t < k) { ss[t] += ss[t+k]; sm[t] = fmaxf(sm[t], sm[t+k]); }
        __syncthreads();
    }
    if (t == 0) {
        avg[bc] = ss[0] * (1.f / HW);
        if (mx) mx[bc] = sm[0];
    }
}

// ---------------- gate network + pair compaction -----------------------------
__global__ void gate_kernel(const int* __restrict__ dom,
                            const float* __restrict__ w1, const float* __restrict__ b1,
                            const float* __restrict__ lns, const float* __restrict__ lnb,
                            const float* __restrict__ w2, const float* __restrict__ b2,
                            const float* __restrict__ dom_emb) {
    __shared__ float gi[GIN];
    __shared__ float red[256];
    __shared__ float logit[Ee];
    int t = threadIdx.x;
    for (int b = 0; b < Bz; b++) {
        for (int k = t; k < GIN; k += 256) {
            float v;
            if (k < Cc)        v = g_xavg[b*Cc + k];
            else if (k < 2*Cc) v = g_xmax[b*Cc + k - Cc];
            else               v = dom_emb[dom[b]*16 + (k - 2*Cc)];
            gi[k] = v;
        }
        __syncthreads();
        float acc = b1[t];
        for (int k = 0; k < GIN; k++) acc += gi[k] * w1[k*Cc + t];
        red[t] = acc; __syncthreads();
        for (int k = 128; k; k >>= 1) { if (t < k) red[t] += red[t+k]; __syncthreads(); }
        float mu = red[0] * (1.f / Cc);
        __syncthreads();
        red[t] = acc * acc; __syncthreads();
        for (int k = 128; k; k >>= 1) { if (t < k) red[t] += red[t+k]; __syncthreads(); }
        float var = red[0] * (1.f / Cc) - mu * mu;
        __syncthreads();
        float h = (acc - mu) * rsqrtf(var + 1e-5f) * lns[t] + lnb[t];
        h = fmaxf(h, 0.f);
        for (int e = 0; e < Ee; e++) {
            red[t] = h * w2[t*Ee + e]; __syncthreads();
            for (int k = 128; k; k >>= 1) { if (t < k) red[t] += red[t+k]; __syncthreads(); }
            if (t == 0) logit[e] = red[0] + b2[e];
            __syncthreads();
        }
        if (t == 0) {
            float mx = logit[0];
            for (int e = 1; e < Ee; e++) mx = fmaxf(mx, logit[e]);
            float pr[Ee], s = 0.f;
            for (int e = 0; e < Ee; e++) { pr[e] = __expf(logit[e] - mx); s += pr[e]; }
            for (int e = 0; e < Ee; e++) pr[e] /= s;
            int i1 = 0;
            for (int e = 1; e < Ee; e++) if (pr[e] > pr[i1]) i1 = e;
            int i2 = -1;
            for (int e = 0; e < Ee; e++) if (e != i1 && (i2 < 0 || pr[e] > pr[i2])) i2 = e;
            float s2 = pr[i1] + pr[i2];
            int lo = i1 < i2 ? i1 : i2;
            int hi = i1 < i2 ? i2 : i1;
            g_pairs[b*2 + 0] = b*4 + lo;  g_wpair[b*2 + 0] = pr[lo] / s2;
            g_pairs[b*2 + 1] = b*4 + hi;  g_wpair[b*2 + 1] = pr[hi] / s2;
        }
        __syncthreads();
    }
}

// ---------------- domain gate (per pair) -------------------------------------
__global__ void dgate_kernel(const float* __restrict__ gw, const float* __restrict__ gb) {
    int pair = blockIdx.x;
    int e = g_pairs[pair] & 3;
    int t = threadIdx.x;
    __shared__ float red[256];
    red[t] = g_stat1[pair*Cc + t] * gw[e*Cc + t];
    __syncthreads();
    for (int k = 128; k; k >>= 1) { if (t < k) red[t] += red[t+k]; __syncthreads(); }
    if (t == 0) g_g1[pair] = sigmoidf_(red[0] + gb[e]);
}

// ---------------- bufC = x + g1*bufB; emit packed padded ---------------------
__global__ void axpy_kernel(const float* __restrict__ x) {
    int pair = blockIdx.y;
    int b = g_pairs[pair] >> 2;
    int i = blockIdx.x * 256 + threadIdx.x;
    size_t po = (size_t)pair * Cc * HW + i;
    float v = x[(size_t)b * Cc * HW + i] + g_g1[pair] * g_bufB[po];
    g_bufC[po] = v;
    int c = i >> 12, p = i & 4095;
    g_pkC[((size_t)pair*Cc + c) * PIMG + ((p>>6) + 1) * PW + (p & 63) + 1] = pack_hilo(v);
}

// ---------------- channel attention MLP --------------------------------------
__global__ void camlp_kernel(const float* __restrict__ w1, const float* __restrict__ w2) {
    int pair = blockIdx.x;
    int e = g_pairs[pair] & 3;
    int t = threadIdx.x;
    __shared__ float hs[CRr];
    if (t < CRr) {
        float sa_ = 0.f, sm_ = 0.f;
        const float* w1r = w1 + ((size_t)e*CRr + t) * Cc;
        for (int c = 0; c < Cc; c++) {
            sa_ += g_stat1[pair*Cc + c] * w1r[c];
            sm_ += g_stat2[pair*Cc + c] * w1r[c];
        }
        hs[t] = fmaxf(sa_, 0.f) + fmaxf(sm_, 0.f);
    }
    __syncthreads();
    float o = 0.f;
    const float* w2r = w2 + ((size_t)e*Cc + t) * CRr;
    #pragma unroll
    for (int j = 0; j < CRr; j++) o += hs[j] * w2r[j];
    g_ca[pair*Cc + t] = sigmoidf_(o);
}

// ---------------- SA input stats ---------------------------------------------
__global__ void sastats_kernel() {
    int pair = blockIdx.y;
    __shared__ float sca[Cc];
    int t = threadIdx.x;
    sca[t] = g_ca[pair*Cc + t];
    __syncthreads();
    int p = blockIdx.x * 256 + t;
    float s = 0.f, m = -INFINITY;
    for (int c = 0; c < Cc; c++) {
        float v = g_bufB[((size_t)pair*Cc + c)*HW + p] * sca[c];
        s += v; m = fmaxf(m, v);
    }
    g_sain[((size_t)pair*2    )*HW + p] = s * (1.f / Cc);
    g_sain[((size_t)pair*2 + 1)*HW + p] = m;
}

// ---------------- SA 7x7 conv ------------------------------------------------
__global__ void saconv_kernel(const float* __restrict__ saw) {
    int pair = blockIdx.y;
    int e = g_pairs[pair] & 3;
    __shared__ float sw[2*49];
    int t = threadIdx.x;
    if (t < 98) sw[t] = saw[e*98 + t];
    __syncthreads();
    int p = blockIdx.x * 256 + t;
    int y = p >> 6, x = p & 63;
    float a = 0.f;
    #pragma unroll
    for (int ch = 0; ch < 2; ch++)
        for (int ky = 0; ky < 7; ky++) {
            int gy = y + ky - 3;
            if (gy < 0 || gy >= Hh) continue;
            for (int kx = 0; kx < 7; kx++) {
                int gx = x + kx - 3;
                if (gx < 0 || gx >= Ww) continue;
                a += g_sain[((size_t)pair*2 + ch)*HW + gy*Ww + gx] * sw[ch*49 + ky*7 + kx];
            }
        }
    g_sa[(size_t)pair*HW + p] = sigmoidf_(a);
}

// ---------------- final: both pairs of a batch, direct write -----------------
__global__ void final_kernel(const float* __restrict__ adapter, const int* __restrict__ dom,
                             float* __restrict__ out) {
    int b = blockIdx.y;
    int idx = blockIdx.x * 256 + threadIdx.x;
    int c = idx >> 12, p = idx & 4095;
    float r = 0.f;
    #pragma unroll
    for (int j = 0; j < 2; j++) {
        int pair = b*2 + j;
        int e = g_pairs[pair] & 3;
        float w = g_wpair[pair];
        size_t po = (size_t)pair * Cc * HW + idx;
        float v = g_bufB[po] * g_ca[pair*Cc + c] * g_sa[(size_t)pair*HW + p] + g_bufC[po];
        v = fmaxf(v, 0.f) + adapter[((size_t)e*Dd + dom[b])*Cc + c];
        r += w * v;
    }
    out[(size_t)b * Cc * HW + idx] = r;
}

// ---------------- launch -----------------------------------------------------
extern "C" void kernel_launch(void* const* d_in, const int* in_sizes, int n_in,
                              void* d_out, int out_size) {
    const float* x        = (const float*)d_in[0];
    const int*   dom      = (const int*)  d_in[1];
    const float* g_w1     = (const float*)d_in[2];
    const float* g_b1     = (const float*)d_in[3];
    const float* ln_s     = (const float*)d_in[4];
    const float* ln_b     = (const float*)d_in[5];
    const float* g_w2     = (const float*)d_in[6];
    const float* g_b2     = (const float*)d_in[7];
    const float* dom_emb  = (const float*)d_in[8];
    const float* dt_w1    = (const float*)d_in[9];
    const float* dt_bn1s  = (const float*)d_in[10];
    const float* dt_bn1b  = (const float*)d_in[11];
    const float* dt_w2    = (const float*)d_in[12];
    const float* dt_bn2s  = (const float*)d_in[13];
    const float* dt_bn2b  = (const float*)d_in[14];
    const float* gate_w   = (const float*)d_in[15];
    const float* gate_b   = (const float*)d_in[16];
    const float* c1_w     = (const float*)d_in[17];
    const float* c1_b     = (const float*)d_in[18];
    const float* bn1s     = (const float*)d_in[19];
    const float* bn1b     = (const float*)d_in[20];
    const float* c2_w     = (const float*)d_in[21];
    const float* c2_b     = (const float*)d_in[22];
    const float* bn2s     = (const float*)d_in[23];
    const float* bn2b     = (const float*)d_in[24];
    const float* ca_w1    = (const float*)d_in[25];
    const float* ca_w2    = (const float*)d_in[26];
    const float* sa_w     = (const float*)d_in[27];
    const float* adapter  = (const float*)d_in[28];
    float* out = (float*)d_out;

    float *bufB, *pxavg, *pxmax, *pstat1, *pstat2, *Mbuf;
    uint32_t *xpk, *pkA, *pkC;
    uint16_t *Uh, *Ul, *Vh, *Vl;
    cudaGetSymbolAddress((void**)&bufB,  g_bufB);
    cudaGetSymbolAddress((void**)&pxavg, g_xavg);
    cudaGetSymbolAddress((void**)&pxmax, g_xmax);
    cudaGetSymbolAddress((void**)&pstat1, g_stat1);
    cudaGetSymbolAddress((void**)&pstat2, g_stat2);
    cudaGetSymbolAddress((void**)&xpk, g_xpk);
    cudaGetSymbolAddress((void**)&pkA, g_pkA);
    cudaGetSymbolAddress((void**)&pkC, g_pkC);
    cudaGetSymbolAddress((void**)&Uh, g_Uh);
    cudaGetSymbolAddress((void**)&Ul, g_Ul);
    cudaGetSymbolAddress((void**)&Vh, g_Vh);
    cudaGetSymbolAddress((void**)&Vl, g_Vl);
    cudaGetSymbolAddress((void**)&Mbuf, g_M);

    static int smem_set = 0;
    if (!smem_set) {
        cudaFuncSetAttribute(wgemm_kernel,
                             cudaFuncAttributeMaxDynamicSharedMemorySize, SMEM_TOTAL);
        smem_set = 1;
    }

    int ntot = Bz * Cc * HW;
    dim3 ggrid(8, 2, NPAIR*16);
    dim3 egrid(Cc*HW/256, NPAIR);
    dim3 sgrid(HW/256, NPAIR);
    dim3 fgrid(Cc*HW/256, Bz);
    int nwt = Ee*Cc*Cc/256;                 // wtrans blocks
    dim3 itgB(1024, Bz), itgP(1024, NPAIR), otg(1024, NPAIR);

    // launch order puts wgemm at launch #6 (ncu -s 5 -c 1 profiles it)
    packx_kernel <<<ntot/256, 256>>>(x, xpk);                         // 1
    wtrans_kernel<<<nwt, 256>>>(dt_w1, Uh, Ul);                       // 2
    itrans_kernel<<<itgB, 256>>>(xpk, Vh, Vl);                        // 3 (by batch)
    stats_kernel <<<Bz*Cc, 256>>>(x, pxavg, pxmax);                   // 4
    gate_kernel  <<<1, 256>>>(dom, g_w1, g_b1, ln_s, ln_b, g_w2, g_b2, dom_emb); // 5
    wgemm_kernel <<<ggrid, 512, SMEM_TOTAL>>>(Uh, Ul, Vh, Vl, Mbuf, 1);          // 6
    otrans_kernel<<<otg, 256>>>(Mbuf, nullptr, dt_bn1s, dt_bn1b, nullptr, pkA, MODE_GELU);

    wtrans_kernel<<<nwt, 256>>>(dt_w2, Uh, Ul);
    itrans_kernel<<<itgP, 256>>>(pkA, Vh, Vl);
    wgemm_kernel <<<ggrid, 512, SMEM_TOTAL>>>(Uh, Ul, Vh, Vl, Mbuf, 0);
    otrans_kernel<<<otg, 256>>>(Mbuf, nullptr, dt_bn2s, dt_bn2b, bufB, nullptr, MODE_NONE);

    stats_kernel<<<NPAIR*Cc, 256>>>(bufB, pstat1, nullptr);
    dgate_kernel<<<NPAIR, 256>>>(gate_w, gate_b);
    axpy_kernel <<<egrid, 256>>>(x);

    wtrans_kernel<<<nwt, 256>>>(c1_w, Uh, Ul);
    itrans_kernel<<<itgP, 256>>>(pkC, Vh, Vl);
    wgemm_kernel <<<ggrid, 512, SMEM_TOTAL>>>(Uh, Ul, Vh, Vl, Mbuf, 0);
    otrans_kernel<<<otg, 256>>>(Mbuf, c1_b, bn1s, bn1b, nullptr, pkA, MODE_RELU);

    wtrans_kernel<<<nwt, 256>>>(c2_w, Uh, Ul);
    itrans_kernel<<<itgP, 256>>>(pkA, Vh, Vl);
    wgemm_kernel <<<ggrid, 512, SMEM_TOTAL>>>(Uh, Ul, Vh, Vl, Mbuf, 0);
    otrans_kernel<<<otg, 256>>>(Mbuf, c2_b, bn2s, bn2b, bufB, nullptr, MODE_NONE);

    stats_kernel<<<NPAIR*Cc, 256>>>(bufB, pstat1, pstat2);
    camlp_kernel<<<NPAIR, 256>>>(ca_w1, ca_w2);
    sastats_kernel<<<sgrid, 256>>>();
    saconv_kernel<<<sgrid, 256>>>(sa_w);
    final_kernel<<<fgrid, 256>>>(adapter, dom, out);
}

// round 10
// speedup vs baseline: 6.7168x; 2.0338x over previous
#include <cuda_runtime.h>
#include <cuda_bf16.h>
#include <math.h>
#include <stdint.h>

// Problem constants
#define Bz   8
#define Cc   256
#define Hh   64
#define Ww   64
#define HW   (Hh*Ww)
#define Ee   4
#define Dd   4
#define CRr  16
#define GIN  (2*Cc+16)   // 528
#define NPAIR 16

// Winograd F(4x4,3x3) constants
#define PW     66            // padded width/height (1 px border)
#define PIMG   (PW*PW)
#define NTIL   256           // 16x16 tiles of 4x4 per image
#define NPOS   36
#define VSLAB  (Cc*NTIL)     // 65536 elems per (slot,pos)
#define USLAB  (Cc*Cc)       // 65536 per (e,pos)
#define WKT    256
#define WKCH   64
#define WNCH   (WKT/WKCH)    // 4

// smem strides (u16 units)
#define SA_STR 72            // 64 k + 8 pad -> 144B rows
#define SB_STR 136           // 128 n + 8 pad -> 272B rows
#define A_PL   (128*SA_STR*2)        // 18432 B
#define B_PL   (64*SB_STR*2)         // 17408 B
#define STG_BYTES (2*A_PL + 2*B_PL)  // 71680
#define SMEM_TOTAL (2*STG_BYTES)     // 143360

// ---------------- scratch ----------------------------------------------------
__device__ float    g_bufB[NPAIR*Cc*HW];
__device__ float    g_bufC[NPAIR*Cc*HW];
__device__ uint32_t g_xpk [Bz*Cc*PIMG];
__device__ uint32_t g_pkA [NPAIR*Cc*PIMG];
__device__ uint32_t g_pkC [NPAIR*Cc*PIMG];
__device__ __align__(16) uint16_t g_Uh[Ee*NPOS*USLAB];
__device__ __align__(16) uint16_t g_Ul[Ee*NPOS*USLAB];
__device__ __align__(16) uint16_t g_Vh[NPAIR*NPOS*VSLAB];
__device__ __align__(16) uint16_t g_Vl[NPAIR*NPOS*VSLAB];
__device__ float    g_M [NPAIR*NPOS*VSLAB];
__device__ float g_xavg[Bz*Cc];
__device__ float g_xmax[Bz*Cc];
__device__ float g_stat1[NPAIR*Cc];
__device__ float g_stat2[NPAIR*Cc];
__device__ int   g_pairs[NPAIR];
__device__ float g_wpair[NPAIR];
__device__ float g_g1[NPAIR];
__device__ float g_ca[NPAIR*Cc];
__device__ float g_sain[NPAIR*2*HW];
__device__ float g_sa[NPAIR*HW];

// ---------------- helpers ----------------------------------------------------
__device__ __forceinline__ float sigmoidf_(float x) { return 1.f / (1.f + __expf(-x)); }
__device__ __forceinline__ float gelu_tanh(float v) {
    float x3 = v * v * v;
    return 0.5f * v * (1.f + tanhf(0.7978845608028654f * (v + 0.044715f * x3)));
}
__device__ __forceinline__ uint32_t pack_hilo(float v) {
    __nv_bfloat16 h = __float2bfloat16(v);
    float r = v - __bfloat162float(h);
    __nv_bfloat16 l = __float2bfloat16(r);
    return (uint32_t)__bfloat16_as_ushort(h) | ((uint32_t)__bfloat16_as_ushort(l) << 16);
}
__device__ __forceinline__ float unpack_hilo(uint32_t u) {
    return __bfloat162float(__ushort_as_bfloat16((uint16_t)u)) +
           __bfloat162float(__ushort_as_bfloat16((uint16_t)(u >> 16)));
}
__device__ __forceinline__ void split_hilo(float v, uint16_t& h, uint16_t& l) {
    __nv_bfloat16 hb = __float2bfloat16(v);
    float r = v - __bfloat162float(hb);
    h = __bfloat16_as_ushort(hb);
    l = __bfloat16_as_ushort(__float2bfloat16(r));
}
__device__ __forceinline__ uint32_t sptr(const void* p) {
    return (uint32_t)__cvta_generic_to_shared(p);
}

#define CP_ASYNC16(dst, src) \
    asm volatile("cp.async.cg.shared.global [%0], [%1], 16;" :: "r"(dst), "l"(src))
#define CP_COMMIT() asm volatile("cp.async.commit_group;" ::: "memory")
#define CP_WAIT0()  asm volatile("cp.async.wait_group 0;" ::: "memory")

#define LDSM4(r, addr) \
    asm volatile("ldmatrix.sync.aligned.m8n8.x4.shared.b16 {%0,%1,%2,%3}, [%4];" \
        : "=r"((r)[0]), "=r"((r)[1]), "=r"((r)[2]), "=r"((r)[3]) : "r"(addr))
#define LDSM4T(r, addr) \
    asm volatile("ldmatrix.sync.aligned.m8n8.x4.trans.shared.b16 {%0,%1,%2,%3}, [%4];" \
        : "=r"((r)[0]), "=r"((r)[1]), "=r"((r)[2]), "=r"((r)[3]) : "r"(addr))
#define MMA16816(d, a, b0_, b1_) \
    asm volatile("mma.sync.aligned.m16n8k16.row.col.f32.bf16.bf16.f32 " \
        "{%0,%1,%2,%3}, {%4,%5,%6,%7}, {%8,%9}, {%0,%1,%2,%3};" \
        : "+f"((d)[0]), "+f"((d)[1]), "+f"((d)[2]), "+f"((d)[3]) \
        : "r"((a)[0]), "r"((a)[1]), "r"((a)[2]), "r"((a)[3]), "r"(b0_), "r"(b1_))

// ---------------- x pack ------------------------------------------------------
__global__ void packx_kernel(const float* __restrict__ x, uint32_t* __restrict__ out) {
    int idx = blockIdx.x * 256 + threadIdx.x;
    int p = idx & 4095, c = idx >> 12;
    int y = p >> 6, xx = p & 63;
    out[(size_t)c * PIMG + (y + 1) * PW + xx + 1] = pack_hilo(x[idx]);
}

// ---------------- F(4,3) weight transform: U = G g G^T ------------------------
__global__ void wtrans_kernel(const float* __restrict__ w,
                              uint16_t* __restrict__ Uh, uint16_t* __restrict__ Ul) {
    int idx = blockIdx.x * 256 + threadIdx.x;   // (e*256+co)*256+ci
    int ci = idx & 255, co = (idx >> 8) & 255, e = idx >> 16;
    const float* g = w + (size_t)idx * 9;
    float q[3][3];
    #pragma unroll
    for (int i = 0; i < 3; i++)
        #pragma unroll
        for (int j = 0; j < 3; j++) q[i][j] = g[i*3 + j];
    const float S6 = 1.f/6.f, S24 = 1.f/24.f;
    float t[6][3];
    #pragma unroll
    for (int c = 0; c < 3; c++) {
        float a = q[0][c], b = q[1][c], d = q[2][c];
        t[0][c] = 0.25f * a;
        t[1][c] = -S6 * (a + b + d);
        t[2][c] = -S6 * (a - b + d);
        t[3][c] = S24 * (a + 2.f*b + 4.f*d);
        t[4][c] = S24 * (a - 2.f*b + 4.f*d);
        t[5][c] = d;
    }
    #pragma unroll
    for (int r = 0; r < 6; r++) {
        float a = t[r][0], b = t[r][1], d = t[r][2];
        float uu[6];
        uu[0] = 0.25f * a;
        uu[1] = -S6 * (a + b + d);
        uu[2] = -S6 * (a - b + d);
        uu[3] = S24 * (a + 2.f*b + 4.f*d);
        uu[4] = S24 * (a - 2.f*b + 4.f*d);
        uu[5] = d;
        #pragma unroll
        for (int c = 0; c < 6; c++) {
            uint16_t hh, ll; split_hilo(uu[c], hh, ll);
            size_t o = ((size_t)(e*NPOS + r*6 + c) * Cc + co) * 256 + ci;
            Uh[o] = hh; Ul[o] = ll;
        }
    }
}

// ---------------- F(4,3) input transform: V = B^T d B -------------------------
__global__ void itrans_kernel(const uint32_t* __restrict__ pkin,
                              uint16_t* __restrict__ Vh, uint16_t* __restrict__ Vl) {
    int slot = blockIdx.y;
    int idx = blockIdx.x * 256 + threadIdx.x;   // ci*256 + t
    int ci = idx >> 8, t = idx & 255;
    int ty = t >> 4, tx = t & 15;
    const uint32_t* p = pkin + ((size_t)slot * Cc + ci) * PIMG + (4*ty) * PW + 4*tx;
    float d[6][6];
    #pragma unroll
    for (int r = 0; r < 6; r++)
        #pragma unroll
        for (int c = 0; c < 6; c++) d[r][c] = unpack_hilo(p[r*PW + c]);
    float w[6][6];
    #pragma unroll
    for (int c = 0; c < 6; c++) {
        float d0=d[0][c], d1=d[1][c], d2=d[2][c], d3=d[3][c], d4=d[4][c], d5=d[5][c];
        w[0][c] = 4.f*d0 - 5.f*d2 + d4;
        w[1][c] = -4.f*d1 - 4.f*d2 + d3 + d4;
        w[2][c] =  4.f*d1 - 4.f*d2 - d3 + d4;
        w[3][c] = -2.f*d1 - d2 + 2.f*d3 + d4;
        w[4][c] =  2.f*d1 - d2 - 2.f*d3 + d4;
        w[5][c] =  4.f*d1 - 5.f*d3 + d5;
    }
    #pragma unroll
    for (int r = 0; r < 6; r++) {
        float d0=w[r][0], d1=w[r][1], d2=w[r][2], d3=w[r][3], d4=w[r][4], d5=w[r][5];
        float vv[6];
        vv[0] = 4.f*d0 - 5.f*d2 + d4;
        vv[1] = -4.f*d1 - 4.f*d2 + d3 + d4;
        vv[2] =  4.f*d1 - 4.f*d2 - d3 + d4;
        vv[3] = -2.f*d1 - d2 + 2.f*d3 + d4;
        vv[4] =  2.f*d1 - d2 - 2.f*d3 + d4;
        vv[5] =  4.f*d1 - 5.f*d3 + d5;
        #pragma unroll
        for (int c = 0; c < 6; c++) {
            uint16_t hh, ll; split_hilo(vv[c], hh, ll);
            size_t o = ((size_t)(slot*NPOS + r*6 + c) * Cc + ci) * 256 + t;
            Vh[o] = hh; Vl[o] = ll;
        }
    }
}

// ---------------- Winograd GEMM: M[pos] = U[pos] * V[pos], bf16x3 -------------
// grid (2 tile-blocks, 2 co-blocks, NPAIR*36)
__global__ __launch_bounds__(512, 1) void wgemm_kernel(
    const uint16_t* __restrict__ Uh, const uint16_t* __restrict__ Ul,
    const uint16_t* __restrict__ Vh, const uint16_t* __restrict__ Vl,
    float* __restrict__ M, int vByBatch)
{
    int zb = blockIdx.z;
    int pair = zb / NPOS, pos = zb - pair*NPOS;
    int pe = g_pairs[pair];
    int e = pe & 3;
    int vslot = vByBatch ? (pe >> 2) : pair;
    int cob = blockIdx.y * 128;
    int tb  = blockIdx.x * 128;

    const uint16_t* Ahp = Uh + ((size_t)(e*NPOS + pos) * Cc + cob) * 256;
    const uint16_t* Alp = Ul + ((size_t)(e*NPOS + pos) * Cc + cob) * 256;
    const uint16_t* Bhp = Vh + (size_t)(vslot*NPOS + pos) * VSLAB + tb;
    const uint16_t* Blp = Vl + (size_t)(vslot*NPOS + pos) * VSLAB + tb;

    extern __shared__ __align__(16) char smem[];
    int tid  = threadIdx.x;
    int lane = tid & 31, wid = tid >> 5;
    int wco  = (wid & 3) * 32;
    int wpx  = (wid >> 2) * 32;
    int coG = tid >> 3, jG = tid & 7;

    float acc[2][4][4];
    #pragma unroll
    for (int mt = 0; mt < 2; mt++)
        #pragma unroll
        for (int nt = 0; nt < 4; nt++)
            #pragma unroll
            for (int q = 0; q < 4; q++) acc[mt][nt][q] = 0.f;

    #define W_ISSUE(c, s) do { \
        char* _ab = smem + (s)*STG_BYTES; \
        size_t _ka = (size_t)(c) * WKCH + jG*8; \
        CP_ASYNC16(sptr(_ab + coG*144 + jG*16),             Ahp + (size_t)coG*256 + _ka); \
        CP_ASYNC16(sptr(_ab + (coG+64)*144 + jG*16),        Ahp + (size_t)(coG+64)*256 + _ka); \
        CP_ASYNC16(sptr(_ab + A_PL + coG*144 + jG*16),      Alp + (size_t)coG*256 + _ka); \
        CP_ASYNC16(sptr(_ab + A_PL + (coG+64)*144 + jG*16), Alp + (size_t)(coG+64)*256 + _ka); \
        char* _bb = _ab + 2*A_PL; \
        size_t _kb = (size_t)((c)*WKCH + coG) * 256; \
        CP_ASYNC16(sptr(_bb + coG*272 + jG*16),         Bhp + _kb + jG*8); \
        CP_ASYNC16(sptr(_bb + coG*272 + jG*16 + 128),   Bhp + _kb + jG*8 + 64); \
        CP_ASYNC16(sptr(_bb + B_PL + coG*272 + jG*16),       Blp + _kb + jG*8); \
        CP_ASYNC16(sptr(_bb + B_PL + coG*272 + jG*16 + 128), Blp + _kb + jG*8 + 64); \
    } while (0)

    W_ISSUE(0, 0); CP_COMMIT();

    for (int c = 0; c < WNCH; c++) {
        int s = c & 1;
        CP_WAIT0();
        __syncthreads();
        if (c + 1 < WNCH) { W_ISSUE(c + 1, s ^ 1); CP_COMMIT(); }
        uint16_t* sAh = (uint16_t*)(smem + s*STG_BYTES);
        uint16_t* sAl = (uint16_t*)(smem + s*STG_BYTES + A_PL);
        uint16_t* sBh = (uint16_t*)(smem + s*STG_BYTES + 2*A_PL);
        uint16_t* sBl = (uint16_t*)(smem + s*STG_BYTES + 2*A_PL + B_PL);
        #pragma unroll
        for (int ks = 0; ks < 4; ks++) {
            int kO = ks * 16;
            uint32_t ah[2][4], al[2][4], bh[2][4], bl[2][4];
            #pragma unroll
            for (int mt = 0; mt < 2; mt++) {
                uint32_t ad = sptr(sAh + (wco + mt*16 + (lane & 15))*SA_STR + kO + (lane >> 4)*8);
                LDSM4(ah[mt], ad);
                ad = sptr(sAl + (wco + mt*16 + (lane & 15))*SA_STR + kO + (lane >> 4)*8);
                LDSM4(al[mt], ad);
            }
            #pragma unroll
            for (int nt = 0; nt < 2; nt++) {
                uint32_t bd = sptr(sBh + (kO + (lane & 15))*SB_STR + wpx + nt*16 + (lane >> 4)*8);
                LDSM4T(bh[nt], bd);
                bd = sptr(sBl + (kO + (lane & 15))*SB_STR + wpx + nt*16 + (lane >> 4)*8);
                LDSM4T(bl[nt], bd);
            }
            #pragma unroll
            for (int mt = 0; mt < 2; mt++) {
                #pragma unroll
                for (int n8 = 0; n8 < 4; n8++) {
                    uint32_t bh0 = bh[n8 >> 1][(n8 & 1)*2], bh1 = bh[n8 >> 1][(n8 & 1)*2 + 1];
                    uint32_t bl0 = bl[n8 >> 1][(n8 & 1)*2], bl1 = bl[n8 >> 1][(n8 & 1)*2 + 1];
                    MMA16816(acc[mt][n8], ah[mt], bh0, bh1);
                    MMA16816(acc[mt][n8], ah[mt], bl0, bl1);
                    MMA16816(acc[mt][n8], al[mt], bh0, bh1);
                }
            }
        }
    }
    #undef W_ISSUE

    float* Mb = M + (size_t)zb * VSLAB;
    int r  = lane >> 2;
    int cp = (lane & 3) * 2;
    #pragma unroll
    for (int mt = 0; mt < 2; mt++) {
        #pragma unroll
        for (int hf = 0; hf < 2; hf++) {
            int co = cob + wco + mt*16 + r + hf*8;
            #pragma unroll
            for (int n8 = 0; n8 < 4; n8++) {
                int tile = tb + wpx + n8*8 + cp;
                float2 f2 = make_float2(acc[mt][n8][hf*2 + 0], acc[mt][n8][hf*2 + 1]);
                *(float2*)(Mb + (size_t)co*256 + tile) = f2;
            }
        }
    }
}

// ---------------- F(4,3) output transform + epilogue --------------------------
#define MODE_GELU 0
#define MODE_NONE 1
#define MODE_RELU 2

__global__ void otrans_kernel(const float* __restrict__ M,
                              const float* __restrict__ bias,
                              const float* __restrict__ bns, const float* __restrict__ bnb,
                              float* __restrict__ f32out, uint32_t* __restrict__ pkout, int mode)
{
    int pair = blockIdx.y;
    int e = g_pairs[pair] & 3;
    int idx = blockIdx.x * 256 + threadIdx.x;   // co*256 + t
    int co = idx >> 8, t = idx & 255;
    int ty = t >> 4, tx = t & 15;
    const float* Mb = M + ((size_t)pair * NPOS * Cc + co) * 256 + t;
    float m[6][6];
    #pragma unroll
    for (int pos = 0; pos < NPOS; pos++)
        m[pos / 6][pos % 6] = Mb[(size_t)pos * VSLAB];
    float ta[4][6];
    #pragma unroll
    for (int c = 0; c < 6; c++) {
        float m0=m[0][c], m1=m[1][c], m2=m[2][c], m3=m[3][c], m4=m[4][c], m5=m[5][c];
        ta[0][c] = m0 + m1 + m2 + m3 + m4;
        ta[1][c] = m1 - m2 + 2.f*m3 - 2.f*m4;
        ta[2][c] = m1 + m2 + 4.f*m3 + 4.f*m4;
        ta[3][c] = m1 - m2 + 8.f*m3 - 8.f*m4 + m5;
    }
    float Y[4][4];
    #pragma unroll
    for (int i = 0; i < 4; i++) {
        float m0=ta[i][0], m1=ta[i][1], m2=ta[i][2], m3=ta[i][3], m4=ta[i][4], m5=ta[i][5];
        Y[i][0] = m0 + m1 + m2 + m3 + m4;
        Y[i][1] = m1 - m2 + 2.f*m3 - 2.f*m4;
        Y[i][2] = m1 + m2 + 4.f*m3 + 4.f*m4;
        Y[i][3] = m1 - m2 + 8.f*m3 - 8.f*m4 + m5;
    }
    float bsc = bns[e*Cc + co], bsh = bnb[e*Cc + co];
    float bi  = bias ? bias[e*Cc + co] : 0.f;
    #pragma unroll
    for (int dy = 0; dy < 4; dy++)
        #pragma unroll
        for (int dx = 0; dx < 4; dx++) {
            float v = (Y[dy][dx] + bi) * bsc + bsh;
            if (mode == MODE_GELU)      v = gelu_tanh(v);
            else if (mode == MODE_RELU) v = fmaxf(v, 0.f);
            int py = 4*ty + dy, px = 4*tx + dx;
            if (f32out)
                f32out[((size_t)pair*Cc + co)*HW + py*Ww + px] = v;
            if (pkout)
                pkout[((size_t)pair*Cc + co)*PIMG + (py + 1)*PW + px + 1] = pack_hilo(v);
        }
}

// ---------------- spatial avg/max stats ---------------------------------------
__global__ void stats_kernel(const float* __restrict__ in,
                             float* __restrict__ avg, float* __restrict__ mx) {
    int bc = blockIdx.x;
    const float* p = in + (size_t)bc * HW;
    float s = 0.f, m = -INFINITY;
    for (int i = threadIdx.x; i < HW; i += 256) {
        float v = p[i];
        s += v; m = fmaxf(m, v);
    }
    __shared__ float ss[256], sm[256];
    int t = threadIdx.x;
    ss[t] = s; sm[t] = m; __syncthreads();
    for (int k = 128; k; k >>= 1) {
        if (t < k) { ss[t] += ss[t+k]; sm[t] = fmaxf(sm[t], sm[t+k]); }
        __syncthreads();
    }
    if (t == 0) {
        avg[bc] = ss[0] * (1.f / HW);
        if (mx) mx[bc] = sm[0];
    }
}

// ---------------- gate network + pair compaction ------------------------------
__global__ void gate_kernel(const int* __restrict__ dom,
                            const float* __restrict__ w1, const float* __restrict__ b1,
                            const float* __restrict__ lns, const float* __restrict__ lnb,
                            const float* __restrict__ w2, const float* __restrict__ b2,
                            const float* __restrict__ dom_emb) {
    __shared__ float gi[GIN];
    __shared__ float red[256];
    __shared__ float logit[Ee];
    int t = threadIdx.x;
    for (int b = 0; b < Bz; b++) {
        for (int k = t; k < GIN; k += 256) {
            float v;
            if (k < Cc)        v = g_xavg[b*Cc + k];
            else if (k < 2*Cc) v = g_xmax[b*Cc + k - Cc];
            else               v = dom_emb[dom[b]*16 + (k - 2*Cc)];
            gi[k] = v;
        }
        __syncthreads();
        float acc = b1[t];
        for (int k = 0; k < GIN; k++) acc += gi[k] * w1[k*Cc + t];
        red[t] = acc; __syncthreads();
        for (int k = 128; k; k >>= 1) { if (t < k) red[t] += red[t+k]; __syncthreads(); }
        float mu = red[0] * (1.f / Cc);
        __syncthreads();
        red[t] = acc * acc; __syncthreads();
        for (int k = 128; k; k >>= 1) { if (t < k) red[t] += red[t+k]; __syncthreads(); }
        float var = red[0] * (1.f / Cc) - mu * mu;
        __syncthreads();
        float h = (acc - mu) * rsqrtf(var + 1e-5f) * lns[t] + lnb[t];
        h = fmaxf(h, 0.f);
        for (int e = 0; e < Ee; e++) {
            red[t] = h * w2[t*Ee + e]; __syncthreads();
            for (int k = 128; k; k >>= 1) { if (t < k) red[t] += red[t+k]; __syncthreads(); }
            if (t == 0) logit[e] = red[0] + b2[e];
            __syncthreads();
        }
        if (t == 0) {
            float mx = logit[0];
            for (int e = 1; e < Ee; e++) mx = fmaxf(mx, logit[e]);
            float pr[Ee], s = 0.f;
            for (int e = 0; e < Ee; e++) { pr[e] = __expf(logit[e] - mx); s += pr[e]; }
            for (int e = 0; e < Ee; e++) pr[e] /= s;
            int i1 = 0;
            for (int e = 1; e < Ee; e++) if (pr[e] > pr[i1]) i1 = e;
            int i2 = -1;
            for (int e = 0; e < Ee; e++) if (e != i1 && (i2 < 0 || pr[e] > pr[i2])) i2 = e;
            float s2 = pr[i1] + pr[i2];
            int lo = i1 < i2 ? i1 : i2;
            int hi = i1 < i2 ? i2 : i1;
            g_pairs[b*2 + 0] = b*4 + lo;  g_wpair[b*2 + 0] = pr[lo] / s2;
            g_pairs[b*2 + 1] = b*4 + hi;  g_wpair[b*2 + 1] = pr[hi] / s2;
        }
        __syncthreads();
    }
}

// ---------------- domain gate -------------------------------------------------
__global__ void dgate_kernel(const float* __restrict__ gw, const float* __restrict__ gb) {
    int pair = blockIdx.x;
    int e = g_pairs[pair] & 3;
    int t = threadIdx.x;
    __shared__ float red[256];
    red[t] = g_stat1[pair*Cc + t] * gw[e*Cc + t];
    __syncthreads();
    for (int k = 128; k; k >>= 1) { if (t < k) red[t] += red[t+k]; __syncthreads(); }
    if (t == 0) g_g1[pair] = sigmoidf_(red[0] + gb[e]);
}

// ---------------- bufC = x + g1*bufB; emit packed padded ----------------------
__global__ void axpy_kernel(const float* __restrict__ x) {
    int pair = blockIdx.y;
    int b = g_pairs[pair] >> 2;
    int i = blockIdx.x * 256 + threadIdx.x;
    size_t po = (size_t)pair * Cc * HW + i;
    float v = x[(size_t)b * Cc * HW + i] + g_g1[pair] * g_bufB[po];
    g_bufC[po] = v;
    int c = i >> 12, p = i & 4095;
    g_pkC[((size_t)pair*Cc + c) * PIMG + ((p>>6) + 1) * PW + (p & 63) + 1] = pack_hilo(v);
}

// ---------------- channel attention MLP ---------------------------------------
__global__ void camlp_kernel(const float* __restrict__ w1, const float* __restrict__ w2) {
    int pair = blockIdx.x;
    int e = g_pairs[pair] & 3;
    int t = threadIdx.x;
    __shared__ float hs[CRr];
    if (t < CRr) {
        float sa_ = 0.f, sm_ = 0.f;
        const float* w1r = w1 + ((size_t)e*CRr + t) * Cc;
        for (int c = 0; c < Cc; c++) {
            sa_ += g_stat1[pair*Cc + c] * w1r[c];
            sm_ += g_stat2[pair*Cc + c] * w1r[c];
        }
        hs[t] = fmaxf(sa_, 0.f) + fmaxf(sm_, 0.f);
    }
    __syncthreads();
    float o = 0.f;
    const float* w2r = w2 + ((size_t)e*Cc + t) * CRr;
    #pragma unroll
    for (int j = 0; j < CRr; j++) o += hs[j] * w2r[j];
    g_ca[pair*Cc + t] = sigmoidf_(o);
}

// ---------------- SA input stats ----------------------------------------------
__global__ void sastats_kernel() {
    int pair = blockIdx.y;
    __shared__ float sca[Cc];
    int t = threadIdx.x;
    sca[t] = g_ca[pair*Cc + t];
    __syncthreads();
    int p = blockIdx.x * 256 + t;
    float s = 0.f, m = -INFINITY;
    for (int c = 0; c < Cc; c++) {
        float v = g_bufB[((size_t)pair*Cc + c)*HW + p] * sca[c];
        s += v; m = fmaxf(m, v);
    }
    g_sain[((size_t)pair*2    )*HW + p] = s * (1.f / Cc);
    g_sain[((size_t)pair*2 + 1)*HW + p] = m;
}

// ---------------- SA 7x7 conv -------------------------------------------------
__global__ void saconv_kernel(const float* __restrict__ saw) {
    int pair = blockIdx.y;
    int e = g_pairs[pair] & 3;
    __shared__ float sw[2*49];
    int t = threadIdx.x;
    if (t < 98) sw[t] = saw[e*98 + t];
    __syncthreads();
    int p = blockIdx.x * 256 + t;
    int y = p >> 6, x = p & 63;
    float a = 0.f;
    #pragma unroll
    for (int ch = 0; ch < 2; ch++)
        for (int ky = 0; ky < 7; ky++) {
            int gy = y + ky - 3;
            if (gy < 0 || gy >= Hh) continue;
            for (int kx = 0; kx < 7; kx++) {
                int gx = x + kx - 3;
                if (gx < 0 || gx >= Ww) continue;
                a += g_sain[((size_t)pair*2 + ch)*HW + gy*Ww + gx] * sw[ch*49 + ky*7 + kx];
            }
        }
    g_sa[(size_t)pair*HW + p] = sigmoidf_(a);
}

// ---------------- final: both pairs of a batch, direct write ------------------
__global__ void final_kernel(const float* __restrict__ adapter, const int* __restrict__ dom,
                             float* __restrict__ out) {
    int b = blockIdx.y;
    int idx = blockIdx.x * 256 + threadIdx.x;
    int c = idx >> 12, p = idx & 4095;
    float r = 0.f;
    #pragma unroll
    for (int j = 0; j < 2; j++) {
        int pair = b*2 + j;
        int e = g_pairs[pair] & 3;
        float w = g_wpair[pair];
        size_t po = (size_t)pair * Cc * HW + idx;
        float v = g_bufB[po] * g_ca[pair*Cc + c] * g_sa[(size_t)pair*HW + p] + g_bufC[po];
        v = fmaxf(v, 0.f) + adapter[((size_t)e*Dd + dom[b])*Cc + c];
        r += w * v;
    }
    out[(size_t)b * Cc * HW + idx] = r;
}

// ---------------- launch ------------------------------------------------------
extern "C" void kernel_launch(void* const* d_in, const int* in_sizes, int n_in,
                              void* d_out, int out_size) {
    const float* x        = (const float*)d_in[0];
    const int*   dom      = (const int*)  d_in[1];
    const float* g_w1     = (const float*)d_in[2];
    const float* g_b1     = (const float*)d_in[3];
    const float* ln_s     = (const float*)d_in[4];
    const float* ln_b     = (const float*)d_in[5];
    const float* g_w2     = (const float*)d_in[6];
    const float* g_b2     = (const float*)d_in[7];
    const float* dom_emb  = (const float*)d_in[8];
    const float* dt_w1    = (const float*)d_in[9];
    const float* dt_bn1s  = (const float*)d_in[10];
    const float* dt_bn1b  = (const float*)d_in[11];
    const float* dt_w2    = (const float*)d_in[12];
    const float* dt_bn2s  = (const float*)d_in[13];
    const float* dt_bn2b  = (const float*)d_in[14];
    const float* gate_w   = (const float*)d_in[15];
    const float* gate_b   = (const float*)d_in[16];
    const float* c1_w     = (const float*)d_in[17];
    const float* c1_b     = (const float*)d_in[18];
    const float* bn1s     = (const float*)d_in[19];
    const float* bn1b     = (const float*)d_in[20];
    const float* c2_w     = (const float*)d_in[21];
    const float* c2_b     = (const float*)d_in[22];
    const float* bn2s     = (const float*)d_in[23];
    const float* bn2b     = (const float*)d_in[24];
    const float* ca_w1    = (const float*)d_in[25];
    const float* ca_w2    = (const float*)d_in[26];
    const float* sa_w     = (const float*)d_in[27];
    const float* adapter  = (const float*)d_in[28];
    float* out = (float*)d_out;

    float *bufB, *pxavg, *pxmax, *pstat1, *pstat2, *Mbuf;
    uint32_t *xpk, *pkA, *pkC;
    uint16_t *Uh, *Ul, *Vh, *Vl;
    cudaGetSymbolAddress((void**)&bufB,  g_bufB);
    cudaGetSymbolAddress((void**)&pxavg, g_xavg);
    cudaGetSymbolAddress((void**)&pxmax, g_xmax);
    cudaGetSymbolAddress((void**)&pstat1, g_stat1);
    cudaGetSymbolAddress((void**)&pstat2, g_stat2);
    cudaGetSymbolAddress((void**)&xpk, g_xpk);
    cudaGetSymbolAddress((void**)&pkA, g_pkA);
    cudaGetSymbolAddress((void**)&pkC, g_pkC);
    cudaGetSymbolAddress((void**)&Uh, g_Uh);
    cudaGetSymbolAddress((void**)&Ul, g_Ul);
    cudaGetSymbolAddress((void**)&Vh, g_Vh);
    cudaGetSymbolAddress((void**)&Vl, g_Vl);
    cudaGetSymbolAddress((void**)&Mbuf, g_M);

    static int smem_set = 0;
    if (!smem_set) {
        cudaFuncSetAttribute(wgemm_kernel,
                             cudaFuncAttributeMaxDynamicSharedMemorySize, SMEM_TOTAL);
        smem_set = 1;
    }

    int ntot = Bz * Cc * HW;
    dim3 ggrid(2, 2, NPAIR*NPOS);
    dim3 egrid(Cc*HW/256, NPAIR);
    dim3 sgrid(HW/256, NPAIR);
    dim3 fgrid(Cc*HW/256, Bz);
    int nwt = Ee*Cc*Cc/256;
    dim3 itgB(Cc, Bz), itgP(Cc, NPAIR), otg(Cc, NPAIR);

    // launch order keeps wgemm at launch #6 for ncu -s 5 -c 1
    packx_kernel <<<ntot/256, 256>>>(x, xpk);                         // 1
    wtrans_kernel<<<nwt, 256>>>(dt_w1, Uh, Ul);                       // 2
    itrans_kernel<<<itgB, 256>>>(xpk, Vh, Vl);                        // 3 (by batch)
    stats_kernel <<<Bz*Cc, 256>>>(x, pxavg, pxmax);                   // 4
    gate_kernel  <<<1, 256>>>(dom, g_w1, g_b1, ln_s, ln_b, g_w2, g_b2, dom_emb); // 5
    wgemm_kernel <<<ggrid, 512, SMEM_TOTAL>>>(Uh, Ul, Vh, Vl, Mbuf, 1);          // 6
    otrans_kernel<<<otg, 256>>>(Mbuf, nullptr, dt_bn1s, dt_bn1b, nullptr, pkA, MODE_GELU);

    wtrans_kernel<<<nwt, 256>>>(dt_w2, Uh, Ul);
    itrans_kernel<<<itgP, 256>>>(pkA, Vh, Vl);
    wgemm_kernel <<<ggrid, 512, SMEM_TOTAL>>>(Uh, Ul, Vh, Vl, Mbuf, 0);
    otrans_kernel<<<otg, 256>>>(Mbuf, nullptr, dt_bn2s, dt_bn2b, bufB, nullptr, MODE_NONE);

    stats_kernel<<<NPAIR*Cc, 256>>>(bufB, pstat1, nullptr);
    dgate_kernel<<<NPAIR, 256>>>(gate_w, gate_b);
    axpy_kernel <<<egrid, 256>>>(x);

    wtrans_kernel<<<nwt, 256>>>(c1_w, Uh, Ul);
    itrans_kernel<<<itgP, 256>>>(pkC, Vh, Vl);
    wgemm_kernel <<<ggrid, 512, SMEM_TOTAL>>>(Uh, Ul, Vh, Vl, Mbuf, 0);
    otrans_kernel<<<otg, 256>>>(Mbuf, c1_b, bn1s, bn1b, nullptr, pkA, MODE_RELU);

    wtrans_kernel<<<nwt, 256>>>(c2_w, Uh, Ul);
    itrans_kernel<<<itgP, 256>>>(pkA, Vh, Vl);
    wgemm_kernel <<<ggrid, 512, SMEM_TOTAL>>>(Uh, Ul, Vh, Vl, Mbuf, 0);
    otrans_kernel<<<otg, 256>>>(Mbuf, c2_b, bn2s, bn2b, bufB, nullptr, MODE_NONE);

    stats_kernel<<<NPAIR*Cc, 256>>>(bufB, pstat1, pstat2);
    camlp_kernel<<<NPAIR, 256>>>(ca_w1, ca_w2);
    sastats_kernel<<<sgrid, 256>>>();
    saconv_kernel<<<sgrid, 256>>>(sa_w);
    final_kernel<<<fgrid, 256>>>(adapter, dom, out);
}

// round 11
// speedup vs baseline: 7.4215x; 1.1049x over previous
#include <cuda_runtime.h>
#include <cuda_bf16.h>
#include <math.h>
#include <stdint.h>

#define Bz   8
#define Cc   256
#define Hh   64
#define Ww   64
#define HW   (Hh*Ww)
#define Ee   4
#define Dd   4
#define CRr  16
#define GIN  (2*Cc+16)
#define NPAIR 16

#define NTIL   256
#define NPOS   36
#define VSLAB  (Cc*NTIL)
#define USLAB  (Cc*Cc)
#define UPLANE (Ee*NPOS*USLAB)
#define WKT    256
#define WKCH   64
#define WNCH   (WKT/WKCH)
#define SIMG   (66*67)

#define SA_STR 72
#define SB_STR 136
#define A_PL   (128*SA_STR*2)
#define B_PL   (64*SB_STR*2)
#define STG_BYTES (2*A_PL + 2*B_PL)
#define SMEM_TOTAL (2*STG_BYTES)

__device__ float    g_bufB[NPAIR*Cc*HW];
__device__ float    g_bufC[NPAIR*Cc*HW];
__device__ __align__(16) uint16_t g_Uh[4*UPLANE];
__device__ __align__(16) uint16_t g_Ul[4*UPLANE];
__device__ __align__(16) uint16_t g_Vh[NPAIR*NPOS*VSLAB];
__device__ __align__(16) uint16_t g_Vl[NPAIR*NPOS*VSLAB];
__device__ float    g_M [NPAIR*NPOS*VSLAB];
__device__ float g_xavg[Bz*Cc];
__device__ float g_xmax[Bz*Cc];
__device__ float g_stat1[NPAIR*Cc];
__device__ float g_stat2[NPAIR*Cc];
__device__ int   g_pairs[NPAIR];
__device__ float g_wpair[NPAIR];
__device__ float g_g1[NPAIR];
__device__ float g_ca[NPAIR*Cc];
__device__ float g_sain[NPAIR*2*HW];
__device__ float g_sa[NPAIR*HW];

__device__ __forceinline__ float sigmoidf_(float x) { return 1.f / (1.f + __expf(-x)); }
__device__ __forceinline__ float gelu_tanh(float v) {
    float x3 = v * v * v;
    return 0.5f * v * (1.f + tanhf(0.7978845608028654f * (v + 0.044715f * x3)));
}
__device__ __forceinline__ void split_hilo(float v, uint16_t& h, uint16_t& l) {
    __nv_bfloat16 hb = __float2bfloat16(v);
    float r = v - __bfloat162float(hb);
    h = __bfloat16_as_ushort(hb);
    l = __bfloat16_as_ushort(__float2bfloat16(r));
}
__device__ __forceinline__ uint32_t sptr(const void* p) {
    return (uint32_t)__cvta_generic_to_shared(p);
}

#define CP_ASYNC16(dst, src) \
    asm volatile("cp.async.cg.shared.global [%0], [%1], 16;" :: "r"(dst), "l"(src))
#define CP_COMMIT() asm volatile("cp.async.commit_group;" ::: "memory")
#define CP_WAIT0()  asm volatile("cp.async.wait_group 0;" ::: "memory")

#define LDSM4(r, addr) \
    asm volatile("ldmatrix.sync.aligned.m8n8.x4.shared.b16 {%0,%1,%2,%3}, [%4];" \
        : "=r"((r)[0]), "=r"((r)[1]), "=r"((r)[2]), "=r"((r)[3]) : "r"(addr))
#define LDSM4T(r, addr) \
    asm volatile("ldmatrix.sync.aligned.m8n8.x4.trans.shared.b16 {%0,%1,%2,%3}, [%4];" \
        : "=r"((r)[0]), "=r"((r)[1]), "=r"((r)[2]), "=r"((r)[3]) : "r"(addr))
#define MMA16816(d, a, b0_, b1_) \
    asm volatile("mma.sync.aligned.m16n8k16.row.col.f32.bf16.bf16.f32 " \
        "{%0,%1,%2,%3}, {%4,%5,%6,%7}, {%8,%9}, {%0,%1,%2,%3};" \
        : "+f"((d)[0]), "+f"((d)[1]), "+f"((d)[2]), "+f"((d)[3]) \
        : "r"((a)[0]), "r"((a)[1]), "r"((a)[2]), "r"((a)[3]), "r"(b0_), "r"(b1_))

__device__ __forceinline__ void tile_to_V(const float* s, int t, size_t vbase,
                                          uint16_t* __restrict__ Vh,
                                          uint16_t* __restrict__ Vl) {
    int ty = t >> 4, tx = t & 15;
    const float* sp = s + (4*ty)*67 + 4*tx;
    float d[6][6];
    #pragma unroll
    for (int r = 0; r < 6; r++)
        #pragma unroll
        for (int c = 0; c < 6; c++) d[r][c] = sp[r*67 + c];
    float w[6][6];
    #pragma unroll
    for (int c = 0; c < 6; c++) {
        float d0=d[0][c], d1=d[1][c], d2=d[2][c], d3=d[3][c], d4=d[4][c], d5=d[5][c];
        w[0][c] = 4.f*d0 - 5.f*d2 + d4;
        w[1][c] = -4.f*d1 - 4.f*d2 + d3 + d4;
        w[2][c] =  4.f*d1 - 4.f*d2 - d3 + d4;
        w[3][c] = -2.f*d1 - d2 + 2.f*d3 + d4;
        w[4][c] =  2.f*d1 - d2 - 2.f*d3 + d4;
        w[5][c] =  4.f*d1 - 5.f*d3 + d5;
    }
    #pragma unroll
    for (int r = 0; r < 6; r++) {
        float d0=w[r][0], d1=w[r][1], d2=w[r][2], d3=w[r][3], d4=w[r][4], d5=w[r][5];
        float vv[6];
        vv[0] = 4.f*d0 - 5.f*d2 + d4;
        vv[1] = -4.f*d1 - 4.f*d2 + d3 + d4;
        vv[2] =  4.f*d1 - 4.f*d2 - d3 + d4;
        vv[3] = -2.f*d1 - d2 + 2.f*d3 + d4;
        vv[4] =  2.f*d1 - d2 - 2.f*d3 + d4;
        vv[5] =  4.f*d1 - 5.f*d3 + d5;
        #pragma unroll
        for (int c = 0; c < 6; c++) {
            uint16_t hh, ll; split_hilo(vv[c], hh, ll);
            size_t o = vbase + (size_t)(r*6 + c) * VSLAB;
            Vh[o] = hh; Vl[o] = ll;
        }
    }
}

// itrans from raw x: grid (Cc, Bz)
__global__ void itransx_kernel(const float* __restrict__ x,
                               uint16_t* __restrict__ Vh, uint16_t* __restrict__ Vl) {
    int c = blockIdx.x, b = blockIdx.y;
    __shared__ float s[SIMG];
    int tid = threadIdx.x;
    for (int i = tid; i < SIMG; i += 256) s[i] = 0.f;
    __syncthreads();
    const float* xc = x + ((size_t)b*Cc + c)*HW;
    for (int i = tid; i < HW; i += 256)
        s[((i>>6) + 1)*67 + (i & 63) + 1] = xc[i];
    __syncthreads();
    size_t vbase = (size_t)b*NPOS*VSLAB + (size_t)c*256 + tid;
    tile_to_V(s, tid, vbase, Vh, Vl);
}

__global__ void wtrans_kernel(const float* __restrict__ w,
                              uint16_t* __restrict__ Uh, uint16_t* __restrict__ Ul) {
    int idx = blockIdx.x * 256 + threadIdx.x;
    int ci = idx & 255, co = (idx >> 8) & 255, e = idx >> 16;
    const float* g = w + (size_t)idx * 9;
    float q[3][3];
    #pragma unroll
    for (int i = 0; i < 3; i++)
        #pragma unroll
        for (int j = 0; j < 3; j++) q[i][j] = g[i*3 + j];
    const float S6 = 1.f/6.f, S24 = 1.f/24.f;
    float t[6][3];
    #pragma unroll
    for (int c = 0; c < 3; c++) {
        float a = q[0][c], b = q[1][c], d = q[2][c];
        t[0][c] = 0.25f * a;
        t[1][c] = -S6 * (a + b + d);
        t[2][c] = -S6 * (a - b + d);
        t[3][c] = S24 * (a + 2.f*b + 4.f*d);
        t[4][c] = S24 * (a - 2.f*b + 4.f*d);
        t[5][c] = d;
    }
    #pragma unroll
    for (int r = 0; r < 6; r++) {
        float a = t[r][0], b = t[r][1], d = t[r][2];
        float uu[6];
        uu[0] = 0.25f * a;
        uu[1] = -S6 * (a + b + d);
        uu[2] = -S6 * (a - b + d);
        uu[3] = S24 * (a + 2.f*b + 4.f*d);
        uu[4] = S24 * (a - 2.f*b + 4.f*d);
        uu[5] = d;
        #pragma unroll
        for (int c = 0; c < 6; c++) {
            uint16_t hh, ll; split_hilo(uu[c], hh, ll);
            size_t o = ((size_t)(e*NPOS + r*6 + c) * Cc + co) * 256 + ci;
            Uh[o] = hh; Ul[o] = ll;
        }
    }
}

__global__ __launch_bounds__(512, 1) void wgemm_kernel(
    const uint16_t* __restrict__ Uh, const uint16_t* __restrict__ Ul,
    const uint16_t* __restrict__ Vh, const uint16_t* __restrict__ Vl,
    float* __restrict__ M, int vByBatch)
{
    int zb = blockIdx.z;
    int pair = zb / NPOS, pos = zb - pair*NPOS;
    int pe = g_pairs[pair];
    int e = pe & 3;
    int vslot = vByBatch ? (pe >> 2) : pair;
    int cob = blockIdx.y * 128;
    int tb  = blockIdx.x * 128;

    const uint16_t* Ahp = Uh + ((size_t)(e*NPOS + pos) * Cc + cob) * 256;
    const uint16_t* Alp = Ul + ((size_t)(e*NPOS + pos) * Cc + cob) * 256;
    const uint16_t* Bhp = Vh + (size_t)(vslot*NPOS + pos) * VSLAB + tb;
    const uint16_t* Blp = Vl + (size_t)(vslot*NPOS + pos) * VSLAB + tb;

    extern __shared__ __align__(16) char smem[];
    int tid  = threadIdx.x;
    int lane = tid & 31, wid = tid >> 5;
    int wco  = (wid & 3) * 32;
    int wpx  = (wid >> 2) * 32;
    int coG = tid >> 3, jG = tid & 7;

    float acc[2][4][4];
    #pragma unroll
    for (int mt = 0; mt < 2; mt++)
        #pragma unroll
        for (int nt = 0; nt < 4; nt++)
            #pragma unroll
            for (int q = 0; q < 4; q++) acc[mt][nt][q] = 0.f;

    #define W_ISSUE(c, s) do { \
        char* _ab = smem + (s)*STG_BYTES; \
        size_t _ka = (size_t)(c) * WKCH + jG*8; \
        CP_ASYNC16(sptr(_ab + coG*144 + jG*16),             Ahp + (size_t)coG*256 + _ka); \
        CP_ASYNC16(sptr(_ab + (coG+64)*144 + jG*16),        Ahp + (size_t)(coG+64)*256 + _ka); \
        CP_ASYNC16(sptr(_ab + A_PL + coG*144 + jG*16),      Alp + (size_t)coG*256 + _ka); \
        CP_ASYNC16(sptr(_ab + A_PL + (coG+64)*144 + jG*16), Alp + (size_t)(coG+64)*256 + _ka); \
        char* _bb = _ab + 2*A_PL; \
        size_t _kb = (size_t)((c)*WKCH + coG) * 256; \
        CP_ASYNC16(sptr(_bb + coG*272 + jG*16),         Bhp + _kb + jG*8); \
        CP_ASYNC16(sptr(_bb + coG*272 + jG*16 + 128),   Bhp + _kb + jG*8 + 64); \
        CP_ASYNC16(sptr(_bb + B_PL + coG*272 + jG*16),       Blp + _kb + jG*8); \
        CP_ASYNC16(sptr(_bb + B_PL + coG*272 + jG*16 + 128), Blp + _kb + jG*8 + 64); \
    } while (0)

    W_ISSUE(0, 0); CP_COMMIT();

    for (int c = 0; c < WNCH; c++) {
        int s = c & 1;
        CP_WAIT0();
        __syncthreads();
        if (c + 1 < WNCH) { W_ISSUE(c + 1, s ^ 1); CP_COMMIT(); }
        uint16_t* sAh = (uint16_t*)(smem + s*STG_BYTES);
        uint16_t* sAl = (uint16_t*)(smem + s*STG_BYTES + A_PL);
        uint16_t* sBh = (uint16_t*)(smem + s*STG_BYTES + 2*A_PL);
        uint16_t* sBl = (uint16_t*)(smem + s*STG_BYTES + 2*A_PL + B_PL);
        #pragma unroll
        for (int ks = 0; ks < 4; ks++) {
            int kO = ks * 16;
            uint32_t ah[2][4], al[2][4], bh[2][4], bl[2][4];
            #pragma unroll
            for (int mt = 0; mt < 2; mt++) {
                uint32_t ad = sptr(sAh + (wco + mt*16 + (lane & 15))*SA_STR + kO + (lane >> 4)*8);
                LDSM4(ah[mt], ad);
                ad = sptr(sAl + (wco + mt*16 + (lane & 15))*SA_STR + kO + (lane >> 4)*8);
                LDSM4(al[mt], ad);
            }
            #pragma unroll
            for (int nt = 0; nt < 2; nt++) {
                uint32_t bd = sptr(sBh + (kO + (lane & 15))*SB_STR + wpx + nt*16 + (lane >> 4)*8);
                LDSM4T(bh[nt], bd);
                bd = sptr(sBl + (kO + (lane & 15))*SB_STR + wpx + nt*16 + (lane >> 4)*8);
                LDSM4T(bl[nt], bd);
            }
            #pragma unroll
            for (int mt = 0; mt < 2; mt++) {
                #pragma unroll
                for (int n8 = 0; n8 < 4; n8++) {
                    uint32_t bh0 = bh[n8 >> 1][(n8 & 1)*2], bh1 = bh[n8 >> 1][(n8 & 1)*2 + 1];
                    uint32_t bl0 = bl[n8 >> 1][(n8 & 1)*2], bl1 = bl[n8 >> 1][(n8 & 1)*2 + 1];
                    MMA16816(acc[mt][n8], ah[mt], bh0, bh1);
                    MMA16816(acc[mt][n8], ah[mt], bl0, bl1);
                    MMA16816(acc[mt][n8], al[mt], bh0, bh1);
                }
            }
        }
    }
    #undef W_ISSUE

    float* Mb = M + (size_t)zb * VSLAB;
    int r  = lane >> 2;
    int cp = (lane & 3) * 2;
    #pragma unroll
    for (int mt = 0; mt < 2; mt++) {
        #pragma unroll
        for (int hf = 0; hf < 2; hf++) {
            int co = cob + wco + mt*16 + r + hf*8;
            #pragma unroll
            for (int n8 = 0; n8 < 4; n8++) {
                int tile = tb + wpx + n8*8 + cp;
                float2 f2 = make_float2(acc[mt][n8][hf*2 + 0], acc[mt][n8][hf*2 + 1]);
                *(float2*)(Mb + (size_t)co*256 + tile) = f2;
            }
        }
    }
}

#define MODE_GELU 0
#define MODE_NONE 1
#define MODE_RELU 2

// fused otrans: grid (Cc, NPAIR)
__global__ void otrans_kernel(const float* __restrict__ M,
                              const float* __restrict__ bias,
                              const float* __restrict__ bns, const float* __restrict__ bnb,
                              float* __restrict__ f32out, int statMode,
                              float* __restrict__ stat1, float* __restrict__ stat2,
                              uint16_t* __restrict__ Vh, uint16_t* __restrict__ Vl,
                              int mode)
{
    int co = blockIdx.x, pair = blockIdx.y;
    int e = g_pairs[pair] & 3;
    __shared__ float s[SIMG];
    __shared__ float red[256], rm[256];
    int tid = threadIdx.x;
    for (int i = tid; i < SIMG; i += 256) s[i] = 0.f;
    __syncthreads();

    int t = tid, ty = t >> 4, tx = t & 15;
    const float* Mb = M + ((size_t)pair*NPOS*Cc + co)*256 + t;
    float m[6][6];
    #pragma unroll
    for (int pos = 0; pos < NPOS; pos++)
        m[pos / 6][pos % 6] = Mb[(size_t)pos * VSLAB];
    float ta[4][6];
    #pragma unroll
    for (int c = 0; c < 6; c++) {
        float m0=m[0][c], m1=m[1][c], m2=m[2][c], m3=m[3][c], m4=m[4][c], m5=m[5][c];
        ta[0][c] = m0 + m1 + m2 + m3 + m4;
        ta[1][c] = m1 - m2 + 2.f*m3 - 2.f*m4;
        ta[2][c] = m1 + m2 + 4.f*m3 + 4.f*m4;
        ta[3][c] = m1 - m2 + 8.f*m3 - 8.f*m4 + m5;
    }
    float bsc = bns[e*Cc + co], bsh = bnb[e*Cc + co];
    float bi  = bias ? bias[e*Cc + co] : 0.f;
    #pragma unroll
    for (int i = 0; i < 4; i++) {
        float m0=ta[i][0], m1=ta[i][1], m2=ta[i][2], m3=ta[i][3], m4=ta[i][4], m5=ta[i][5];
        float Yv[4];
        Yv[0] = m0 + m1 + m2 + m3 + m4;
        Yv[1] = m1 - m2 + 2.f*m3 - 2.f*m4;
        Yv[2] = m1 + m2 + 4.f*m3 + 4.f*m4;
        Yv[3] = m1 - m2 + 8.f*m3 - 8.f*m4 + m5;
        #pragma unroll
        for (int dx = 0; dx < 4; dx++) {
            float v = (Yv[dx] + bi) * bsc + bsh;
            if (mode == MODE_GELU)      v = gelu_tanh(v);
            else if (mode == MODE_RELU) v = fmaxf(v, 0.f);
            s[(4*ty + i + 1)*67 + 4*tx + dx + 1] = v;
        }
    }
    __syncthreads();

    if (f32out || statMode) {
        float ls = 0.f, lm = -INFINITY;
        float* oc = f32out ? f32out + ((size_t)pair*Cc + co)*HW : nullptr;
        for (int i = tid; i < HW; i += 256) {
            float v = s[((i>>6) + 1)*67 + (i & 63) + 1];
            if (oc) oc[i] = v;
            ls += v; lm = fmaxf(lm, v);
        }
        if (statMode) {
            red[tid] = ls; rm[tid] = lm; __syncthreads();
            for (int k = 128; k; k >>= 1) {
                if (tid < k) { red[tid] += red[tid+k]; rm[tid] = fmaxf(rm[tid], rm[tid+k]); }
                __syncthreads();
            }
            if (tid == 0) {
                stat1[pair*Cc + co] = red[0] * (1.f / HW);
                if (statMode == 2) stat2[pair*Cc + co] = rm[0];
            }
        }
    }
    if (Vh) {
        size_t vbase = (size_t)pair*NPOS*VSLAB + (size_t)co*256 + t;
        tile_to_V(s, t, vbase, Vh, Vl);
    }
}

// fused axpy + itrans: grid (Cc, NPAIR)
__global__ void axpy_kernel(const float* __restrict__ x,
                            uint16_t* __restrict__ Vh, uint16_t* __restrict__ Vl) {
    int c = blockIdx.x, pair = blockIdx.y;
    int b = g_pairs[pair] >> 2;
    __shared__ float s[SIMG];
    int tid = threadIdx.x;
    for (int i = tid; i < SIMG; i += 256) s[i] = 0.f;
    __syncthreads();
    float g1 = g_g1[pair];
    const float* xc = x + ((size_t)b*Cc + c)*HW;
    const float* bc = g_bufB + ((size_t)pair*Cc + c)*HW;
    float* cc = g_bufC + ((size_t)pair*Cc + c)*HW;
    for (int i = tid; i < HW; i += 256) {
        float v = xc[i] + g1 * bc[i];
        cc[i] = v;
        s[((i>>6) + 1)*67 + (i & 63) + 1] = v;
    }
    __syncthreads();
    size_t vbase = (size_t)pair*NPOS*VSLAB + (size_t)c*256 + tid;
    tile_to_V(s, tid, vbase, Vh, Vl);
}

__global__ void stats_kernel(const float* __restrict__ in,
                             float* __restrict__ avg, float* __restrict__ mx) {
    int bc = blockIdx.x;
    const float* p = in + (size_t)bc * HW;
    float s = 0.f, m = -INFINITY;
    for (int i = threadIdx.x; i < HW; i += 256) {
        float v = p[i];
        s += v; m = fmaxf(m, v);
    }
    __shared__ float ss[256], sm[256];
    int t = threadIdx.x;
    ss[t] = s; sm[t] = m; __syncthreads();
    for (int k = 128; k; k >>= 1) {
        if (t < k) { ss[t] += ss[t+k]; sm[t] = fmaxf(sm[t], sm[t+k]); }
        __syncthreads();
    }
    if (t == 0) {
        avg[bc] = ss[0] * (1.f / HW);
        if (mx) mx[bc] = sm[0];
    }
}

__global__ void gate_kernel(const int* __restrict__ dom,
                            const float* __restrict__ w1, const float* __restrict__ b1,
                            const float* __restrict__ lns, const float* __restrict__ lnb,
                            const float* __restrict__ w2, const float* __restrict__ b2,
                            const float* __restrict__ dom_emb) {
    __shared__ float gi[GIN];
    __shared__ float red[256];
    __shared__ float logit[Ee];
    int t = threadIdx.x;
    for (int b = 0; b < Bz; b++) {
        for (int k = t; k < GIN; k += 256) {
            float v;
            if (k < Cc)        v = g_xavg[b*Cc + k];
            else if (k < 2*Cc) v = g_xmax[b*Cc + k - Cc];
            else               v = dom_emb[dom[b]*16 + (k - 2*Cc)];
            gi[k] = v;
        }
        __syncthreads();
        float acc = b1[t];
        for (int k = 0; k < GIN; k++) acc += gi[k] * w1[k*Cc + t];
        red[t] = acc; __syncthreads();
        for (int k = 128; k; k >>= 1) { if (t < k) red[t] += red[t+k]; __syncthreads(); }
        float mu = red[0] * (1.f / Cc);
        __syncthreads();
        red[t] = acc * acc; __syncthreads();
        for (int k = 128; k; k >>= 1) { if (t < k) red[t] += red[t+k]; __syncthreads(); }
        float var = red[0] * (1.f / Cc) - mu * mu;
        __syncthreads();
        float h = (acc - mu) * rsqrtf(var + 1e-5f) * lns[t] + lnb[t];
        h = fmaxf(h, 0.f);
        for (int e = 0; e < Ee; e++) {
            red[t] = h * w2[t*Ee + e]; __syncthreads();
            for (int k = 128; k; k >>= 1) { if (t < k) red[t] += red[t+k]; __syncthreads(); }
            if (t == 0) logit[e] = red[0] + b2[e];
            __syncthreads();
        }
        if (t == 0) {
            float mx = logit[0];
            for (int e = 1; e < Ee; e++) mx = fmaxf(mx, logit[e]);
            float pr[Ee], s = 0.f;
            for (int e = 0; e < Ee; e++) { pr[e] = __expf(logit[e] - mx); s += pr[e]; }
            for (int e = 0; e < Ee; e++) pr[e] /= s;
            int i1 = 0;
            for (int e = 1; e < Ee; e++) if (pr[e] > pr[i1]) i1 = e;
            int i2 = -1;
            for (int e = 0; e < Ee; e++) if (e != i1 && (i2 < 0 || pr[e] > pr[i2])) i2 = e;
            float s2 = pr[i1] + pr[i2];
            int lo = i1 < i2 ? i1 : i2;
            int hi = i1 < i2 ? i2 : i1;
            g_pairs[b*2 + 0] = b*4 + lo;  g_wpair[b*2 + 0] = pr[lo] / s2;
            g_pairs[b*2 + 1] = b*4 + hi;  g_wpair[b*2 + 1] = pr[hi] / s2;
        }
        __syncthreads();
    }
}

__global__ void dgate_kernel(const float* __restrict__ gw, const float* __restrict__ gb) {
    int pair = blockIdx.x;
    int e = g_pairs[pair] & 3;
    int t = threadIdx.x;
    __shared__ float red[256];
    red[t] = g_stat1[pair*Cc + t] * gw[e*Cc + t];
    __syncthreads();
    for (int k = 128; k; k >>= 1) { if (t < k) red[t] += red[t+k]; __syncthreads(); }
    if (t == 0) g_g1[pair] = sigmoidf_(red[0] + gb[e]);
}

__global__ void camlp_kernel(const float* __restrict__ w1, const float* __restrict__ w2) {
    int pair = blockIdx.x;
    int e = g_pairs[pair] & 3;
    int t = threadIdx.x;
    __shared__ float hs[CRr];
    if (t < CRr) {
        float sa_ = 0.f, sm_ = 0.f;
        const float* w1r = w1 + ((size_t)e*CRr + t) * Cc;
        for (int c = 0; c < Cc; c++) {
            sa_ += g_stat1[pair*Cc + c] * w1r[c];
            sm_ += g_stat2[pair*Cc + c] * w1r[c];
        }
        hs[t] = fmaxf(sa_, 0.f) + fmaxf(sm_, 0.f);
    }
    __syncthreads();
    float o = 0.f;
    const float* w2r = w2 + ((size_t)e*Cc + t) * CRr;
    #pragma unroll
    for (int j = 0; j < CRr; j++) o += hs[j] * w2r[j];
    g_ca[pair*Cc + t] = sigmoidf_(o);
}

__global__ void sastats_kernel() {
    int pair = blockIdx.y;
    __shared__ float sca[Cc];
    int t = threadIdx.x;
    sca[t] = g_ca[pair*Cc + t];
    __syncthreads();
    int p = blockIdx.x * 256 + t;
    float s = 0.f, m = -INFINITY;
    for (int c = 0; c < Cc; c++) {
        float v = g_bufB[((size_t)pair*Cc + c)*HW + p] * sca[c];
        s += v; m = fmaxf(m, v);
    }
    g_sain[((size_t)pair*2    )*HW + p] = s * (1.f / Cc);
    g_sain[((size_t)pair*2 + 1)*HW + p] = m;
}

__global__ void saconv_kernel(const float* __restrict__ saw) {
    int pair = blockIdx.y;
    int e = g_pairs[pair] & 3;
    __shared__ float sw[2*49];
    int t = threadIdx.x;
    if (t < 98) sw[t] = saw[e*98 + t];
    __syncthreads();
    int p = blockIdx.x * 256 + t;
    int y = p >> 6, x = p & 63;
    float a = 0.f;
    #pragma unroll
    for (int ch = 0; ch < 2; ch++)
        for (int ky = 0; ky < 7; ky++) {
            int gy = y + ky - 3;
            if (gy < 0 || gy >= Hh) continue;
            for (int kx = 0; kx < 7; kx++) {
                int gx = x + kx - 3;
                if (gx < 0 || gx >= Ww) continue;
                a += g_sain[((size_t)pair*2 + ch)*HW + gy*Ww + gx] * sw[ch*49 + ky*7 + kx];
            }
        }
    g_sa[(size_t)pair*HW + p] = sigmoidf_(a);
}

__global__ void final_kernel(const float* __restrict__ adapter, const int* __restrict__ dom,
                             float* __restrict__ out) {
    int b = blockIdx.y;
    int idx = blockIdx.x * 256 + threadIdx.x;
    int c = idx >> 12, p = idx & 4095;
    float r = 0.f;
    #pragma unroll
    for (int j = 0; j < 2; j++) {
        int pair = b*2 + j;
        int e = g_pairs[pair] & 3;
        float w = g_wpair[pair];
        size_t po = (size_t)pair * Cc * HW + idx;
        float v = g_bufB[po] * g_ca[pair*Cc + c] * g_sa[(size_t)pair*HW + p] + g_bufC[po];
        v = fmaxf(v, 0.f) + adapter[((size_t)e*Dd + dom[b])*Cc + c];
        r += w * v;
    }
    out[(size_t)b * Cc * HW + idx] = r;
}

extern "C" void kernel_launch(void* const* d_in, const int* in_sizes, int n_in,
                              void* d_out, int out_size) {
    const float* x        = (const float*)d_in[0];
    const int*   dom      = (const int*)  d_in[1];
    const float* g_w1     = (const float*)d_in[2];
    const float* g_b1     = (const float*)d_in[3];
    const float* ln_s     = (const float*)d_in[4];
    const float* ln_b     = (const float*)d_in[5];
    const float* g_w2     = (const float*)d_in[6];
    const float* g_b2     = (const float*)d_in[7];
    const float* dom_emb  = (const float*)d_in[8];
    const float* dt_w1    = (const float*)d_in[9];
    const float* dt_bn1s  = (const float*)d_in[10];
    const float* dt_bn1b  = (const float*)d_in[11];
    const float* dt_w2    = (const float*)d_in[12];
    const float* dt_bn2s  = (const float*)d_in[13];
    const float* dt_bn2b  = (const float*)d_in[14];
    const float* gate_w   = (const float*)d_in[15];
    const float* gate_b   = (const float*)d_in[16];
    const float* c1_w     = (const float*)d_in[17];
    const float* c1_b     = (const float*)d_in[18];
    const float* bn1s     = (const float*)d_in[19];
    const float* bn1b     = (const float*)d_in[20];
    const float* c2_w     = (const float*)d_in[21];
    const float* c2_b     = (const float*)d_in[22];
    const float* bn2s     = (const float*)d_in[23];
    const float* bn2b     = (const float*)d_in[24];
    const float* ca_w1    = (const float*)d_in[25];
    const float* ca_w2    = (const float*)d_in[26];
    const float* sa_w     = (const float*)d_in[27];
    const float* adapter  = (const float*)d_in[28];
    float* out = (float*)d_out;

    float *pxavg, *pxmax, *pstat1, *pstat2, *Mbuf, *bufB;
    uint16_t *Uh, *Ul, *Vh, *Vl;
    cudaGetSymbolAddress((void**)&pxavg, g_xavg);
    cudaGetSymbolAddress((void**)&pxmax, g_xmax);
    cudaGetSymbolAddress((void**)&pstat1, g_stat1);
    cudaGetSymbolAddress((void**)&pstat2, g_stat2);
    cudaGetSymbolAddress((void**)&bufB, g_bufB);
    cudaGetSymbolAddress((void**)&Uh, g_Uh);
    cudaGetSymbolAddress((void**)&Ul, g_Ul);
    cudaGetSymbolAddress((void**)&Vh, g_Vh);
    cudaGetSymbolAddress((void**)&Vl, g_Vl);
    cudaGetSymbolAddress((void**)&Mbuf, g_M);

    static int smem_set = 0;
    if (!smem_set) {
        cudaFuncSetAttribute(wgemm_kernel,
                             cudaFuncAttributeMaxDynamicSharedMemorySize, SMEM_TOTAL);
        smem_set = 1;
    }

    dim3 ggrid(2, 2, NPAIR*NPOS);
    dim3 sgrid(HW/256, NPAIR);
    dim3 fgrid(Cc*HW/256, Bz);
    int nwt = Ee*Cc*Cc/256;
    dim3 cgB(Cc, Bz), cgP(Cc, NPAIR);

    stats_kernel <<<Bz*Cc, 256>>>(x, pxavg, pxmax);                                   // 1
    gate_kernel  <<<1, 256>>>(dom, g_w1, g_b1, ln_s, ln_b, g_w2, g_b2, dom_emb);      // 2
    wtrans_kernel<<<nwt, 256>>>(dt_w1, Uh, Ul);                                       // 3
    itransx_kernel<<<cgB, 256>>>(x, Vh, Vl);                                          // 4
    wtrans_kernel<<<nwt, 256>>>(dt_w2, Uh + (size_t)UPLANE, Ul + (size_t)UPLANE);     // 5
    wgemm_kernel <<<ggrid, 512, SMEM_TOTAL>>>(Uh, Ul, Vh, Vl, Mbuf, 1);               // 6
    otrans_kernel<<<cgP, 256>>>(Mbuf, nullptr, dt_bn1s, dt_bn1b,
                                nullptr, 0, nullptr, nullptr, Vh, Vl, MODE_GELU);
    wgemm_kernel <<<ggrid, 512, SMEM_TOTAL>>>(Uh + (size_t)UPLANE, Ul + (size_t)UPLANE,
                                              Vh, Vl, Mbuf, 0);
    otrans_kernel<<<cgP, 256>>>(Mbuf, nullptr, dt_bn2s, dt_bn2b,
                                bufB, 1, pstat1, nullptr, nullptr, nullptr, MODE_NONE);
    dgate_kernel <<<NPAIR, 256>>>(gate_w, gate_b);
    wtrans_kernel<<<nwt, 256>>>(c1_w, Uh + 2*(size_t)UPLANE, Ul + 2*(size_t)UPLANE);
    axpy_kernel  <<<cgP, 256>>>(x, Vh, Vl);
    wgemm_kernel <<<ggrid, 512, SMEM_TOTAL>>>(Uh + 2*(size_t)UPLANE, Ul + 2*(size_t)UPLANE,
                                              Vh, Vl, Mbuf, 0);
    wtrans_kernel<<<nwt, 256>>>(c2_w, Uh + 3*(size_t)UPLANE, Ul + 3*(size_t)UPLANE);
    otrans_kernel<<<cgP, 256>>>(Mbuf, c1_b, bn1s, bn1b,
                                nullptr, 0, nullptr, nullptr, Vh, Vl, MODE_RELU);
    wgemm_kernel <<<ggrid, 512, SMEM_TOTAL>>>(Uh + 3*(size_t)UPLANE, Ul + 3*(size_t)UPLANE,
                                              Vh, Vl, Mbuf, 0);
    otrans_kernel<<<cgP, 256>>>(Mbuf, c2_b, bn2s, bn2b,
                                bufB, 2, pstat1, pstat2, nullptr, nullptr, MODE_NONE);
    camlp_kernel <<<NPAIR, 256>>>(ca_w1, ca_w2);
    sastats_kernel<<<sgrid, 256>>>();
    saconv_kernel<<<sgrid, 256>>>(sa_w);
    final_kernel <<<fgrid, 256>>>(adapter, dom, out);
}